// round 1
// baseline (speedup 1.0000x reference)
#include <cuda_runtime.h>
#include <cuda_bf16.h>
#include <math.h>

// Problem constants
#define B_    2
#define LQ_   21760
#define C_    256
#define NHEAD 8
#define KPT   4
#define NSC   4
#define NL_   6
#define FF_   1024
#define DK_   32
#define MROWS (B_ * LQ_)          // 43520

// Scratch buffers (static device globals; no runtime allocation)
__device__ float g_x   [MROWS * C_];
__device__ float g_xp  [MROWS * C_];
__device__ float g_v   [MROWS * C_];
__device__ float g_off [MROWS * 256];   // NHEAD*NS*K*2 = 256
__device__ float g_att [MROWS * 128];   // NHEAD*NS*K   = 128
__device__ float g_attn[MROWS * C_];
__device__ float g_proj[MROWS * C_];
__device__ float g_hid [MROWS * FF_];

// ---------------------------------------------------------------------------
// Elementwise: xp = x + pos
// ---------------------------------------------------------------------------
__global__ void addpos_kernel(const float* __restrict__ x,
                              const float* __restrict__ pos,
                              float* __restrict__ xp, int n4) {
    int i = blockIdx.x * blockDim.x + threadIdx.x;
    if (i < n4) {
        float4 a = ((const float4*)x)[i];
        float4 b = ((const float4*)pos)[i];
        float4 o;
        o.x = a.x + b.x; o.y = a.y + b.y; o.z = a.z + b.z; o.w = a.w + b.w;
        ((float4*)xp)[i] = o;
    }
}

// ---------------------------------------------------------------------------
// SGEMM: C[M,N] = A[M,K] @ W[K,N] + bias[N]  (optional ReLU)
// BM=BN=128, BK=16, 256 threads, 8x8 per thread. M%128==0, N%128==0, K%16==0.
// ---------------------------------------------------------------------------
#define BM 128
#define BN 128
#define BK 16

template<int RELU>
__global__ __launch_bounds__(256)
void sgemm_kernel(const float* __restrict__ A, const float* __restrict__ W,
                  const float* __restrict__ bias, float* __restrict__ Cmat,
                  int M, int N, int K) {
    __shared__ float As[BK][BM + 4];
    __shared__ float Bs[BK][BN];

    const int tid  = threadIdx.x;
    const int brow = blockIdx.y * BM;
    const int bcol = blockIdx.x * BN;

    // A-load mapping: thread -> (row = tid/4 in {0..63}, col4 = (tid&3)*4); 2 rows (+64)
    const int arow = tid >> 2;
    const int acol = (tid & 3) << 2;
    // B-load mapping: thread -> (row = tid/32 in {0..7}, col4 = (tid&31)*4); 2 rows (+8)
    const int brw  = tid >> 5;
    const int bcl  = (tid & 31) << 2;

    const float* Aptr = A + (size_t)(brow + arow) * K + acol;
    const float* Bptr = W + (size_t)brw * N + bcol + bcl;

    const int ty = tid >> 4;   // 0..15 -> M direction (8 rows each)
    const int tx = tid & 15;   // 0..15 -> N direction (8 cols each)

    float acc[8][8];
    #pragma unroll
    for (int i = 0; i < 8; i++)
        #pragma unroll
        for (int j = 0; j < 8; j++) acc[i][j] = 0.0f;

    for (int k0 = 0; k0 < K; k0 += BK) {
        float4 a0 = *(const float4*)(Aptr);
        float4 a1 = *(const float4*)(Aptr + (size_t)64 * K);
        float4 b0 = *(const float4*)(Bptr);
        float4 b1 = *(const float4*)(Bptr + (size_t)8 * N);

        As[acol + 0][arow] = a0.x;
        As[acol + 1][arow] = a0.y;
        As[acol + 2][arow] = a0.z;
        As[acol + 3][arow] = a0.w;
        As[acol + 0][arow + 64] = a1.x;
        As[acol + 1][arow + 64] = a1.y;
        As[acol + 2][arow + 64] = a1.z;
        As[acol + 3][arow + 64] = a1.w;
        *(float4*)&Bs[brw][bcl]     = b0;
        *(float4*)&Bs[brw + 8][bcl] = b1;
        __syncthreads();

        #pragma unroll
        for (int kk = 0; kk < BK; kk++) {
            float af[8], bf[8];
            *(float4*)(af)     = *(const float4*)&As[kk][ty * 8];
            *(float4*)(af + 4) = *(const float4*)&As[kk][ty * 8 + 4];
            *(float4*)(bf)     = *(const float4*)&Bs[kk][tx * 8];
            *(float4*)(bf + 4) = *(const float4*)&Bs[kk][tx * 8 + 4];
            #pragma unroll
            for (int i = 0; i < 8; i++)
                #pragma unroll
                for (int j = 0; j < 8; j++)
                    acc[i][j] = fmaf(af[i], bf[j], acc[i][j]);
        }
        __syncthreads();

        Aptr += BK;
        Bptr += (size_t)BK * N;
    }

    // Epilogue
    const int row = brow + ty * 8;
    const int col = bcol + tx * 8;
    float bs[8];
    #pragma unroll
    for (int j = 0; j < 8; j++) bs[j] = bias[col + j];

    #pragma unroll
    for (int i = 0; i < 8; i++) {
        float4 o0, o1;
        float vals[8];
        #pragma unroll
        for (int j = 0; j < 8; j++) {
            float t = acc[i][j] + bs[j];
            if (RELU) t = fmaxf(t, 0.0f);
            vals[j] = t;
        }
        o0.x = vals[0]; o0.y = vals[1]; o0.z = vals[2]; o0.w = vals[3];
        o1.x = vals[4]; o1.y = vals[5]; o1.z = vals[6]; o1.w = vals[7];
        float* cp = Cmat + (size_t)(row + i) * N + col;
        *(float4*)(cp)     = o0;
        *(float4*)(cp + 4) = o1;
    }
}

// ---------------------------------------------------------------------------
// Deformable attention sampling. One warp per (b, q, head); lane = channel.
// ---------------------------------------------------------------------------
__constant__ int c_SW[4] = {128, 64, 32, 16};
__constant__ int c_SH[4] = {128, 64, 32, 16};
__constant__ int c_START[4] = {0, 16384, 20480, 21504};

__global__ __launch_bounds__(256)
void deform_kernel(const float* __restrict__ off, const float* __restrict__ attr,
                   const float* __restrict__ ref, const float* __restrict__ v,
                   float* __restrict__ outp) {
    const int wid  = blockIdx.x * 8 + (threadIdx.x >> 5);
    const int lane = threadIdx.x & 31;
    const int h    = wid & 7;
    const int bq   = wid >> 3;          // b*LQ + q
    const int b    = bq / LQ_;

    // Softmax over NS*K = 16 attention logits (each lane redundantly)
    const float* ar = attr + (size_t)bq * 128 + h * 16;
    float w[16];
    float mx = -1e30f;
    #pragma unroll
    for (int j = 0; j < 16; j++) { w[j] = ar[j]; mx = fmaxf(mx, w[j]); }
    float s = 0.0f;
    #pragma unroll
    for (int j = 0; j < 16; j++) { w[j] = expf(w[j] - mx); s += w[j]; }
    const float inv_s = 1.0f / s;

    const float refx = ref[bq * 2 + 0];
    const float refy = ref[bq * 2 + 1];
    const float* ob = off + (size_t)bq * 256 + h * 32;
    const float* vb = v + (size_t)b * LQ_ * C_ + h * DK_ + lane;

    float acc = 0.0f;
    #pragma unroll
    for (int l = 0; l < 4; l++) {
        const int   Wl = c_SW[l], Hl = c_SH[l];
        const float fw = (float)Wl, fh = (float)Hl;
        const int   st = c_START[l];
        #pragma unroll
        for (int k = 0; k < KPT; k++) {
            float ox = ob[l * 8 + k * 2 + 0];
            float oy = ob[l * 8 + k * 2 + 1];
            float x = (refx + ox * (1.0f / fw)) * (fw - 1.0f);
            float y = (refy + oy * (1.0f / fh)) * (fh - 1.0f);
            x = fminf(fmaxf(x, 0.0f), fw - 1.0f);
            y = fminf(fmaxf(y, 0.0f), fh - 1.0f);
            float x0f = floorf(x), y0f = floorf(y);
            int x0 = (int)x0f, y0 = (int)y0f;
            int x1 = min(x0 + 1, Wl - 1);
            int y1 = min(y0 + 1, Hl - 1);
            float wx = x - x0f, wy = y - y0f;
            float aw = w[l * 4 + k] * inv_s;

            const float* p00 = vb + (size_t)(st + y0 * Wl + x0) * C_;
            const float* p01 = vb + (size_t)(st + y0 * Wl + x1) * C_;
            const float* p10 = vb + (size_t)(st + y1 * Wl + x0) * C_;
            const float* p11 = vb + (size_t)(st + y1 * Wl + x1) * C_;
            float v00 = *p00, v01 = *p01, v10 = *p10, v11 = *p11;
            float bil = (1.0f - wx) * (1.0f - wy) * v00
                      + wx * (1.0f - wy) * v01
                      + (1.0f - wx) * wy * v10
                      + wx * wy * v11;
            acc = fmaf(aw, bil, acc);
        }
    }
    outp[(size_t)bq * C_ + h * DK_ + lane] = acc;
}

// ---------------------------------------------------------------------------
// LayerNorm with residual: o = LN(a + r) * s + bb. One warp per row (C=256).
// ---------------------------------------------------------------------------
__global__ __launch_bounds__(256)
void ln_residual_kernel(const float* __restrict__ a, const float* __restrict__ r,
                        const float* __restrict__ s, const float* __restrict__ bb,
                        float* __restrict__ o) {
    const int row  = blockIdx.x * 8 + (threadIdx.x >> 5);
    const int lane = threadIdx.x & 31;
    const float* pa = a + (size_t)row * C_;
    const float* pr = r + (size_t)row * C_;

    float vals[8];
    float sum = 0.0f;
    #pragma unroll
    for (int j = 0; j < 8; j++) {
        int e = lane + 32 * j;
        float t = pa[e] + pr[e];
        vals[j] = t;
        sum += t;
    }
    #pragma unroll
    for (int d = 16; d > 0; d >>= 1) sum += __shfl_xor_sync(0xFFFFFFFF, sum, d);
    const float mean = sum * (1.0f / C_);

    float sq = 0.0f;
    #pragma unroll
    for (int j = 0; j < 8; j++) {
        float d = vals[j] - mean;
        sq = fmaf(d, d, sq);
    }
    #pragma unroll
    for (int d = 16; d > 0; d >>= 1) sq += __shfl_xor_sync(0xFFFFFFFF, sq, d);
    const float inv = rsqrtf(sq * (1.0f / C_) + 1e-5f);

    float* po = o + (size_t)row * C_;
    #pragma unroll
    for (int j = 0; j < 8; j++) {
        int e = lane + 32 * j;
        po[e] = (vals[j] - mean) * inv * s[e] + bb[e];
    }
}

// ---------------------------------------------------------------------------
// Host orchestration
// ---------------------------------------------------------------------------
extern "C" void kernel_launch(void* const* d_in, const int* in_sizes, int n_in,
                              void* d_out, int out_size) {
    const float* src  = (const float*)d_in[0];
    const float* pos  = (const float*)d_in[1];
    const float* ref  = (const float*)d_in[2];
    const float* Woff = (const float*)d_in[3];
    const float* boff = (const float*)d_in[4];
    const float* Wat  = (const float*)d_in[5];
    const float* bat  = (const float*)d_in[6];
    const float* Wv   = (const float*)d_in[7];
    const float* bv   = (const float*)d_in[8];
    const float* Wo   = (const float*)d_in[9];
    const float* bo   = (const float*)d_in[10];
    const float* W1   = (const float*)d_in[11];
    const float* b1   = (const float*)d_in[12];
    const float* W2   = (const float*)d_in[13];
    const float* b2   = (const float*)d_in[14];
    const float* n1s  = (const float*)d_in[15];
    const float* n1b  = (const float*)d_in[16];
    const float* n2s  = (const float*)d_in[17];
    const float* n2b  = (const float*)d_in[18];
    float* outp = (float*)d_out;

    float *px, *pxp, *pv, *poff, *patt, *pattn, *pproj, *phid;
    cudaGetSymbolAddress((void**)&px,    g_x);
    cudaGetSymbolAddress((void**)&pxp,   g_xp);
    cudaGetSymbolAddress((void**)&pv,    g_v);
    cudaGetSymbolAddress((void**)&poff,  g_off);
    cudaGetSymbolAddress((void**)&patt,  g_att);
    cudaGetSymbolAddress((void**)&pattn, g_attn);
    cudaGetSymbolAddress((void**)&pproj, g_proj);
    cudaGetSymbolAddress((void**)&phid,  g_hid);

    const int M = MROWS;
    const int n4 = M * C_ / 4;
    dim3 gAdd((n4 + 255) / 256);
    dim3 gG256(C_ / BN, M / BM);        // N=256
    dim3 gG128(1,       M / BM);        // N=128
    dim3 gG1024(FF_ / BN, M / BM);      // N=1024
    dim3 gDef(M);                       // 8 warps/block, NHEAD per bq
    dim3 gLN(M / 8);

    for (int i = 0; i < NL_; i++) {
        const float* xin = (i == 0) ? src : px;
        const float* Woff_i = Woff + (size_t)i * C_ * 256;
        const float* boff_i = boff + (size_t)i * 256;
        const float* Wat_i  = Wat  + (size_t)i * C_ * 128;
        const float* bat_i  = bat  + (size_t)i * 128;
        const float* Wv_i   = Wv   + (size_t)i * C_ * C_;
        const float* bv_i   = bv   + (size_t)i * C_;
        const float* Wo_i   = Wo   + (size_t)i * C_ * C_;
        const float* bo_i   = bo   + (size_t)i * C_;
        const float* W1_i   = W1   + (size_t)i * C_ * FF_;
        const float* b1_i   = b1   + (size_t)i * FF_;
        const float* W2_i   = W2   + (size_t)i * FF_ * C_;
        const float* b2_i   = b2   + (size_t)i * C_;
        const float* n1s_i  = n1s  + (size_t)i * C_;
        const float* n1b_i  = n1b  + (size_t)i * C_;
        const float* n2s_i  = n2s  + (size_t)i * C_;
        const float* n2b_i  = n2b  + (size_t)i * C_;

        addpos_kernel<<<gAdd, 256>>>(xin, pos, pxp, n4);

        sgemm_kernel<0><<<gG256, 256>>>(pxp, Wv_i,  bv_i,  pv,   M, 256, 256);
        sgemm_kernel<0><<<gG256, 256>>>(pxp, Woff_i, boff_i, poff, M, 256, 256);
        sgemm_kernel<0><<<gG128, 256>>>(pxp, Wat_i, bat_i, patt, M, 128, 256);

        deform_kernel<<<gDef, 256>>>(poff, patt, ref, pv, pattn);

        sgemm_kernel<0><<<gG256, 256>>>(pattn, Wo_i, bo_i, pproj, M, 256, 256);
        ln_residual_kernel<<<gLN, 256>>>(pxp, pproj, n1s_i, n1b_i, px);

        sgemm_kernel<1><<<gG1024, 256>>>(px, W1_i, b1_i, phid, M, FF_, 256);
        sgemm_kernel<0><<<gG256, 256>>>(phid, W2_i, b2_i, pproj, M, 256, FF_);

        float* lnout = (i == NL_ - 1) ? outp : px;
        ln_residual_kernel<<<gLN, 256>>>(px, pproj, n2s_i, n2b_i, lnout);
    }
}

// round 3
// speedup vs baseline: 1.0170x; 1.0170x over previous
#include <cuda_runtime.h>
#include <cuda_bf16.h>
#include <math.h>

// Problem constants
#define B_    2
#define LQ_   21760
#define C_    256
#define NHEAD 8
#define KPT   4
#define NL_   6
#define FF_   1024
#define DK_   32
#define MROWS (B_ * LQ_)          // 43520
#define NPACK 640                 // 256 (v) + 256 (off) + 128 (att)

// Scratch buffers (static device globals; no runtime allocation)
__device__ float g_x    [MROWS * C_];
__device__ float g_xp   [MROWS * C_];
__device__ float g_vow  [MROWS * NPACK];   // v | off | att packed per row
__device__ float g_attn [MROWS * C_];
__device__ float g_proj [MROWS * C_];
__device__ float g_hid  [MROWS * FF_];
__device__ float g_wpack[NL_ * C_ * NPACK];
__device__ float g_bpack[NL_ * NPACK];

// ---------------------------------------------------------------------------
// Weight packing: wpack[l][k][0:256)=Wv, [256:512)=Woff, [512:640)=Wat
// ---------------------------------------------------------------------------
__global__ void packw_kernel(const float* __restrict__ Wv,
                             const float* __restrict__ Woff,
                             const float* __restrict__ Wat,
                             float* __restrict__ wp) {
    int idx = blockIdx.x * blockDim.x + threadIdx.x;   // over NL*C*NPACK
    if (idx >= NL_ * C_ * NPACK) return;
    int n = idx % NPACK;
    int k = (idx / NPACK) % C_;
    int l = idx / (NPACK * C_);
    float val;
    if (n < 256)      val = Wv  [((size_t)l * C_ + k) * 256 + n];
    else if (n < 512) val = Woff[((size_t)l * C_ + k) * 256 + (n - 256)];
    else              val = Wat [((size_t)l * C_ + k) * 128 + (n - 512)];
    wp[idx] = val;
}

__global__ void packb_kernel(const float* __restrict__ bv,
                             const float* __restrict__ boff,
                             const float* __restrict__ bat,
                             float* __restrict__ bp) {
    int idx = blockIdx.x * blockDim.x + threadIdx.x;   // over NL*NPACK
    if (idx >= NL_ * NPACK) return;
    int n = idx % NPACK;
    int l = idx / NPACK;
    float val;
    if (n < 256)      val = bv  [(size_t)l * 256 + n];
    else if (n < 512) val = boff[(size_t)l * 256 + (n - 256)];
    else              val = bat [(size_t)l * 128 + (n - 512)];
    bp[idx] = val;
}

// ---------------------------------------------------------------------------
// Elementwise: xp = x + pos
// ---------------------------------------------------------------------------
__global__ void addpos_kernel(const float* __restrict__ x,
                              const float* __restrict__ pos,
                              float* __restrict__ xp, int n4) {
    int i = blockIdx.x * blockDim.x + threadIdx.x;
    if (i < n4) {
        float4 a = ((const float4*)x)[i];
        float4 b = ((const float4*)pos)[i];
        float4 o;
        o.x = a.x + b.x; o.y = a.y + b.y; o.z = a.z + b.z; o.w = a.w + b.w;
        ((float4*)xp)[i] = o;
    }
}

// ---------------------------------------------------------------------------
// SGEMM with packed f32x2 FMA (FFMA2): C = A[M,K] @ W[K,N] + bias  (opt ReLU)
// BM=128, BNt in {64,128}, BK=16, 256 threads, per-thread 8 x (BNt/16).
// ---------------------------------------------------------------------------
#define BM 128
#define BK 16

template<int BNt, int RELU>
__global__ __launch_bounds__(256, 2)
void sgemm_f32x2(const float* __restrict__ A, const float* __restrict__ W,
                 const float* __restrict__ bias, float* __restrict__ Cmat,
                 int M, int N, int K) {
    constexpr int EN = BNt / 16;   // cols per thread: 8 or 4
    constexpr int PN = EN / 2;     // f32x2 packs per thread: 4 or 2

    __shared__ float As[BK][BM + 4];
    __shared__ float Bs[BK][BNt];

    const int tid  = threadIdx.x;
    const int brow = blockIdx.y * BM;
    const int bcol = blockIdx.x * BNt;

    // A-load: row = tid/4 (0..63) and +64; col4 = (tid&3)*4
    const int arow = tid >> 2;
    const int acol = (tid & 3) << 2;
    const float* Aptr = A + (size_t)(brow + arow) * K + acol;

    const int ty = tid >> 4;   // 0..15 -> M (8 rows each)
    const int tx = tid & 15;   // 0..15 -> N (EN cols each)

    unsigned long long acc[8][PN];
    #pragma unroll
    for (int i = 0; i < 8; i++)
        #pragma unroll
        for (int j = 0; j < PN; j++) acc[i][j] = 0ull;

    // B-load mapping
    int brw, bcl;
    if (BNt == 128) { brw = tid >> 5; bcl = (tid & 31) << 2; }  // 8 rows, +8
    else            { brw = tid >> 4; bcl = (tid & 15) << 2; }  // 16 rows
    const float* Bptr = W + (size_t)brw * N + bcol + bcl;

    for (int k0 = 0; k0 < K; k0 += BK) {
        float4 a0 = *(const float4*)(Aptr);
        float4 a1 = *(const float4*)(Aptr + (size_t)64 * K);
        As[acol + 0][arow]      = a0.x;
        As[acol + 1][arow]      = a0.y;
        As[acol + 2][arow]      = a0.z;
        As[acol + 3][arow]      = a0.w;
        As[acol + 0][arow + 64] = a1.x;
        As[acol + 1][arow + 64] = a1.y;
        As[acol + 2][arow + 64] = a1.z;
        As[acol + 3][arow + 64] = a1.w;

        if (BNt == 128) {
            float4 b0 = *(const float4*)(Bptr);
            float4 b1 = *(const float4*)(Bptr + (size_t)8 * N);
            *(float4*)&Bs[brw][bcl]     = b0;
            *(float4*)&Bs[brw + 8][bcl] = b1;
        } else {
            float4 b0 = *(const float4*)(Bptr);
            *(float4*)&Bs[brw][bcl] = b0;
        }
        __syncthreads();

        #pragma unroll
        for (int kk = 0; kk < BK; kk++) {
            float af[8];
            *(float4*)(af)     = *(const float4*)&As[kk][ty * 8];
            *(float4*)(af + 4) = *(const float4*)&As[kk][ty * 8 + 4];

            unsigned long long bp[PN];
            #pragma unroll
            for (int p = 0; p < PN; p += 2) {
                // packs p and p+1 = floats [tx*EN + p*2 .. tx*EN + p*2 + 3]
                ulonglong2 t = *(const ulonglong2*)&Bs[kk][tx * EN + p * 2];
                bp[p]     = t.x;
                bp[p + 1] = t.y;
            }

            #pragma unroll
            for (int i = 0; i < 8; i++) {
                unsigned long long a2;
                unsigned int au = __float_as_uint(af[i]);
                asm("mov.b64 %0, {%1, %1};" : "=l"(a2) : "r"(au));
                #pragma unroll
                for (int j = 0; j < PN; j++)
                    asm("fma.rn.f32x2 %0, %1, %2, %0;"
                        : "+l"(acc[i][j]) : "l"(a2), "l"(bp[j]));
            }
        }
        __syncthreads();

        Aptr += BK;
        Bptr += (size_t)BK * N;
    }

    // Epilogue
    const int row = brow + ty * 8;
    const int col = bcol + tx * EN;
    float bs[EN];
    #pragma unroll
    for (int j = 0; j < EN; j++) bs[j] = bias[col + j];

    #pragma unroll
    for (int i = 0; i < 8; i++) {
        float vals[EN];
        #pragma unroll
        for (int j = 0; j < PN; j++) {
            unsigned long long u = acc[i][j];
            float lo = __uint_as_float((unsigned int)(u & 0xffffffffull));
            float hi = __uint_as_float((unsigned int)(u >> 32));
            float t0 = lo + bs[j * 2 + 0];
            float t1 = hi + bs[j * 2 + 1];
            if (RELU) { t0 = fmaxf(t0, 0.0f); t1 = fmaxf(t1, 0.0f); }
            vals[j * 2 + 0] = t0;
            vals[j * 2 + 1] = t1;
        }
        float* cp = Cmat + (size_t)(row + i) * N + col;
        #pragma unroll
        for (int j = 0; j < EN; j += 4) {
            float4 o;
            o.x = vals[j]; o.y = vals[j + 1]; o.z = vals[j + 2]; o.w = vals[j + 3];
            *(float4*)(cp + j) = o;
        }
    }
}

// ---------------------------------------------------------------------------
// Deformable attention sampling. One warp per (b, q, head); lane = channel.
// Reads v/off/att from the packed vow buffer (row stride NPACK).
// ---------------------------------------------------------------------------
__constant__ int c_SW[4] = {128, 64, 32, 16};
__constant__ int c_SH[4] = {128, 64, 32, 16};
__constant__ int c_START[4] = {0, 16384, 20480, 21504};

__global__ __launch_bounds__(256)
void deform_kernel(const float* __restrict__ vow, const float* __restrict__ ref,
                   float* __restrict__ outp) {
    const int wid  = blockIdx.x * 8 + (threadIdx.x >> 5);
    const int lane = threadIdx.x & 31;
    const int h    = wid & 7;
    const int bq   = wid >> 3;          // b*LQ + q
    const int b    = bq / LQ_;

    // Softmax over NS*K = 16 attention logits (each lane redundantly)
    const float* ar = vow + (size_t)bq * NPACK + 512 + h * 16;
    float w[16];
    float mx = -1e30f;
    #pragma unroll
    for (int j = 0; j < 16; j++) { w[j] = ar[j]; mx = fmaxf(mx, w[j]); }
    float s = 0.0f;
    #pragma unroll
    for (int j = 0; j < 16; j++) { w[j] = expf(w[j] - mx); s += w[j]; }
    const float inv_s = 1.0f / s;

    const float refx = ref[bq * 2 + 0];
    const float refy = ref[bq * 2 + 1];
    const float* ob = vow + (size_t)bq * NPACK + 256 + h * 32;
    const float* vb = vow + (size_t)b * LQ_ * NPACK + h * DK_ + lane;

    float acc = 0.0f;
    #pragma unroll
    for (int l = 0; l < 4; l++) {
        const int   Wl = c_SW[l], Hl = c_SH[l];
        const float fw = (float)Wl, fh = (float)Hl;
        const int   st = c_START[l];
        #pragma unroll
        for (int k = 0; k < KPT; k++) {
            float ox = ob[l * 8 + k * 2 + 0];
            float oy = ob[l * 8 + k * 2 + 1];
            float x = (refx + ox * (1.0f / fw)) * (fw - 1.0f);
            float y = (refy + oy * (1.0f / fh)) * (fh - 1.0f);
            x = fminf(fmaxf(x, 0.0f), fw - 1.0f);
            y = fminf(fmaxf(y, 0.0f), fh - 1.0f);
            float x0f = floorf(x), y0f = floorf(y);
            int x0 = (int)x0f, y0 = (int)y0f;
            int x1 = min(x0 + 1, Wl - 1);
            int y1 = min(y0 + 1, Hl - 1);
            float wx = x - x0f, wy = y - y0f;
            float aw = w[l * 4 + k] * inv_s;

            const float* p00 = vb + (size_t)(st + y0 * Wl + x0) * NPACK;
            const float* p01 = vb + (size_t)(st + y0 * Wl + x1) * NPACK;
            const float* p10 = vb + (size_t)(st + y1 * Wl + x0) * NPACK;
            const float* p11 = vb + (size_t)(st + y1 * Wl + x1) * NPACK;
            float v00 = *p00, v01 = *p01, v10 = *p10, v11 = *p11;
            float bil = (1.0f - wx) * (1.0f - wy) * v00
                      + wx * (1.0f - wy) * v01
                      + (1.0f - wx) * wy * v10
                      + wx * wy * v11;
            acc = fmaf(aw, bil, acc);
        }
    }
    outp[(size_t)bq * C_ + h * DK_ + lane] = acc;
}

// ---------------------------------------------------------------------------
// LayerNorm with residual: o = LN(a + r) * s + bb. One warp per row (C=256).
// ---------------------------------------------------------------------------
__global__ __launch_bounds__(256)
void ln_residual_kernel(const float* __restrict__ a, const float* __restrict__ r,
                        const float* __restrict__ s, const float* __restrict__ bb,
                        float* __restrict__ o) {
    const int row  = blockIdx.x * 8 + (threadIdx.x >> 5);
    const int lane = threadIdx.x & 31;
    const float* pa = a + (size_t)row * C_;
    const float* pr = r + (size_t)row * C_;

    float vals[8];
    float sum = 0.0f;
    #pragma unroll
    for (int j = 0; j < 8; j++) {
        int e = lane + 32 * j;
        float t = pa[e] + pr[e];
        vals[j] = t;
        sum += t;
    }
    #pragma unroll
    for (int d = 16; d > 0; d >>= 1) sum += __shfl_xor_sync(0xFFFFFFFF, sum, d);
    const float mean = sum * (1.0f / C_);

    float sq = 0.0f;
    #pragma unroll
    for (int j = 0; j < 8; j++) {
        float d = vals[j] - mean;
        sq = fmaf(d, d, sq);
    }
    #pragma unroll
    for (int d = 16; d > 0; d >>= 1) sq += __shfl_xor_sync(0xFFFFFFFF, sq, d);
    const float inv = rsqrtf(sq * (1.0f / C_) + 1e-5f);

    float* po = o + (size_t)row * C_;
    #pragma unroll
    for (int j = 0; j < 8; j++) {
        int e = lane + 32 * j;
        po[e] = (vals[j] - mean) * inv * s[e] + bb[e];
    }
}

// ---------------------------------------------------------------------------
// Host orchestration
// ---------------------------------------------------------------------------
extern "C" void kernel_launch(void* const* d_in, const int* in_sizes, int n_in,
                              void* d_out, int out_size) {
    const float* src  = (const float*)d_in[0];
    const float* pos  = (const float*)d_in[1];
    const float* ref  = (const float*)d_in[2];
    const float* Woff = (const float*)d_in[3];
    const float* boff = (const float*)d_in[4];
    const float* Wat  = (const float*)d_in[5];
    const float* bat  = (const float*)d_in[6];
    const float* Wv   = (const float*)d_in[7];
    const float* bv   = (const float*)d_in[8];
    const float* Wo   = (const float*)d_in[9];
    const float* bo   = (const float*)d_in[10];
    const float* W1   = (const float*)d_in[11];
    const float* b1   = (const float*)d_in[12];
    const float* W2   = (const float*)d_in[13];
    const float* b2   = (const float*)d_in[14];
    const float* n1s  = (const float*)d_in[15];
    const float* n1b  = (const float*)d_in[16];
    const float* n2s  = (const float*)d_in[17];
    const float* n2b  = (const float*)d_in[18];
    float* outp = (float*)d_out;

    float *px, *pxp, *pvow, *pattn, *pproj, *phid, *pwp, *pbp;
    cudaGetSymbolAddress((void**)&px,    g_x);
    cudaGetSymbolAddress((void**)&pxp,   g_xp);
    cudaGetSymbolAddress((void**)&pvow,  g_vow);
    cudaGetSymbolAddress((void**)&pattn, g_attn);
    cudaGetSymbolAddress((void**)&pproj, g_proj);
    cudaGetSymbolAddress((void**)&phid,  g_hid);
    cudaGetSymbolAddress((void**)&pwp,   g_wpack);
    cudaGetSymbolAddress((void**)&pbp,   g_bpack);

    const int M = MROWS;
    const int n4 = M * C_ / 4;

    // One-time weight packing for the fused projection GEMM
    {
        int tot = NL_ * C_ * NPACK;
        packw_kernel<<<(tot + 255) / 256, 256>>>(Wv, Woff, Wat, pwp);
        int tb = NL_ * NPACK;
        packb_kernel<<<(tb + 255) / 256, 256>>>(bv, boff, bat, pbp);
    }

    dim3 gAdd((n4 + 255) / 256);
    dim3 gG640(NPACK / 128, M / BM);   // fused projections, BN=128
    dim3 gG256(C_ / 64, M / BM);       // N=256 outputs, BN=64 (tail-friendly)
    dim3 gG1024(FF_ / 128, M / BM);    // FFN up, BN=128
    dim3 gDef(M);                      // 8 warps/block
    dim3 gLN(M / 8);

    for (int i = 0; i < NL_; i++) {
        const float* xin = (i == 0) ? src : px;
        const float* wp_i = pwp + (size_t)i * C_ * NPACK;
        const float* bp_i = pbp + (size_t)i * NPACK;
        const float* Wo_i = Wo + (size_t)i * C_ * C_;
        const float* bo_i = bo + (size_t)i * C_;
        const float* W1_i = W1 + (size_t)i * C_ * FF_;
        const float* b1_i = b1 + (size_t)i * FF_;
        const float* W2_i = W2 + (size_t)i * FF_ * C_;
        const float* b2_i = b2 + (size_t)i * C_;

        addpos_kernel<<<gAdd, 256>>>(xin, pos, pxp, n4);

        sgemm_f32x2<128, 0><<<gG640, 256>>>(pxp, wp_i, bp_i, pvow, M, NPACK, 256);

        deform_kernel<<<gDef, 256>>>(pvow, ref, pattn);

        sgemm_f32x2<64, 0><<<gG256, 256>>>(pattn, Wo_i, bo_i, pproj, M, 256, 256);
        ln_residual_kernel<<<gLN, 256>>>(pxp, pproj, n1s + (size_t)i * C_,
                                         n1b + (size_t)i * C_, px);

        sgemm_f32x2<128, 1><<<gG1024, 256>>>(px, W1_i, b1_i, phid, M, FF_, 256);
        sgemm_f32x2<64, 0><<<gG256, 256>>>(phid, W2_i, b2_i, pproj, M, 256, FF_);

        float* lnout = (i == NL_ - 1) ? outp : px;
        ln_residual_kernel<<<gLN, 256>>>(px, pproj, n2s + (size_t)i * C_,
                                         n2b + (size_t)i * C_, lnout);
    }
}

// round 6
// speedup vs baseline: 1.5358x; 1.5100x over previous
#include <cuda_runtime.h>
#include <cuda_bf16.h>
#include <math.h>
#include <stdint.h>

// Problem constants
#define B_    2
#define LQ_   21760
#define C_    256
#define NHEAD 8
#define KPT   4
#define NL_   6
#define FF_   1024
#define DK_   32
#define MROWS (B_ * LQ_)          // 43520
#define NPACK 640                 // 256 (v) + 256 (off) + 128 (att)

// ---------------------------------------------------------------------------
// Device scratch (no runtime allocation)
// ---------------------------------------------------------------------------
__device__ float g_x    [MROWS * C_];
__device__ float g_xp   [MROWS * C_];
__device__ float g_vow  [MROWS * NPACK];
__device__ float g_proj [MROWS * C_];

// Activation bf16 split pairs
__device__ __nv_bfloat16 g_pa_h[MROWS * C_];
__device__ __nv_bfloat16 g_pa_l[MROWS * C_];
__device__ __nv_bfloat16 g_ph_h[MROWS * FF_];
__device__ __nv_bfloat16 g_ph_l[MROWS * FF_];

// Weight bf16 split pairs, [N,K] transposed layout
__device__ __nv_bfloat16 g_wproj_h[NL_ * NPACK * C_];
__device__ __nv_bfloat16 g_wproj_l[NL_ * NPACK * C_];
__device__ __nv_bfloat16 g_wo_h[NL_ * C_ * C_];
__device__ __nv_bfloat16 g_wo_l[NL_ * C_ * C_];
__device__ __nv_bfloat16 g_w1_h[NL_ * FF_ * C_];
__device__ __nv_bfloat16 g_w1_l[NL_ * FF_ * C_];
__device__ __nv_bfloat16 g_w2_h[NL_ * C_ * FF_];
__device__ __nv_bfloat16 g_w2_l[NL_ * C_ * FF_];
__device__ float g_bpack[NL_ * NPACK];

// ---------------------------------------------------------------------------
// Helpers
// ---------------------------------------------------------------------------
__device__ __forceinline__ uint32_t smem_u32(const void* p) {
    uint32_t a;
    asm("{ .reg .u64 t; cvta.to.shared.u64 t, %1; cvt.u32.u64 %0, t; }"
        : "=r"(a) : "l"(p));
    return a;
}

__device__ __forceinline__ void bf16_split(float v, __nv_bfloat16& h, __nv_bfloat16& l) {
    h = __float2bfloat16(v);
    l = __float2bfloat16(v - __bfloat162float(h));
}

#define MMA_BF16(d, a, b0v, b1v)                                              \
    asm volatile("mma.sync.aligned.m16n8k16.row.col.f32.bf16.bf16.f32 "       \
        "{%0,%1,%2,%3}, {%4,%5,%6,%7}, {%8,%9}, {%0,%1,%2,%3};"               \
        : "+f"((d)[0]), "+f"((d)[1]), "+f"((d)[2]), "+f"((d)[3])              \
        : "r"((a)[0]), "r"((a)[1]), "r"((a)[2]), "r"((a)[3]),                 \
          "r"(b0v), "r"(b1v))

#define LDMATRIX_X4(r0, r1, r2, r3, addr)                                     \
    asm volatile("ldmatrix.sync.aligned.m8n8.x4.shared.b16 {%0,%1,%2,%3}, [%4];" \
        : "=r"(r0), "=r"(r1), "=r"(r2), "=r"(r3) : "r"(addr))

#define CP_ASYNC16(saddr, gptr)                                               \
    asm volatile("cp.async.cg.shared.global [%0], [%1], 16;"                  \
        :: "r"(saddr), "l"(gptr))

// ---------------------------------------------------------------------------
// Weight packing (fp32 [K,N] -> bf16 hi/lo [N,K])
// ---------------------------------------------------------------------------
__global__ void pack_proj_w(const float* __restrict__ Wv,
                            const float* __restrict__ Woff,
                            const float* __restrict__ Wat,
                            __nv_bfloat16* __restrict__ Bh,
                            __nv_bfloat16* __restrict__ Bl) {
    int idx = blockIdx.x * blockDim.x + threadIdx.x;   // NL*640*256
    if (idx >= NL_ * NPACK * C_) return;
    int k = idx & 255;
    int n = (idx >> 8) % NPACK;
    int l = idx / (NPACK * C_);
    float v;
    if (n < 256)      v = Wv  [((size_t)l * C_ + k) * 256 + n];
    else if (n < 512) v = Woff[((size_t)l * C_ + k) * 256 + (n - 256)];
    else              v = Wat [((size_t)l * C_ + k) * 128 + (n - 512)];
    __nv_bfloat16 h, lo;
    bf16_split(v, h, lo);
    Bh[idx] = h; Bl[idx] = lo;
}

__global__ void pack_w(const float* __restrict__ W,
                       __nv_bfloat16* __restrict__ Bh,
                       __nv_bfloat16* __restrict__ Bl, int K, int N) {
    int idx = blockIdx.x * blockDim.x + threadIdx.x;   // NL*N*K
    if (idx >= NL_ * N * K) return;
    int k = idx % K;
    int n = (idx / K) % N;
    int l = idx / (N * K);
    float v = W[(size_t)l * K * N + (size_t)k * N + n];
    __nv_bfloat16 h, lo;
    bf16_split(v, h, lo);
    Bh[idx] = h; Bl[idx] = lo;
}

__global__ void packb_kernel(const float* __restrict__ bv,
                             const float* __restrict__ boff,
                             const float* __restrict__ bat,
                             float* __restrict__ bp) {
    int idx = blockIdx.x * blockDim.x + threadIdx.x;
    if (idx >= NL_ * NPACK) return;
    int n = idx % NPACK;
    int l = idx / NPACK;
    float val;
    if (n < 256)      val = bv  [(size_t)l * 256 + n];
    else if (n < 512) val = boff[(size_t)l * 256 + (n - 256)];
    else              val = bat [(size_t)l * 128 + (n - 512)];
    bp[idx] = val;
}

// ---------------------------------------------------------------------------
// addpos: xp = x + pos (fp32) + bf16 split pair
// ---------------------------------------------------------------------------
__global__ void addpos_pair(const float* __restrict__ x,
                            const float* __restrict__ pos,
                            float* __restrict__ xp,
                            __nv_bfloat16* __restrict__ ph,
                            __nv_bfloat16* __restrict__ pl, int n4) {
    int i = blockIdx.x * blockDim.x + threadIdx.x;
    if (i >= n4) return;
    float4 a = ((const float4*)x)[i];
    float4 b = ((const float4*)pos)[i];
    float4 o;
    o.x = a.x + b.x; o.y = a.y + b.y; o.z = a.z + b.z; o.w = a.w + b.w;
    ((float4*)xp)[i] = o;
    __nv_bfloat16 h0, l0, h1, l1, h2, l2, h3, l3;
    bf16_split(o.x, h0, l0); bf16_split(o.y, h1, l1);
    bf16_split(o.z, h2, l2); bf16_split(o.w, h3, l3);
    ((__nv_bfloat162*)ph)[i * 2]     = __halves2bfloat162(h0, h1);
    ((__nv_bfloat162*)ph)[i * 2 + 1] = __halves2bfloat162(h2, h3);
    ((__nv_bfloat162*)pl)[i * 2]     = __halves2bfloat162(l0, l1);
    ((__nv_bfloat162*)pl)[i * 2 + 1] = __halves2bfloat162(l2, l3);
}

// ---------------------------------------------------------------------------
// mma.sync bf16 split-precision GEMM (sm_80-compatible instructions only).
// C[M,N] = (Ah+Al)[M,K] @ (Bh+Bl)[N,K]^T + bias   (3-term split)
// CTA 128x128, BK=64, 8 warps (4Mx2N), warp tile 32x64.
// cp.async double-buffered; SW128-style xor swizzle; dynamic smem 64KB.
// ---------------------------------------------------------------------------
template<int RELU, int PAIR>
__global__ __launch_bounds__(256)
void mma_gemm(const __nv_bfloat16* __restrict__ Ah,
              const __nv_bfloat16* __restrict__ Al,
              const __nv_bfloat16* __restrict__ Bh,
              const __nv_bfloat16* __restrict__ Bl,
              const float* __restrict__ bias,
              float* __restrict__ Cf,
              __nv_bfloat16* __restrict__ Ch,
              __nv_bfloat16* __restrict__ Cl,
              int N, int K) {
    extern __shared__ uint8_t smem[];
    const int tid  = threadIdx.x;
    const int wid  = tid >> 5;
    const int lane = tid & 31;
    const int brow = blockIdx.y * 128;
    const int bcol = blockIdx.x * 128;
    const int kIters = K >> 6;
    const int tIters = 3 * kIters;

    const int ldrow = tid >> 1;          // 0..127 (row within tile)
    const int ldcb  = (tid & 1) << 2;    // chunk base: 0 or 4 (16B chunks)

    const uint32_t smbase = smem_u32(smem);

    // Issue cp.async for tile t into buffer buf
    auto load_tile = [&](int t, int buf) {
        int phase = (t >= kIters) + (t >= 2 * kIters);
        int koff  = (t - phase * kIters) << 6;
        const __nv_bfloat16* As = (phase == 2) ? Al : Ah;
        const __nv_bfloat16* Bs = (phase == 1) ? Bl : Bh;
        uint32_t sA = smbase + buf * 32768;
        uint32_t sB = sA + 16384;
        const __nv_bfloat16* ga = As + (size_t)(brow + ldrow) * K + koff + ldcb * 8;
        const __nv_bfloat16* gb = Bs + (size_t)(bcol + ldrow) * K + koff + ldcb * 8;
        const uint32_t rb = ldrow * 128;
        #pragma unroll
        for (int j = 0; j < 4; j++) {
            uint32_t sw = rb + (((ldcb + j) ^ (ldrow & 7)) << 4);
            CP_ASYNC16(sA + sw, ga + j * 8);
            CP_ASYNC16(sB + sw, gb + j * 8);
        }
    };

    const int wm = (wid & 3) * 32;
    const int wn = (wid >> 2) * 64;

    float acc[2][8][4];
    #pragma unroll
    for (int mi = 0; mi < 2; mi++)
        #pragma unroll
        for (int nj = 0; nj < 8; nj++)
            #pragma unroll
            for (int r = 0; r < 4; r++) acc[mi][nj][r] = 0.0f;

    auto compute = [&](int buf) {
        uint32_t sA = smbase + buf * 32768;
        uint32_t sB = sA + 16384;
        #pragma unroll
        for (int ks = 0; ks < 4; ks++) {
            uint32_t a[2][4];
            #pragma unroll
            for (int mi = 0; mi < 2; mi++) {
                int r = wm + mi * 16 + (lane & 15);
                int c = ks * 2 + (lane >> 4);
                uint32_t addr = sA + r * 128 + ((c ^ (r & 7)) << 4);
                LDMATRIX_X4(a[mi][0], a[mi][1], a[mi][2], a[mi][3], addr);
            }
            #pragma unroll
            for (int ng = 0; ng < 4; ng++) {
                uint32_t b0, b1, b2, b3;
                int r = wn + ng * 16 + (lane & 15);
                int c = ks * 2 + (lane >> 4);
                uint32_t addr = sB + r * 128 + ((c ^ (r & 7)) << 4);
                LDMATRIX_X4(b0, b1, b2, b3, addr);
                #pragma unroll
                for (int mi = 0; mi < 2; mi++) {
                    MMA_BF16(acc[mi][ng * 2 + 0], a[mi], b0, b2);
                    MMA_BF16(acc[mi][ng * 2 + 1], a[mi], b1, b3);
                }
            }
        }
    };

    // 2-stage pipeline
    load_tile(0, 0);
    asm volatile("cp.async.commit_group;" ::: "memory");
    for (int t = 0; t < tIters; t++) {
        const int buf = t & 1;
        if (t + 1 < tIters) {
            load_tile(t + 1, (t + 1) & 1);
            asm volatile("cp.async.commit_group;" ::: "memory");
            asm volatile("cp.async.wait_group 1;" ::: "memory");
        } else {
            asm volatile("cp.async.wait_group 0;" ::: "memory");
        }
        __syncthreads();
        compute(buf);
        __syncthreads();
    }

    // Epilogue
    const int tr = lane >> 2;            // 0..7
    const int tc = (lane & 3) * 2;
    #pragma unroll
    for (int mi = 0; mi < 2; mi++) {
        #pragma unroll
        for (int nj = 0; nj < 8; nj++) {
            const int col = bcol + wn + nj * 8 + tc;
            const float bb0 = bias[col], bb1 = bias[col + 1];
            #pragma unroll
            for (int rr = 0; rr < 2; rr++) {
                const int row = brow + wm + mi * 16 + rr * 8 + tr;
                float v0 = acc[mi][nj][rr * 2 + 0] + bb0;
                float v1 = acc[mi][nj][rr * 2 + 1] + bb1;
                if (RELU) { v0 = fmaxf(v0, 0.f); v1 = fmaxf(v1, 0.f); }
                if (!PAIR) {
                    float2 o; o.x = v0; o.y = v1;
                    *(float2*)(Cf + (size_t)row * N + col) = o;
                } else {
                    __nv_bfloat16 h0, l0, h1, l1;
                    bf16_split(v0, h0, l0);
                    bf16_split(v1, h1, l1);
                    size_t idx = (size_t)row * N + col;
                    *(__nv_bfloat162*)(Ch + idx) = __halves2bfloat162(h0, h1);
                    *(__nv_bfloat162*)(Cl + idx) = __halves2bfloat162(l0, l1);
                }
            }
        }
    }
}

// ---------------------------------------------------------------------------
// Deformable attention sampling. One warp per (b,q,head); lane = channel.
// Output: bf16 split pair (feeds Wo GEMM).
// ---------------------------------------------------------------------------
__constant__ int c_SW[4] = {128, 64, 32, 16};
__constant__ int c_START[4] = {0, 16384, 20480, 21504};

__global__ __launch_bounds__(256)
void deform_kernel(const float* __restrict__ vow, const float* __restrict__ ref,
                   __nv_bfloat16* __restrict__ oh, __nv_bfloat16* __restrict__ ol) {
    const int wid  = blockIdx.x * 8 + (threadIdx.x >> 5);
    const int lane = threadIdx.x & 31;
    const int h    = wid & 7;
    const int bq   = wid >> 3;
    const int b    = bq / LQ_;

    const float* ar = vow + (size_t)bq * NPACK + 512 + h * 16;
    float w[16];
    float mx = -1e30f;
    #pragma unroll
    for (int j = 0; j < 16; j++) { w[j] = ar[j]; mx = fmaxf(mx, w[j]); }
    float s = 0.0f;
    #pragma unroll
    for (int j = 0; j < 16; j++) { w[j] = expf(w[j] - mx); s += w[j]; }
    const float inv_s = 1.0f / s;

    const float refx = ref[bq * 2 + 0];
    const float refy = ref[bq * 2 + 1];
    const float* ob = vow + (size_t)bq * NPACK + 256 + h * 32;
    const float* vb = vow + (size_t)b * LQ_ * NPACK + h * DK_ + lane;

    float acc = 0.0f;
    #pragma unroll
    for (int l = 0; l < 4; l++) {
        const int   Wl = c_SW[l];
        const float fw = (float)Wl;
        const int   st = c_START[l];
        #pragma unroll
        for (int k = 0; k < KPT; k++) {
            float ox = ob[l * 8 + k * 2 + 0];
            float oy = ob[l * 8 + k * 2 + 1];
            float x = (refx + ox * (1.0f / fw)) * (fw - 1.0f);
            float y = (refy + oy * (1.0f / fw)) * (fw - 1.0f);
            x = fminf(fmaxf(x, 0.0f), fw - 1.0f);
            y = fminf(fmaxf(y, 0.0f), fw - 1.0f);
            float x0f = floorf(x), y0f = floorf(y);
            int x0 = (int)x0f, y0 = (int)y0f;
            int x1 = min(x0 + 1, Wl - 1);
            int y1 = min(y0 + 1, Wl - 1);
            float wx = x - x0f, wy = y - y0f;
            float aw = w[l * 4 + k] * inv_s;

            const float* p00 = vb + (size_t)(st + y0 * Wl + x0) * NPACK;
            const float* p01 = vb + (size_t)(st + y0 * Wl + x1) * NPACK;
            const float* p10 = vb + (size_t)(st + y1 * Wl + x0) * NPACK;
            const float* p11 = vb + (size_t)(st + y1 * Wl + x1) * NPACK;
            float v00 = *p00, v01 = *p01, v10 = *p10, v11 = *p11;
            float bil = (1.0f - wx) * (1.0f - wy) * v00
                      + wx * (1.0f - wy) * v01
                      + (1.0f - wx) * wy * v10
                      + wx * wy * v11;
            acc = fmaf(aw, bil, acc);
        }
    }
    __nv_bfloat16 hh, ll;
    bf16_split(acc, hh, ll);
    size_t idx = (size_t)bq * C_ + h * DK_ + lane;
    oh[idx] = hh; ol[idx] = ll;
}

// ---------------------------------------------------------------------------
// LayerNorm w/ residual: o = LN(a + r)*s + bb; optional bf16 split pair out.
// ---------------------------------------------------------------------------
template<int PAIR>
__global__ __launch_bounds__(256)
void ln_residual(const float* __restrict__ a, const float* __restrict__ r,
                 const float* __restrict__ s, const float* __restrict__ bb,
                 float* __restrict__ o,
                 __nv_bfloat16* __restrict__ ph, __nv_bfloat16* __restrict__ pl) {
    const int row  = blockIdx.x * 8 + (threadIdx.x >> 5);
    const int lane = threadIdx.x & 31;
    const float* pa = a + (size_t)row * C_;
    const float* pr = r + (size_t)row * C_;

    float vals[8];
    float sum = 0.0f;
    #pragma unroll
    for (int j = 0; j < 8; j++) {
        int e = lane + 32 * j;
        float t = pa[e] + pr[e];
        vals[j] = t;
        sum += t;
    }
    #pragma unroll
    for (int d = 16; d > 0; d >>= 1) sum += __shfl_xor_sync(0xFFFFFFFF, sum, d);
    const float mean = sum * (1.0f / C_);

    float sq = 0.0f;
    #pragma unroll
    for (int j = 0; j < 8; j++) {
        float d = vals[j] - mean;
        sq = fmaf(d, d, sq);
    }
    #pragma unroll
    for (int d = 16; d > 0; d >>= 1) sq += __shfl_xor_sync(0xFFFFFFFF, sq, d);
    const float inv = rsqrtf(sq * (1.0f / C_) + 1e-5f);

    float* po = o + (size_t)row * C_;
    #pragma unroll
    for (int j = 0; j < 8; j++) {
        int e = lane + 32 * j;
        float v = (vals[j] - mean) * inv * s[e] + bb[e];
        po[e] = v;
        if (PAIR) {
            __nv_bfloat16 h, lo;
            bf16_split(v, h, lo);
            ph[(size_t)row * C_ + e] = h;
            pl[(size_t)row * C_ + e] = lo;
        }
    }
}

// ---------------------------------------------------------------------------
// Host orchestration
// ---------------------------------------------------------------------------
extern "C" void kernel_launch(void* const* d_in, const int* in_sizes, int n_in,
                              void* d_out, int out_size) {
    const float* src  = (const float*)d_in[0];
    const float* pos  = (const float*)d_in[1];
    const float* ref  = (const float*)d_in[2];
    const float* Woff = (const float*)d_in[3];
    const float* boff = (const float*)d_in[4];
    const float* Wat  = (const float*)d_in[5];
    const float* bat  = (const float*)d_in[6];
    const float* Wv   = (const float*)d_in[7];
    const float* bv   = (const float*)d_in[8];
    const float* Wo   = (const float*)d_in[9];
    const float* bo   = (const float*)d_in[10];
    const float* W1   = (const float*)d_in[11];
    const float* b1   = (const float*)d_in[12];
    const float* W2   = (const float*)d_in[13];
    const float* b2   = (const float*)d_in[14];
    const float* n1s  = (const float*)d_in[15];
    const float* n1b  = (const float*)d_in[16];
    const float* n2s  = (const float*)d_in[17];
    const float* n2b  = (const float*)d_in[18];
    float* outp = (float*)d_out;

    float *px, *pxp, *pvow, *pproj, *pbp;
    __nv_bfloat16 *pah, *pal, *phh, *phl;
    __nv_bfloat16 *wprojh, *wprojl, *woh, *wol, *w1h, *w1l, *w2h, *w2l;
    cudaGetSymbolAddress((void**)&px,     g_x);
    cudaGetSymbolAddress((void**)&pxp,    g_xp);
    cudaGetSymbolAddress((void**)&pvow,   g_vow);
    cudaGetSymbolAddress((void**)&pproj,  g_proj);
    cudaGetSymbolAddress((void**)&pbp,    g_bpack);
    cudaGetSymbolAddress((void**)&pah,    g_pa_h);
    cudaGetSymbolAddress((void**)&pal,    g_pa_l);
    cudaGetSymbolAddress((void**)&phh,    g_ph_h);
    cudaGetSymbolAddress((void**)&phl,    g_ph_l);
    cudaGetSymbolAddress((void**)&wprojh, g_wproj_h);
    cudaGetSymbolAddress((void**)&wprojl, g_wproj_l);
    cudaGetSymbolAddress((void**)&woh,    g_wo_h);
    cudaGetSymbolAddress((void**)&wol,    g_wo_l);
    cudaGetSymbolAddress((void**)&w1h,    g_w1_h);
    cudaGetSymbolAddress((void**)&w1l,    g_w1_l);
    cudaGetSymbolAddress((void**)&w2h,    g_w2_h);
    cudaGetSymbolAddress((void**)&w2l,    g_w2_l);

    const int M = MROWS;
    const int n4 = M * C_ / 4;
    const int SMEM = 65536;

    cudaFuncSetAttribute(mma_gemm<0, 0>,
                         cudaFuncAttributeMaxDynamicSharedMemorySize, SMEM);
    cudaFuncSetAttribute(mma_gemm<1, 1>,
                         cudaFuncAttributeMaxDynamicSharedMemorySize, SMEM);

    // One-time weight packing (per call; deterministic)
    {
        int t0 = NL_ * NPACK * C_;
        pack_proj_w<<<(t0 + 255) / 256, 256>>>(Wv, Woff, Wat, wprojh, wprojl);
        int t1 = NL_ * C_ * C_;
        pack_w<<<(t1 + 255) / 256, 256>>>(Wo, woh, wol, C_, C_);
        int t2 = NL_ * FF_ * C_;
        pack_w<<<(t2 + 255) / 256, 256>>>(W1, w1h, w1l, C_, FF_);
        pack_w<<<(t2 + 255) / 256, 256>>>(W2, w2h, w2l, FF_, C_);
        int tb = NL_ * NPACK;
        packb_kernel<<<(tb + 255) / 256, 256>>>(bv, boff, bat, pbp);
    }

    dim3 gAdd((n4 + 255) / 256);
    dim3 gProj(NPACK / 128, M / 128);   // (5, 340)
    dim3 gN256(C_ / 128, M / 128);      // (2, 340)
    dim3 gN1024(FF_ / 128, M / 128);    // (8, 340)
    dim3 gDef(M);
    dim3 gLN(M / 8);

    for (int i = 0; i < NL_; i++) {
        const float* xin = (i == 0) ? src : px;
        const float* bp_i = pbp + (size_t)i * NPACK;
        const float* bo_i = bo + (size_t)i * C_;
        const float* b1_i = b1 + (size_t)i * FF_;
        const float* b2_i = b2 + (size_t)i * C_;

        addpos_pair<<<gAdd, 256>>>(xin, pos, pxp, pah, pal, n4);

        // Fused projections: vow = xp @ [Wv|Woff|Wat]   (N=640, K=256)
        mma_gemm<0, 0><<<gProj, 256, SMEM>>>(pah, pal,
            wprojh + (size_t)i * NPACK * C_, wprojl + (size_t)i * NPACK * C_,
            bp_i, pvow, nullptr, nullptr, NPACK, C_);

        deform_kernel<<<gDef, 256>>>(pvow, ref, pah, pal);

        // Wo: proj = attn @ Wo   (N=256, K=256)
        mma_gemm<0, 0><<<gN256, 256, SMEM>>>(pah, pal,
            woh + (size_t)i * C_ * C_, wol + (size_t)i * C_ * C_,
            bo_i, pproj, nullptr, nullptr, C_, C_);

        ln_residual<1><<<gLN, 256>>>(pxp, pproj, n1s + (size_t)i * C_,
                                     n1b + (size_t)i * C_, px, pah, pal);

        // W1 + ReLU -> hid pair   (N=1024, K=256)
        mma_gemm<1, 1><<<gN1024, 256, SMEM>>>(pah, pal,
            w1h + (size_t)i * FF_ * C_, w1l + (size_t)i * FF_ * C_,
            b1_i, nullptr, phh, phl, FF_, C_);

        // W2: proj = hid @ W2   (N=256, K=1024)
        mma_gemm<0, 0><<<gN256, 256, SMEM>>>(phh, phl,
            w2h + (size_t)i * C_ * FF_, w2l + (size_t)i * C_ * FF_,
            b2_i, pproj, nullptr, nullptr, C_, FF_);

        float* lnout = (i == NL_ - 1) ? outp : px;
        ln_residual<0><<<gLN, 256>>>(px, pproj, n2s + (size_t)i * C_,
                                     n2b + (size_t)i * C_, lnout, nullptr, nullptr);
    }
}

// round 7
// speedup vs baseline: 1.9595x; 1.2759x over previous
#include <cuda_runtime.h>
#include <cuda_fp16.h>
#include <math.h>
#include <stdint.h>

// Problem constants
#define B_    2
#define LQ_   21760
#define C_    256
#define NHEAD 8
#define KPT   4
#define NL_   6
#define FF_   1024
#define DK_   32
#define MROWS (B_ * LQ_)          // 43520
#define NPACK 640                 // 256 (v) + 256 (off) + 128 (att)

// ---------------------------------------------------------------------------
// Device scratch (no runtime allocation)
// ---------------------------------------------------------------------------
__device__ float g_x    [MROWS * C_];
__device__ float g_xp   [MROWS * C_];
__device__ float g_vow  [MROWS * NPACK];
__device__ float g_proj [MROWS * C_];

// fp16 activations (single-rounded)
__device__ __half g_a_h [MROWS * C_];     // xp / attn / ln1-out (reused)
__device__ __half g_h_h [MROWS * FF_];    // hid

// fp16 weight split pairs, [N,K] transposed layout
__device__ __half g_wproj_h[NL_ * NPACK * C_];
__device__ __half g_wproj_l[NL_ * NPACK * C_];
__device__ __half g_wo_h[NL_ * C_ * C_];
__device__ __half g_wo_l[NL_ * C_ * C_];
__device__ __half g_w1_h[NL_ * FF_ * C_];
__device__ __half g_w1_l[NL_ * FF_ * C_];
__device__ __half g_w2_h[NL_ * C_ * FF_];
__device__ __half g_w2_l[NL_ * C_ * FF_];
__device__ float g_bpack[NL_ * NPACK];

// ---------------------------------------------------------------------------
// Helpers
// ---------------------------------------------------------------------------
__device__ __forceinline__ uint32_t smem_u32(const void* p) {
    uint32_t a;
    asm("{ .reg .u64 t; cvta.to.shared.u64 t, %1; cvt.u32.u64 %0, t; }"
        : "=r"(a) : "l"(p));
    return a;
}

__device__ __forceinline__ void h_split(float v, __half& h, __half& l) {
    h = __float2half_rn(v);
    l = __float2half_rn(v - __half2float(h));
}

#define MMA_F16(d, a, b0v, b1v)                                               \
    asm volatile("mma.sync.aligned.m16n8k16.row.col.f32.f16.f16.f32 "         \
        "{%0,%1,%2,%3}, {%4,%5,%6,%7}, {%8,%9}, {%0,%1,%2,%3};"               \
        : "+f"((d)[0]), "+f"((d)[1]), "+f"((d)[2]), "+f"((d)[3])              \
        : "r"((a)[0]), "r"((a)[1]), "r"((a)[2]), "r"((a)[3]),                 \
          "r"(b0v), "r"(b1v))

#define LDMATRIX_X4(r0, r1, r2, r3, addr)                                     \
    asm volatile("ldmatrix.sync.aligned.m8n8.x4.shared.b16 {%0,%1,%2,%3}, [%4];" \
        : "=r"(r0), "=r"(r1), "=r"(r2), "=r"(r3) : "r"(addr))

#define CP_ASYNC16(saddr, gptr)                                               \
    asm volatile("cp.async.cg.shared.global [%0], [%1], 16;"                  \
        :: "r"(saddr), "l"(gptr))

// ---------------------------------------------------------------------------
// Weight packing (fp32 [K,N] -> fp16 hi/lo [N,K])
// ---------------------------------------------------------------------------
__global__ void pack_proj_w(const float* __restrict__ Wv,
                            const float* __restrict__ Woff,
                            const float* __restrict__ Wat,
                            __half* __restrict__ Bh,
                            __half* __restrict__ Bl) {
    int idx = blockIdx.x * blockDim.x + threadIdx.x;   // NL*640*256
    if (idx >= NL_ * NPACK * C_) return;
    int k = idx & 255;
    int n = (idx >> 8) % NPACK;
    int l = idx / (NPACK * C_);
    float v;
    if (n < 256)      v = Wv  [((size_t)l * C_ + k) * 256 + n];
    else if (n < 512) v = Woff[((size_t)l * C_ + k) * 256 + (n - 256)];
    else              v = Wat [((size_t)l * C_ + k) * 128 + (n - 512)];
    __half h, lo;
    h_split(v, h, lo);
    Bh[idx] = h; Bl[idx] = lo;
}

__global__ void pack_w(const float* __restrict__ W,
                       __half* __restrict__ Bh,
                       __half* __restrict__ Bl, int K, int N) {
    int idx = blockIdx.x * blockDim.x + threadIdx.x;   // NL*N*K
    if (idx >= NL_ * N * K) return;
    int k = idx % K;
    int n = (idx / K) % N;
    int l = idx / (N * K);
    float v = W[(size_t)l * K * N + (size_t)k * N + n];
    __half h, lo;
    h_split(v, h, lo);
    Bh[idx] = h; Bl[idx] = lo;
}

__global__ void packb_kernel(const float* __restrict__ bv,
                             const float* __restrict__ boff,
                             const float* __restrict__ bat,
                             float* __restrict__ bp) {
    int idx = blockIdx.x * blockDim.x + threadIdx.x;
    if (idx >= NL_ * NPACK) return;
    int n = idx % NPACK;
    int l = idx / NPACK;
    float val;
    if (n < 256)      val = bv  [(size_t)l * 256 + n];
    else if (n < 512) val = boff[(size_t)l * 256 + (n - 256)];
    else              val = bat [(size_t)l * 128 + (n - 512)];
    bp[idx] = val;
}

// ---------------------------------------------------------------------------
// addpos (layer 0 only): xp = x + pos -> fp32 + fp16
// ---------------------------------------------------------------------------
__global__ void addpos_kernel(const float* __restrict__ x,
                              const float* __restrict__ pos,
                              float* __restrict__ xp,
                              __half* __restrict__ ph, int n4) {
    int i = blockIdx.x * blockDim.x + threadIdx.x;
    if (i >= n4) return;
    float4 a = ((const float4*)x)[i];
    float4 b = ((const float4*)pos)[i];
    float4 o;
    o.x = a.x + b.x; o.y = a.y + b.y; o.z = a.z + b.z; o.w = a.w + b.w;
    ((float4*)xp)[i] = o;
    __half2 h0 = __halves2half2(__float2half_rn(o.x), __float2half_rn(o.y));
    __half2 h1 = __halves2half2(__float2half_rn(o.z), __float2half_rn(o.w));
    ((__half2*)ph)[i * 2]     = h0;
    ((__half2*)ph)[i * 2 + 1] = h1;
}

// ---------------------------------------------------------------------------
// mma.sync fp16 split-weight GEMM.
// C[M,N] = A[M,K] @ (Bh+Bl)[N,K]^T + bias   (2 passes: A*Bh + A*Bl)
// CTA 128x128, BK=64, 8 warps (4Mx2N), warp tile 32x64.
// 3-stage cp.async pipeline; xor swizzle; dynamic smem 96KB.
// ---------------------------------------------------------------------------
template<int RELU, int HOUT>
__global__ __launch_bounds__(256)
void mma_gemm(const __half* __restrict__ A,
              const __half* __restrict__ Bh,
              const __half* __restrict__ Bl,
              const float* __restrict__ bias,
              float* __restrict__ Cf,
              __half* __restrict__ Chf,
              int N, int K) {
    extern __shared__ uint8_t smem[];
    const int tid  = threadIdx.x;
    const int wid  = tid >> 5;
    const int lane = tid & 31;
    const int brow = blockIdx.y * 128;
    const int bcol = blockIdx.x * 128;
    const int kIters = K >> 6;
    const int tIters = 2 * kIters;

    const int ldrow = tid >> 1;
    const int ldcb  = (tid & 1) << 2;
    const uint32_t smbase = smem_u32(smem);
    const uint32_t rb = ldrow * 128;

    auto load_tile = [&](int t, int buf) {
        int koff = (t >> 1) << 6;
        const __half* Bs_ = (t & 1) ? Bl : Bh;
        uint32_t sA = smbase + buf * 32768;
        uint32_t sB = sA + 16384;
        const __half* ga = A   + (size_t)(brow + ldrow) * K + koff + ldcb * 8;
        const __half* gb = Bs_ + (size_t)(bcol + ldrow) * K + koff + ldcb * 8;
        #pragma unroll
        for (int j = 0; j < 4; j++) {
            uint32_t sw = rb + (((ldcb + j) ^ (ldrow & 7)) << 4);
            CP_ASYNC16(sA + sw, ga + j * 8);
            CP_ASYNC16(sB + sw, gb + j * 8);
        }
    };

    const int wm = (wid & 3) * 32;
    const int wn = (wid >> 2) * 64;

    float acc[2][8][4];
    #pragma unroll
    for (int mi = 0; mi < 2; mi++)
        #pragma unroll
        for (int nj = 0; nj < 8; nj++)
            #pragma unroll
            for (int r = 0; r < 4; r++) acc[mi][nj][r] = 0.0f;

    auto compute = [&](int buf) {
        uint32_t sA = smbase + buf * 32768;
        uint32_t sB = sA + 16384;
        #pragma unroll
        for (int ks = 0; ks < 4; ks++) {
            uint32_t a[2][4];
            #pragma unroll
            for (int mi = 0; mi < 2; mi++) {
                int r = wm + mi * 16 + (lane & 15);
                int c = ks * 2 + (lane >> 4);
                uint32_t addr = sA + r * 128 + ((c ^ (r & 7)) << 4);
                LDMATRIX_X4(a[mi][0], a[mi][1], a[mi][2], a[mi][3], addr);
            }
            #pragma unroll
            for (int ng = 0; ng < 4; ng++) {
                uint32_t b0, b1, b2, b3;
                int r = wn + ng * 16 + (lane & 15);
                int c = ks * 2 + (lane >> 4);
                uint32_t addr = sB + r * 128 + ((c ^ (r & 7)) << 4);
                LDMATRIX_X4(b0, b1, b2, b3, addr);
                #pragma unroll
                for (int mi = 0; mi < 2; mi++) {
                    MMA_F16(acc[mi][ng * 2 + 0], a[mi], b0, b2);
                    MMA_F16(acc[mi][ng * 2 + 1], a[mi], b1, b3);
                }
            }
        }
    };

    // 3-stage pipeline
    load_tile(0, 0);
    asm volatile("cp.async.commit_group;" ::: "memory");
    load_tile(1, 1);
    asm volatile("cp.async.commit_group;" ::: "memory");

    for (int t = 0; t < tIters; t++) {
        if (t + 1 < tIters)
            asm volatile("cp.async.wait_group 1;" ::: "memory");
        else
            asm volatile("cp.async.wait_group 0;" ::: "memory");
        __syncthreads();
        if (t + 2 < tIters) {
            int nb = (t + 2) % 3;
            load_tile(t + 2, nb);
            asm volatile("cp.async.commit_group;" ::: "memory");
        }
        compute(t % 3);
    }

    // Epilogue
    const int tr = lane >> 2;
    const int tc = (lane & 3) * 2;
    #pragma unroll
    for (int mi = 0; mi < 2; mi++) {
        #pragma unroll
        for (int nj = 0; nj < 8; nj++) {
            const int col = bcol + wn + nj * 8 + tc;
            const float bb0 = bias[col], bb1 = bias[col + 1];
            #pragma unroll
            for (int rr = 0; rr < 2; rr++) {
                const int row = brow + wm + mi * 16 + rr * 8 + tr;
                float v0 = acc[mi][nj][rr * 2 + 0] + bb0;
                float v1 = acc[mi][nj][rr * 2 + 1] + bb1;
                if (RELU) { v0 = fmaxf(v0, 0.f); v1 = fmaxf(v1, 0.f); }
                if (!HOUT) {
                    float2 o; o.x = v0; o.y = v1;
                    *(float2*)(Cf + (size_t)row * N + col) = o;
                } else {
                    *(__half2*)(Chf + (size_t)row * N + col) =
                        __halves2half2(__float2half_rn(v0), __float2half_rn(v1));
                }
            }
        }
    }
}

// ---------------------------------------------------------------------------
// Deformable attention sampling. One warp per (b,q,head); lane = channel.
// Output: fp16 (feeds Wo GEMM).
// ---------------------------------------------------------------------------
__constant__ int c_SW[4] = {128, 64, 32, 16};
__constant__ int c_START[4] = {0, 16384, 20480, 21504};

__global__ __launch_bounds__(256)
void deform_kernel(const float* __restrict__ vow, const float* __restrict__ ref,
                   __half* __restrict__ oh) {
    const int wid  = blockIdx.x * 8 + (threadIdx.x >> 5);
    const int lane = threadIdx.x & 31;
    const int h    = wid & 7;
    const int bq   = wid >> 3;
    const int b    = bq / LQ_;

    const float* ar = vow + (size_t)bq * NPACK + 512 + h * 16;
    float w[16];
    float mx = -1e30f;
    #pragma unroll
    for (int j = 0; j < 16; j++) { w[j] = ar[j]; mx = fmaxf(mx, w[j]); }
    float s = 0.0f;
    #pragma unroll
    for (int j = 0; j < 16; j++) { w[j] = expf(w[j] - mx); s += w[j]; }
    const float inv_s = 1.0f / s;

    const float refx = ref[bq * 2 + 0];
    const float refy = ref[bq * 2 + 1];
    const float* ob = vow + (size_t)bq * NPACK + 256 + h * 32;
    const float* vb = vow + (size_t)b * LQ_ * NPACK + h * DK_ + lane;

    float acc = 0.0f;
    #pragma unroll
    for (int l = 0; l < 4; l++) {
        const int   Wl = c_SW[l];
        const float fw = (float)Wl;
        const int   st = c_START[l];
        #pragma unroll
        for (int k = 0; k < KPT; k++) {
            float ox = ob[l * 8 + k * 2 + 0];
            float oy = ob[l * 8 + k * 2 + 1];
            float x = (refx + ox * (1.0f / fw)) * (fw - 1.0f);
            float y = (refy + oy * (1.0f / fw)) * (fw - 1.0f);
            x = fminf(fmaxf(x, 0.0f), fw - 1.0f);
            y = fminf(fmaxf(y, 0.0f), fw - 1.0f);
            float x0f = floorf(x), y0f = floorf(y);
            int x0 = (int)x0f, y0 = (int)y0f;
            int x1 = min(x0 + 1, Wl - 1);
            int y1 = min(y0 + 1, Wl - 1);
            float wx = x - x0f, wy = y - y0f;
            float aw = w[l * 4 + k] * inv_s;

            const float* p00 = vb + (size_t)(st + y0 * Wl + x0) * NPACK;
            const float* p01 = vb + (size_t)(st + y0 * Wl + x1) * NPACK;
            const float* p10 = vb + (size_t)(st + y1 * Wl + x0) * NPACK;
            const float* p11 = vb + (size_t)(st + y1 * Wl + x1) * NPACK;
            float v00 = *p00, v01 = *p01, v10 = *p10, v11 = *p11;
            float bil = (1.0f - wx) * (1.0f - wy) * v00
                      + wx * (1.0f - wy) * v01
                      + (1.0f - wx) * wy * v10
                      + wx * wy * v11;
            acc = fmaf(aw, bil, acc);
        }
    }
    oh[(size_t)bq * C_ + h * DK_ + lane] = __float2half_rn(acc);
}

// ---------------------------------------------------------------------------
// LayerNorm w/ residual: v = LN(a + r)*s + bb.
// POSADD: emit v+pos (fused next-layer addpos) else v.
// EMITH:  also emit fp16 of the emitted value.
// ---------------------------------------------------------------------------
template<int POSADD, int EMITH>
__global__ __launch_bounds__(256)
void ln_residual(const float* __restrict__ a, const float* __restrict__ r,
                 const float* __restrict__ s, const float* __restrict__ bb,
                 const float* __restrict__ pos,
                 float* __restrict__ o, __half* __restrict__ ph) {
    const int row  = blockIdx.x * 8 + (threadIdx.x >> 5);
    const int lane = threadIdx.x & 31;
    const float* pa = a + (size_t)row * C_;
    const float* pr = r + (size_t)row * C_;

    float vals[8];
    float sum = 0.0f;
    #pragma unroll
    for (int j = 0; j < 8; j++) {
        int e = lane + 32 * j;
        float t = pa[e] + pr[e];
        vals[j] = t;
        sum += t;
    }
    #pragma unroll
    for (int d = 16; d > 0; d >>= 1) sum += __shfl_xor_sync(0xFFFFFFFF, sum, d);
    const float mean = sum * (1.0f / C_);

    float sq = 0.0f;
    #pragma unroll
    for (int j = 0; j < 8; j++) {
        float d = vals[j] - mean;
        sq = fmaf(d, d, sq);
    }
    #pragma unroll
    for (int d = 16; d > 0; d >>= 1) sq += __shfl_xor_sync(0xFFFFFFFF, sq, d);
    const float inv = rsqrtf(sq * (1.0f / C_) + 1e-5f);

    float* po = o + (size_t)row * C_;
    #pragma unroll
    for (int j = 0; j < 8; j++) {
        int e = lane + 32 * j;
        float v = (vals[j] - mean) * inv * s[e] + bb[e];
        if (POSADD) v += pos[(size_t)row * C_ + e];
        po[e] = v;
        if (EMITH) ph[(size_t)row * C_ + e] = __float2half_rn(v);
    }
}

// ---------------------------------------------------------------------------
// Host orchestration
// ---------------------------------------------------------------------------
extern "C" void kernel_launch(void* const* d_in, const int* in_sizes, int n_in,
                              void* d_out, int out_size) {
    const float* src  = (const float*)d_in[0];
    const float* pos  = (const float*)d_in[1];
    const float* ref  = (const float*)d_in[2];
    const float* Woff = (const float*)d_in[3];
    const float* boff = (const float*)d_in[4];
    const float* Wat  = (const float*)d_in[5];
    const float* bat  = (const float*)d_in[6];
    const float* Wv   = (const float*)d_in[7];
    const float* bv   = (const float*)d_in[8];
    const float* Wo   = (const float*)d_in[9];
    const float* bo   = (const float*)d_in[10];
    const float* W1   = (const float*)d_in[11];
    const float* b1   = (const float*)d_in[12];
    const float* W2   = (const float*)d_in[13];
    const float* b2   = (const float*)d_in[14];
    const float* n1s  = (const float*)d_in[15];
    const float* n1b  = (const float*)d_in[16];
    const float* n2s  = (const float*)d_in[17];
    const float* n2b  = (const float*)d_in[18];
    float* outp = (float*)d_out;

    float *px, *pxp, *pvow, *pproj, *pbp;
    __half *pah, *phh;
    __half *wprojh, *wprojl, *woh, *wol, *w1h, *w1l, *w2h, *w2l;
    cudaGetSymbolAddress((void**)&px,     g_x);
    cudaGetSymbolAddress((void**)&pxp,    g_xp);
    cudaGetSymbolAddress((void**)&pvow,   g_vow);
    cudaGetSymbolAddress((void**)&pproj,  g_proj);
    cudaGetSymbolAddress((void**)&pbp,    g_bpack);
    cudaGetSymbolAddress((void**)&pah,    g_a_h);
    cudaGetSymbolAddress((void**)&phh,    g_h_h);
    cudaGetSymbolAddress((void**)&wprojh, g_wproj_h);
    cudaGetSymbolAddress((void**)&wprojl, g_wproj_l);
    cudaGetSymbolAddress((void**)&woh,    g_wo_h);
    cudaGetSymbolAddress((void**)&wol,    g_wo_l);
    cudaGetSymbolAddress((void**)&w1h,    g_w1_h);
    cudaGetSymbolAddress((void**)&w1l,    g_w1_l);
    cudaGetSymbolAddress((void**)&w2h,    g_w2_h);
    cudaGetSymbolAddress((void**)&w2l,    g_w2_l);

    const int M = MROWS;
    const int n4 = M * C_ / 4;
    const int SMEM = 98304;   // 3 stages x 32KB

    cudaFuncSetAttribute(mma_gemm<0, 0>,
                         cudaFuncAttributeMaxDynamicSharedMemorySize, SMEM);
    cudaFuncSetAttribute(mma_gemm<1, 1>,
                         cudaFuncAttributeMaxDynamicSharedMemorySize, SMEM);

    // Weight packing (deterministic, per call)
    {
        int t0 = NL_ * NPACK * C_;
        pack_proj_w<<<(t0 + 255) / 256, 256>>>(Wv, Woff, Wat, wprojh, wprojl);
        int t1 = NL_ * C_ * C_;
        pack_w<<<(t1 + 255) / 256, 256>>>(Wo, woh, wol, C_, C_);
        int t2 = NL_ * FF_ * C_;
        pack_w<<<(t2 + 255) / 256, 256>>>(W1, w1h, w1l, C_, FF_);
        pack_w<<<(t2 + 255) / 256, 256>>>(W2, w2h, w2l, FF_, C_);
        int tb = NL_ * NPACK;
        packb_kernel<<<(tb + 255) / 256, 256>>>(bv, boff, bat, pbp);
    }

    dim3 gAdd((n4 + 255) / 256);
    dim3 gProj(NPACK / 128, M / 128);   // (5, 340)
    dim3 gN256(C_ / 128, M / 128);      // (2, 340)
    dim3 gN1024(FF_ / 128, M / 128);    // (8, 340)
    dim3 gDef(M);
    dim3 gLN(M / 8);

    // Layer 0 addpos; later layers get it fused into LN2
    addpos_kernel<<<gAdd, 256>>>(src, pos, pxp, pah, n4);

    for (int i = 0; i < NL_; i++) {
        const float* bp_i = pbp + (size_t)i * NPACK;
        const float* bo_i = bo + (size_t)i * C_;
        const float* b1_i = b1 + (size_t)i * FF_;
        const float* b2_i = b2 + (size_t)i * C_;

        // Fused projections: vow = xp @ [Wv|Woff|Wat]   (N=640, K=256)
        mma_gemm<0, 0><<<gProj, 256, SMEM>>>(pah,
            wprojh + (size_t)i * NPACK * C_, wprojl + (size_t)i * NPACK * C_,
            bp_i, pvow, nullptr, NPACK, C_);

        deform_kernel<<<gDef, 256>>>(pvow, ref, pah);

        // Wo: proj = attn @ Wo   (N=256, K=256)
        mma_gemm<0, 0><<<gN256, 256, SMEM>>>(pah,
            woh + (size_t)i * C_ * C_, wol + (size_t)i * C_ * C_,
            bo_i, pproj, nullptr, C_, C_);

        // LN1: x = LN(xp + proj); emit fp32 + fp16
        ln_residual<0, 1><<<gLN, 256>>>(pxp, pproj, n1s + (size_t)i * C_,
                                        n1b + (size_t)i * C_, nullptr, px, pah);

        // W1 + ReLU -> hid fp16   (N=1024, K=256)
        mma_gemm<1, 1><<<gN1024, 256, SMEM>>>(pah,
            w1h + (size_t)i * FF_ * C_, w1l + (size_t)i * FF_ * C_,
            b1_i, nullptr, phh, FF_, C_);

        // W2: proj = hid @ W2   (N=256, K=1024)
        mma_gemm<0, 0><<<gN256, 256, SMEM>>>(phh,
            w2h + (size_t)i * C_ * FF_, w2l + (size_t)i * C_ * FF_,
            b2_i, pproj, nullptr, C_, FF_);

        // LN2: final layer emits output; otherwise fused +pos into xp for next layer
        if (i == NL_ - 1) {
            ln_residual<0, 0><<<gLN, 256>>>(px, pproj, n2s + (size_t)i * C_,
                                            n2b + (size_t)i * C_, nullptr,
                                            outp, nullptr);
        } else {
            ln_residual<1, 1><<<gLN, 256>>>(px, pproj, n2s + (size_t)i * C_,
                                            n2b + (size_t)i * C_, pos,
                                            pxp, pah);
        }
    }
}

// round 9
// speedup vs baseline: 2.1439x; 1.0941x over previous
#include <cuda_runtime.h>
#include <cuda_fp16.h>
#include <math.h>
#include <stdint.h>

// Problem constants
#define B_    2
#define LQ_   21760
#define C_    256
#define NHEAD 8
#define KPT   4
#define NL_   6
#define FF_   1024
#define DK_   32
#define MROWS (B_ * LQ_)          // 43520
#define NPACK 640                 // 256 (v) + 256 (off) + 128 (att)
#define NOW   384                 // off|att compact row width

// ---------------------------------------------------------------------------
// Device scratch (no runtime allocation)
// ---------------------------------------------------------------------------
__device__ float g_x    [MROWS * C_];
__device__ float g_xp   [MROWS * C_];
__device__ float g_ow   [MROWS * NOW];    // off (256) | att (128), fp32
__device__ float g_proj [MROWS * C_];

__device__ __half g_v_h [MROWS * C_];     // sampled-value tensor, fp16
__device__ __half g_a_h [MROWS * C_];     // xp / attn / ln1-out fp16 (reused)
__device__ __half g_h_h [MROWS * FF_];    // hid fp16

// fp16 weight split pairs, [N,K] transposed layout
__device__ __half g_wproj_h[NL_ * NPACK * C_];
__device__ __half g_wproj_l[NL_ * NPACK * C_];
__device__ __half g_wo_h[NL_ * C_ * C_];
__device__ __half g_wo_l[NL_ * C_ * C_];
__device__ __half g_w1_h[NL_ * FF_ * C_];
__device__ __half g_w1_l[NL_ * FF_ * C_];
__device__ __half g_w2_h[NL_ * C_ * FF_];
__device__ __half g_w2_l[NL_ * C_ * FF_];
__device__ float g_bpack[NL_ * NPACK];

// ---------------------------------------------------------------------------
// Helpers
// ---------------------------------------------------------------------------
__device__ __forceinline__ uint32_t smem_u32(const void* p) {
    uint32_t a;
    asm("{ .reg .u64 t; cvta.to.shared.u64 t, %1; cvt.u32.u64 %0, t; }"
        : "=r"(a) : "l"(p));
    return a;
}

__device__ __forceinline__ void h_split(float v, __half& h, __half& l) {
    h = __float2half_rn(v);
    l = __float2half_rn(v - __half2float(h));
}

#define MMA_F16(d, a, b0v, b1v)                                               \
    asm volatile("mma.sync.aligned.m16n8k16.row.col.f32.f16.f16.f32 "         \
        "{%0,%1,%2,%3}, {%4,%5,%6,%7}, {%8,%9}, {%0,%1,%2,%3};"               \
        : "+f"((d)[0]), "+f"((d)[1]), "+f"((d)[2]), "+f"((d)[3])              \
        : "r"((a)[0]), "r"((a)[1]), "r"((a)[2]), "r"((a)[3]),                 \
          "r"(b0v), "r"(b1v))

#define LDMATRIX_X4(r0, r1, r2, r3, addr)                                     \
    asm volatile("ldmatrix.sync.aligned.m8n8.x4.shared.b16 {%0,%1,%2,%3}, [%4];" \
        : "=r"(r0), "=r"(r1), "=r"(r2), "=r"(r3) : "r"(addr))

#define CP_ASYNC16(saddr, gptr)                                               \
    asm volatile("cp.async.cg.shared.global [%0], [%1], 16;"                  \
        :: "r"(saddr), "l"(gptr))

// ---------------------------------------------------------------------------
// Weight packing (fp32 [K,N] -> fp16 hi/lo [N,K])
// ---------------------------------------------------------------------------
__global__ void pack_proj_w(const float* __restrict__ Wv,
                            const float* __restrict__ Woff,
                            const float* __restrict__ Wat,
                            __half* __restrict__ Bh,
                            __half* __restrict__ Bl) {
    int idx = blockIdx.x * blockDim.x + threadIdx.x;   // NL*640*256
    if (idx >= NL_ * NPACK * C_) return;
    int k = idx & 255;
    int n = (idx >> 8) % NPACK;
    int l = idx / (NPACK * C_);
    float v;
    if (n < 256)      v = Wv  [((size_t)l * C_ + k) * 256 + n];
    else if (n < 512) v = Woff[((size_t)l * C_ + k) * 256 + (n - 256)];
    else              v = Wat [((size_t)l * C_ + k) * 128 + (n - 512)];
    __half h, lo;
    h_split(v, h, lo);
    Bh[idx] = h; Bl[idx] = lo;
}

__global__ void pack_w(const float* __restrict__ W,
                       __half* __restrict__ Bh,
                       __half* __restrict__ Bl, int K, int N) {
    int idx = blockIdx.x * blockDim.x + threadIdx.x;   // NL*N*K
    if (idx >= NL_ * N * K) return;
    int k = idx % K;
    int n = (idx / K) % N;
    int l = idx / (N * K);
    float v = W[(size_t)l * K * N + (size_t)k * N + n];
    __half h, lo;
    h_split(v, h, lo);
    Bh[idx] = h; Bl[idx] = lo;
}

__global__ void packb_kernel(const float* __restrict__ bv,
                             const float* __restrict__ boff,
                             const float* __restrict__ bat,
                             float* __restrict__ bp) {
    int idx = blockIdx.x * blockDim.x + threadIdx.x;
    if (idx >= NL_ * NPACK) return;
    int n = idx % NPACK;
    int l = idx / NPACK;
    float val;
    if (n < 256)      val = bv  [(size_t)l * 256 + n];
    else if (n < 512) val = boff[(size_t)l * 256 + (n - 256)];
    else              val = bat [(size_t)l * 128 + (n - 512)];
    bp[idx] = val;
}

// ---------------------------------------------------------------------------
// addpos (layer 0 only): xp = x + pos -> fp32 + fp16
// ---------------------------------------------------------------------------
__global__ void addpos_kernel(const float* __restrict__ x,
                              const float* __restrict__ pos,
                              float* __restrict__ xp,
                              __half* __restrict__ ph, int n4) {
    int i = blockIdx.x * blockDim.x + threadIdx.x;
    if (i >= n4) return;
    float4 a = ((const float4*)x)[i];
    float4 b = ((const float4*)pos)[i];
    float4 o;
    o.x = a.x + b.x; o.y = a.y + b.y; o.z = a.z + b.z; o.w = a.w + b.w;
    ((float4*)xp)[i] = o;
    ((__half2*)ph)[i * 2]     = __halves2half2(__float2half_rn(o.x), __float2half_rn(o.y));
    ((__half2*)ph)[i * 2 + 1] = __halves2half2(__float2half_rn(o.z), __float2half_rn(o.w));
}

// ---------------------------------------------------------------------------
// mma.sync fp16 split-weight GEMM, single-visit dual-B accumulation:
//   C = A @ (Bh + Bl)^T + bias, A loaded ONCE per k-tile.
// CTA 128x128, BK=64, 8 warps (4Mx2N). Stage = {A,Bh,Bl} 48KB; 2 stages.
// OMODE: 0 = fp32 out, 1 = fp16 out, 2 = proj split (v fp16 | ow fp32)
// ---------------------------------------------------------------------------
template<int RELU, int OMODE>
__global__ __launch_bounds__(256)
void mma_gemm(const __half* __restrict__ A,
              const __half* __restrict__ Bh,
              const __half* __restrict__ Bl,
              const float* __restrict__ bias,
              float* __restrict__ Cf,
              __half* __restrict__ Chf,
              float* __restrict__ Cow,
              int N, int K) {
    extern __shared__ uint8_t smem[];
    const int tid  = threadIdx.x;
    const int wid  = tid >> 5;
    const int lane = tid & 31;
    const int brow = blockIdx.y * 128;
    const int bcol = blockIdx.x * 128;
    const int kIters = K >> 6;

    const int ldrow = tid >> 1;
    const int ldcb  = (tid & 1) << 2;
    const uint32_t smbase = smem_u32(smem);
    const uint32_t rb = ldrow * 128;

    auto load_tile = [&](int k, int buf) {
        uint32_t sA  = smbase + buf * 49152;
        uint32_t sBh = sA + 16384;
        uint32_t sBl = sA + 32768;
        const __half* ga  = A  + (size_t)(brow + ldrow) * K + (k << 6) + ldcb * 8;
        const __half* gbh = Bh + (size_t)(bcol + ldrow) * K + (k << 6) + ldcb * 8;
        const __half* gbl = Bl + (size_t)(bcol + ldrow) * K + (k << 6) + ldcb * 8;
        #pragma unroll
        for (int j = 0; j < 4; j++) {
            uint32_t sw = rb + (((ldcb + j) ^ (ldrow & 7)) << 4);
            CP_ASYNC16(sA  + sw, ga  + j * 8);
            CP_ASYNC16(sBh + sw, gbh + j * 8);
            CP_ASYNC16(sBl + sw, gbl + j * 8);
        }
    };

    const int wm = (wid & 3) * 32;
    const int wn = (wid >> 2) * 64;

    float acc[2][8][4];
    #pragma unroll
    for (int mi = 0; mi < 2; mi++)
        #pragma unroll
        for (int nj = 0; nj < 8; nj++)
            #pragma unroll
            for (int r = 0; r < 4; r++) acc[mi][nj][r] = 0.0f;

    auto compute = [&](int buf) {
        uint32_t sA  = smbase + buf * 49152;
        uint32_t sBh = sA + 16384;
        uint32_t sBl = sA + 32768;
        #pragma unroll
        for (int ks = 0; ks < 4; ks++) {
            uint32_t a[2][4];
            const int c = ks * 2 + (lane >> 4);
            #pragma unroll
            for (int mi = 0; mi < 2; mi++) {
                int r = wm + mi * 16 + (lane & 15);
                uint32_t addr = sA + r * 128 + ((c ^ (r & 7)) << 4);
                LDMATRIX_X4(a[mi][0], a[mi][1], a[mi][2], a[mi][3], addr);
            }
            #pragma unroll
            for (int ng = 0; ng < 4; ng++) {
                int r = wn + ng * 16 + (lane & 15);
                uint32_t soff = r * 128 + ((c ^ (r & 7)) << 4);
                uint32_t b0, b1, b2, b3;
                LDMATRIX_X4(b0, b1, b2, b3, sBh + soff);
                #pragma unroll
                for (int mi = 0; mi < 2; mi++) {
                    MMA_F16(acc[mi][ng * 2 + 0], a[mi], b0, b2);
                    MMA_F16(acc[mi][ng * 2 + 1], a[mi], b1, b3);
                }
                LDMATRIX_X4(b0, b1, b2, b3, sBl + soff);
                #pragma unroll
                for (int mi = 0; mi < 2; mi++) {
                    MMA_F16(acc[mi][ng * 2 + 0], a[mi], b0, b2);
                    MMA_F16(acc[mi][ng * 2 + 1], a[mi], b1, b3);
                }
            }
        }
    };

    // 2-stage pipeline (sync after compute guards buffer reuse)
    load_tile(0, 0);
    asm volatile("cp.async.commit_group;" ::: "memory");
    for (int t = 0; t < kIters; t++) {
        if (t + 1 < kIters) {
            load_tile(t + 1, (t + 1) & 1);
            asm volatile("cp.async.commit_group;" ::: "memory");
            asm volatile("cp.async.wait_group 1;" ::: "memory");
        } else {
            asm volatile("cp.async.wait_group 0;" ::: "memory");
        }
        __syncthreads();
        compute(t & 1);
        __syncthreads();
    }

    // Epilogue
    const int tr = lane >> 2;
    const int tc = (lane & 3) * 2;
    #pragma unroll
    for (int mi = 0; mi < 2; mi++) {
        #pragma unroll
        for (int nj = 0; nj < 8; nj++) {
            const int col = bcol + wn + nj * 8 + tc;
            const float bb0 = bias[col], bb1 = bias[col + 1];
            #pragma unroll
            for (int rr = 0; rr < 2; rr++) {
                const int row = brow + wm + mi * 16 + rr * 8 + tr;
                float v0 = acc[mi][nj][rr * 2 + 0] + bb0;
                float v1 = acc[mi][nj][rr * 2 + 1] + bb1;
                if (RELU) { v0 = fmaxf(v0, 0.f); v1 = fmaxf(v1, 0.f); }
                if (OMODE == 0) {
                    float2 o; o.x = v0; o.y = v1;
                    *(float2*)(Cf + (size_t)row * N + col) = o;
                } else if (OMODE == 1) {
                    *(__half2*)(Chf + (size_t)row * N + col) =
                        __halves2half2(__float2half_rn(v0), __float2half_rn(v1));
                } else {
                    if (col < 256) {
                        *(__half2*)(Chf + (size_t)row * C_ + col) =
                            __halves2half2(__float2half_rn(v0), __float2half_rn(v1));
                    } else {
                        float2 o; o.x = v0; o.y = v1;
                        *(float2*)(Cow + (size_t)row * NOW + (col - 256)) = o;
                    }
                }
            }
        }
    }
}

// ---------------------------------------------------------------------------
// Deformable attention sampling. One warp per (b,q,head); lane = channel.
// v in fp16 (half gather traffic); off/att fp32 from compact ow buffer.
// ---------------------------------------------------------------------------
__constant__ int c_SW[4] = {128, 64, 32, 16};
__constant__ int c_START[4] = {0, 16384, 20480, 21504};

__global__ __launch_bounds__(256)
void deform_kernel(const __half* __restrict__ vh, const float* __restrict__ ow,
                   const float* __restrict__ ref, __half* __restrict__ oh) {
    const int wid  = blockIdx.x * 8 + (threadIdx.x >> 5);
    const int lane = threadIdx.x & 31;
    const int h    = wid & 7;
    const int bq   = wid >> 3;
    const int b    = bq / LQ_;

    const float* ar = ow + (size_t)bq * NOW + 256 + h * 16;
    float w[16];
    float mx = -1e30f;
    #pragma unroll
    for (int j = 0; j < 16; j++) { w[j] = ar[j]; mx = fmaxf(mx, w[j]); }
    float s = 0.0f;
    #pragma unroll
    for (int j = 0; j < 16; j++) { w[j] = expf(w[j] - mx); s += w[j]; }
    const float inv_s = 1.0f / s;

    const float refx = ref[bq * 2 + 0];
    const float refy = ref[bq * 2 + 1];
    const float* ob = ow + (size_t)bq * NOW + h * 32;
    const __half* vb = vh + (size_t)b * LQ_ * C_ + h * DK_ + lane;

    float acc = 0.0f;
    #pragma unroll
    for (int l = 0; l < 4; l++) {
        const int   Wl = c_SW[l];
        const float fw = (float)Wl;
        const int   st = c_START[l];
        #pragma unroll
        for (int k = 0; k < KPT; k++) {
            float ox = ob[l * 8 + k * 2 + 0];
            float oy = ob[l * 8 + k * 2 + 1];
            float x = (refx + ox * (1.0f / fw)) * (fw - 1.0f);
            float y = (refy + oy * (1.0f / fw)) * (fw - 1.0f);
            x = fminf(fmaxf(x, 0.0f), fw - 1.0f);
            y = fminf(fmaxf(y, 0.0f), fw - 1.0f);
            float x0f = floorf(x), y0f = floorf(y);
            int x0 = (int)x0f, y0 = (int)y0f;
            int x1 = min(x0 + 1, Wl - 1);
            int y1 = min(y0 + 1, Wl - 1);
            float wx = x - x0f, wy = y - y0f;
            float aw = w[l * 4 + k] * inv_s;

            float v00 = __half2float(vb[(size_t)(st + y0 * Wl + x0) * C_]);
            float v01 = __half2float(vb[(size_t)(st + y0 * Wl + x1) * C_]);
            float v10 = __half2float(vb[(size_t)(st + y1 * Wl + x0) * C_]);
            float v11 = __half2float(vb[(size_t)(st + y1 * Wl + x1) * C_]);
            float bil = (1.0f - wx) * (1.0f - wy) * v00
                      + wx * (1.0f - wy) * v01
                      + (1.0f - wx) * wy * v10
                      + wx * wy * v11;
            acc = fmaf(aw, bil, acc);
        }
    }
    oh[(size_t)bq * C_ + h * DK_ + lane] = __float2half_rn(acc);
}

// ---------------------------------------------------------------------------
// LayerNorm w/ residual: v = LN(a + r)*s + bb.
// POSADD: emit v+pos (fused next-layer addpos). EMITH: also emit fp16.
// ---------------------------------------------------------------------------
template<int POSADD, int EMITH>
__global__ __launch_bounds__(256)
void ln_residual(const float* __restrict__ a, const float* __restrict__ r,
                 const float* __restrict__ s, const float* __restrict__ bb,
                 const float* __restrict__ pos,
                 float* __restrict__ o, __half* __restrict__ ph) {
    const int row  = blockIdx.x * 8 + (threadIdx.x >> 5);
    const int lane = threadIdx.x & 31;
    const float* pa = a + (size_t)row * C_;
    const float* pr = r + (size_t)row * C_;

    float vals[8];
    float sum = 0.0f;
    #pragma unroll
    for (int j = 0; j < 8; j++) {
        int e = lane + 32 * j;
        float t = pa[e] + pr[e];
        vals[j] = t;
        sum += t;
    }
    #pragma unroll
    for (int d = 16; d > 0; d >>= 1) sum += __shfl_xor_sync(0xFFFFFFFF, sum, d);
    const float mean = sum * (1.0f / C_);

    float sq = 0.0f;
    #pragma unroll
    for (int j = 0; j < 8; j++) {
        float d = vals[j] - mean;
        sq = fmaf(d, d, sq);
    }
    #pragma unroll
    for (int d = 16; d > 0; d >>= 1) sq += __shfl_xor_sync(0xFFFFFFFF, sq, d);
    const float inv = rsqrtf(sq * (1.0f / C_) + 1e-5f);

    float* po = o + (size_t)row * C_;
    #pragma unroll
    for (int j = 0; j < 8; j++) {
        int e = lane + 32 * j;
        float v = (vals[j] - mean) * inv * s[e] + bb[e];
        if (POSADD) v += pos[(size_t)row * C_ + e];
        po[e] = v;
        if (EMITH) ph[(size_t)row * C_ + e] = __float2half_rn(v);
    }
}

// ---------------------------------------------------------------------------
// Host orchestration
// ---------------------------------------------------------------------------
extern "C" void kernel_launch(void* const* d_in, const int* in_sizes, int n_in,
                              void* d_out, int out_size) {
    const float* src  = (const float*)d_in[0];
    const float* pos  = (const float*)d_in[1];
    const float* ref  = (const float*)d_in[2];
    const float* Woff = (const float*)d_in[3];
    const float* boff = (const float*)d_in[4];
    const float* Wat  = (const float*)d_in[5];
    const float* bat  = (const float*)d_in[6];
    const float* Wv   = (const float*)d_in[7];
    const float* bv   = (const float*)d_in[8];
    const float* Wo   = (const float*)d_in[9];
    const float* bo   = (const float*)d_in[10];
    const float* W1   = (const float*)d_in[11];
    const float* b1   = (const float*)d_in[12];
    const float* W2   = (const float*)d_in[13];
    const float* b2   = (const float*)d_in[14];
    const float* n1s  = (const float*)d_in[15];
    const float* n1b  = (const float*)d_in[16];
    const float* n2s  = (const float*)d_in[17];
    const float* n2b  = (const float*)d_in[18];
    float* outp = (float*)d_out;

    float *px, *pxp, *pow, *pproj, *pbp;
    __half *pvh, *pah, *phh;
    __half *wprojh, *wprojl, *woh, *wol, *w1h, *w1l, *w2h, *w2l;
    cudaGetSymbolAddress((void**)&px,     g_x);
    cudaGetSymbolAddress((void**)&pxp,    g_xp);
    cudaGetSymbolAddress((void**)&pow,    g_ow);
    cudaGetSymbolAddress((void**)&pproj,  g_proj);
    cudaGetSymbolAddress((void**)&pbp,    g_bpack);
    cudaGetSymbolAddress((void**)&pvh,    g_v_h);
    cudaGetSymbolAddress((void**)&pah,    g_a_h);
    cudaGetSymbolAddress((void**)&phh,    g_h_h);
    cudaGetSymbolAddress((void**)&wprojh, g_wproj_h);
    cudaGetSymbolAddress((void**)&wprojl, g_wproj_l);
    cudaGetSymbolAddress((void**)&woh,    g_wo_h);
    cudaGetSymbolAddress((void**)&wol,    g_wo_l);
    cudaGetSymbolAddress((void**)&w1h,    g_w1_h);
    cudaGetSymbolAddress((void**)&w1l,    g_w1_l);
    cudaGetSymbolAddress((void**)&w2h,    g_w2_h);
    cudaGetSymbolAddress((void**)&w2l,    g_w2_l);

    const int M = MROWS;
    const int n4 = M * C_ / 4;
    const int SMEM = 98304;   // 2 stages x 48KB

    cudaFuncSetAttribute(mma_gemm<0, 0>,
                         cudaFuncAttributeMaxDynamicSharedMemorySize, SMEM);
    cudaFuncSetAttribute(mma_gemm<0, 2>,
                         cudaFuncAttributeMaxDynamicSharedMemorySize, SMEM);
    cudaFuncSetAttribute(mma_gemm<1, 1>,
                         cudaFuncAttributeMaxDynamicSharedMemorySize, SMEM);

    // Weight packing (deterministic, per call)
    {
        int t0 = NL_ * NPACK * C_;
        pack_proj_w<<<(t0 + 255) / 256, 256>>>(Wv, Woff, Wat, wprojh, wprojl);
        int t1 = NL_ * C_ * C_;
        pack_w<<<(t1 + 255) / 256, 256>>>(Wo, woh, wol, C_, C_);
        int t2 = NL_ * FF_ * C_;
        pack_w<<<(t2 + 255) / 256, 256>>>(W1, w1h, w1l, C_, FF_);
        pack_w<<<(t2 + 255) / 256, 256>>>(W2, w2h, w2l, FF_, C_);
        int tb = NL_ * NPACK;
        packb_kernel<<<(tb + 255) / 256, 256>>>(bv, boff, bat, pbp);
    }

    dim3 gAdd((n4 + 255) / 256);
    dim3 gProj(NPACK / 128, M / 128);   // (5, 340)
    dim3 gN256(C_ / 128, M / 128);      // (2, 340)
    dim3 gN1024(FF_ / 128, M / 128);    // (8, 340)
    dim3 gDef(M);
    dim3 gLN(M / 8);

    // Layer 0 addpos; later layers get it fused into LN2
    addpos_kernel<<<gAdd, 256>>>(src, pos, pxp, pah, n4);

    for (int i = 0; i < NL_; i++) {
        const float* bp_i = pbp + (size_t)i * NPACK;
        const float* bo_i = bo + (size_t)i * C_;
        const float* b1_i = b1 + (size_t)i * FF_;
        const float* b2_i = b2 + (size_t)i * C_;

        // Fused projections -> v fp16 | off/att fp32   (N=640, K=256)
        mma_gemm<0, 2><<<gProj, 256, SMEM>>>(pah,
            wprojh + (size_t)i * NPACK * C_, wprojl + (size_t)i * NPACK * C_,
            bp_i, nullptr, pvh, pow, NPACK, C_);

        deform_kernel<<<gDef, 256>>>(pvh, pow, ref, pah);

        // Wo: proj = attn @ Wo   (N=256, K=256)
        mma_gemm<0, 0><<<gN256, 256, SMEM>>>(pah,
            woh + (size_t)i * C_ * C_, wol + (size_t)i * C_ * C_,
            bo_i, pproj, nullptr, nullptr, C_, C_);

        // LN1: x = LN(xp + proj); emit fp32 + fp16
        ln_residual<0, 1><<<gLN, 256>>>(pxp, pproj, n1s + (size_t)i * C_,
                                        n1b + (size_t)i * C_, nullptr, px, pah);

        // W1 + ReLU -> hid fp16   (N=1024, K=256)
        mma_gemm<1, 1><<<gN1024, 256, SMEM>>>(pah,
            w1h + (size_t)i * FF_ * C_, w1l + (size_t)i * FF_ * C_,
            b1_i, nullptr, phh, nullptr, FF_, C_);

        // W2: proj = hid @ W2   (N=256, K=1024)
        mma_gemm<0, 0><<<gN256, 256, SMEM>>>(phh,
            w2h + (size_t)i * C_ * FF_, w2l + (size_t)i * C_ * FF_,
            b2_i, pproj, nullptr, nullptr, C_, FF_);

        // LN2: final layer emits output; else fuse +pos for next layer
        if (i == NL_ - 1) {
            ln_residual<0, 0><<<gLN, 256>>>(px, pproj, n2s + (size_t)i * C_,
                                            n2b + (size_t)i * C_, nullptr,
                                            outp, nullptr);
        } else {
            ln_residual<1, 1><<<gLN, 256>>>(px, pproj, n2s + (size_t)i * C_,
                                            n2b + (size_t)i * C_, pos,
                                            pxp, pah);
        }
    }
}

// round 10
// speedup vs baseline: 2.6553x; 1.2386x over previous
#include <cuda_runtime.h>
#include <cuda_fp16.h>
#include <math.h>
#include <stdint.h>

// Problem constants
#define B_    2
#define LQ_   21760
#define C_    256
#define NHEAD 8
#define KPT   4
#define NL_   6
#define FF_   1024
#define DK_   32
#define MROWS (B_ * LQ_)          // 43520
#define NPACK 640                 // 256 (v) + 256 (off) + 128 (att)
#define NOW   384                 // off|att compact row width

// ---------------------------------------------------------------------------
// Device scratch (no runtime allocation)
// ---------------------------------------------------------------------------
__device__ float g_x    [MROWS * C_];
__device__ float g_xp   [MROWS * C_];
__device__ float g_ow   [MROWS * NOW];    // off (256) | att (128), fp32
__device__ float g_proj [MROWS * C_];

__device__ __half g_v_h [MROWS * C_];     // sampled-value tensor, fp16
__device__ __half g_a_h [MROWS * C_];     // xp / attn / ln1-out fp16 (reused)
__device__ __half g_h_h [MROWS * FF_];    // hid fp16

// fp16 weights, [N,K] transposed layout (single-rounded)
__device__ __half g_wproj[NL_ * NPACK * C_];
__device__ __half g_wo   [NL_ * C_ * C_];
__device__ __half g_w1   [NL_ * FF_ * C_];
__device__ __half g_w2   [NL_ * C_ * FF_];
__device__ float  g_bpack[NL_ * NPACK];

// ---------------------------------------------------------------------------
// Helpers
// ---------------------------------------------------------------------------
__device__ __forceinline__ uint32_t smem_u32(const void* p) {
    uint32_t a;
    asm("{ .reg .u64 t; cvta.to.shared.u64 t, %1; cvt.u32.u64 %0, t; }"
        : "=r"(a) : "l"(p));
    return a;
}

#define MMA_F16(d, a, b0v, b1v)                                               \
    asm volatile("mma.sync.aligned.m16n8k16.row.col.f32.f16.f16.f32 "         \
        "{%0,%1,%2,%3}, {%4,%5,%6,%7}, {%8,%9}, {%0,%1,%2,%3};"               \
        : "+f"((d)[0]), "+f"((d)[1]), "+f"((d)[2]), "+f"((d)[3])              \
        : "r"((a)[0]), "r"((a)[1]), "r"((a)[2]), "r"((a)[3]),                 \
          "r"(b0v), "r"(b1v))

#define LDMATRIX_X4(r0, r1, r2, r3, addr)                                     \
    asm volatile("ldmatrix.sync.aligned.m8n8.x4.shared.b16 {%0,%1,%2,%3}, [%4];" \
        : "=r"(r0), "=r"(r1), "=r"(r2), "=r"(r3) : "r"(addr))

#define CP_ASYNC16(saddr, gptr)                                               \
    asm volatile("cp.async.cg.shared.global [%0], [%1], 16;"                  \
        :: "r"(saddr), "l"(gptr))

// ---------------------------------------------------------------------------
// Weight packing (fp32 [K,N] -> fp16 [N,K])
// ---------------------------------------------------------------------------
__global__ void pack_proj_w(const float* __restrict__ Wv,
                            const float* __restrict__ Woff,
                            const float* __restrict__ Wat,
                            __half* __restrict__ Bh) {
    int idx = blockIdx.x * blockDim.x + threadIdx.x;   // NL*640*256
    if (idx >= NL_ * NPACK * C_) return;
    int k = idx & 255;
    int n = (idx >> 8) % NPACK;
    int l = idx / (NPACK * C_);
    float v;
    if (n < 256)      v = Wv  [((size_t)l * C_ + k) * 256 + n];
    else if (n < 512) v = Woff[((size_t)l * C_ + k) * 256 + (n - 256)];
    else              v = Wat [((size_t)l * C_ + k) * 128 + (n - 512)];
    Bh[idx] = __float2half_rn(v);
}

__global__ void pack_w(const float* __restrict__ W,
                       __half* __restrict__ Bh, int K, int N) {
    int idx = blockIdx.x * blockDim.x + threadIdx.x;   // NL*N*K
    if (idx >= NL_ * N * K) return;
    int k = idx % K;
    int n = (idx / K) % N;
    int l = idx / (N * K);
    Bh[idx] = __float2half_rn(W[(size_t)l * K * N + (size_t)k * N + n]);
}

__global__ void packb_kernel(const float* __restrict__ bv,
                             const float* __restrict__ boff,
                             const float* __restrict__ bat,
                             float* __restrict__ bp) {
    int idx = blockIdx.x * blockDim.x + threadIdx.x;
    if (idx >= NL_ * NPACK) return;
    int n = idx % NPACK;
    int l = idx / NPACK;
    float val;
    if (n < 256)      val = bv  [(size_t)l * 256 + n];
    else if (n < 512) val = boff[(size_t)l * 256 + (n - 256)];
    else              val = bat [(size_t)l * 128 + (n - 512)];
    bp[idx] = val;
}

// ---------------------------------------------------------------------------
// addpos (layer 0 only): xp = x + pos -> fp32 + fp16
// ---------------------------------------------------------------------------
__global__ void addpos_kernel(const float* __restrict__ x,
                              const float* __restrict__ pos,
                              float* __restrict__ xp,
                              __half* __restrict__ ph, int n4) {
    int i = blockIdx.x * blockDim.x + threadIdx.x;
    if (i >= n4) return;
    float4 a = ((const float4*)x)[i];
    float4 b = ((const float4*)pos)[i];
    float4 o;
    o.x = a.x + b.x; o.y = a.y + b.y; o.z = a.z + b.z; o.w = a.w + b.w;
    ((float4*)xp)[i] = o;
    ((__half2*)ph)[i * 2]     = __halves2half2(__float2half_rn(o.x), __float2half_rn(o.y));
    ((__half2*)ph)[i * 2 + 1] = __halves2half2(__float2half_rn(o.z), __float2half_rn(o.w));
}

// ---------------------------------------------------------------------------
// mma.sync fp16 GEMM: C[M,N] = A[M,K] @ B[N,K]^T + bias.
// CTA 128x128, BK=64, 8 warps (4Mx2N). Stage {A,B} = 32KB; 3 stages, 96KB.
// One __syncthreads per k-iter.
// OMODE: 0 = fp32 out, 1 = fp16 out, 2 = proj split (v fp16 | ow fp32)
// ---------------------------------------------------------------------------
template<int RELU, int OMODE>
__global__ __launch_bounds__(256)
void mma_gemm(const __half* __restrict__ A,
              const __half* __restrict__ Bm,
              const float* __restrict__ bias,
              float* __restrict__ Cf,
              __half* __restrict__ Chf,
              float* __restrict__ Cow,
              int N, int K) {
    extern __shared__ uint8_t smem[];
    const int tid  = threadIdx.x;
    const int wid  = tid >> 5;
    const int lane = tid & 31;
    const int brow = blockIdx.y * 128;
    const int bcol = blockIdx.x * 128;
    const int kIters = K >> 6;

    const int ldrow = tid >> 1;
    const int ldcb  = (tid & 1) << 2;
    const uint32_t smbase = smem_u32(smem);
    const uint32_t rb = ldrow * 128;

    auto load_tile = [&](int k, int buf) {
        uint32_t sA = smbase + buf * 32768;
        uint32_t sB = sA + 16384;
        const __half* ga = A  + (size_t)(brow + ldrow) * K + (k << 6) + ldcb * 8;
        const __half* gb = Bm + (size_t)(bcol + ldrow) * K + (k << 6) + ldcb * 8;
        #pragma unroll
        for (int j = 0; j < 4; j++) {
            uint32_t sw = rb + (((ldcb + j) ^ (ldrow & 7)) << 4);
            CP_ASYNC16(sA + sw, ga + j * 8);
            CP_ASYNC16(sB + sw, gb + j * 8);
        }
    };

    const int wm = (wid & 3) * 32;
    const int wn = (wid >> 2) * 64;

    float acc[2][8][4];
    #pragma unroll
    for (int mi = 0; mi < 2; mi++)
        #pragma unroll
        for (int nj = 0; nj < 8; nj++)
            #pragma unroll
            for (int r = 0; r < 4; r++) acc[mi][nj][r] = 0.0f;

    auto compute = [&](int buf) {
        uint32_t sA = smbase + buf * 32768;
        uint32_t sB = sA + 16384;
        #pragma unroll
        for (int ks = 0; ks < 4; ks++) {
            uint32_t a[2][4];
            const int c = ks * 2 + (lane >> 4);
            #pragma unroll
            for (int mi = 0; mi < 2; mi++) {
                int r = wm + mi * 16 + (lane & 15);
                uint32_t addr = sA + r * 128 + ((c ^ (r & 7)) << 4);
                LDMATRIX_X4(a[mi][0], a[mi][1], a[mi][2], a[mi][3], addr);
            }
            #pragma unroll
            for (int ng = 0; ng < 4; ng++) {
                int r = wn + ng * 16 + (lane & 15);
                uint32_t soff = r * 128 + ((c ^ (r & 7)) << 4);
                uint32_t b0, b1, b2, b3;
                LDMATRIX_X4(b0, b1, b2, b3, sB + soff);
                #pragma unroll
                for (int mi = 0; mi < 2; mi++) {
                    MMA_F16(acc[mi][ng * 2 + 0], a[mi], b0, b2);
                    MMA_F16(acc[mi][ng * 2 + 1], a[mi], b1, b3);
                }
            }
        }
    };

    // 3-stage pipeline, one sync per iteration
    load_tile(0, 0);
    asm volatile("cp.async.commit_group;" ::: "memory");
    if (kIters > 1) {
        load_tile(1, 1);
        asm volatile("cp.async.commit_group;" ::: "memory");
    }
    for (int t = 0; t < kIters; t++) {
        if (t + 1 < kIters)
            asm volatile("cp.async.wait_group 1;" ::: "memory");
        else
            asm volatile("cp.async.wait_group 0;" ::: "memory");
        __syncthreads();
        if (t + 2 < kIters) {
            load_tile(t + 2, (t + 2) % 3);
            asm volatile("cp.async.commit_group;" ::: "memory");
        }
        compute(t % 3);
    }

    // Epilogue
    const int tr = lane >> 2;
    const int tc = (lane & 3) * 2;
    #pragma unroll
    for (int mi = 0; mi < 2; mi++) {
        #pragma unroll
        for (int nj = 0; nj < 8; nj++) {
            const int col = bcol + wn + nj * 8 + tc;
            const float bb0 = bias[col], bb1 = bias[col + 1];
            #pragma unroll
            for (int rr = 0; rr < 2; rr++) {
                const int row = brow + wm + mi * 16 + rr * 8 + tr;
                float v0 = acc[mi][nj][rr * 2 + 0] + bb0;
                float v1 = acc[mi][nj][rr * 2 + 1] + bb1;
                if (RELU) { v0 = fmaxf(v0, 0.f); v1 = fmaxf(v1, 0.f); }
                if (OMODE == 0) {
                    float2 o; o.x = v0; o.y = v1;
                    *(float2*)(Cf + (size_t)row * N + col) = o;
                } else if (OMODE == 1) {
                    *(__half2*)(Chf + (size_t)row * N + col) =
                        __halves2half2(__float2half_rn(v0), __float2half_rn(v1));
                } else {
                    if (col < 256) {
                        *(__half2*)(Chf + (size_t)row * C_ + col) =
                            __halves2half2(__float2half_rn(v0), __float2half_rn(v1));
                    } else {
                        float2 o; o.x = v0; o.y = v1;
                        *(float2*)(Cow + (size_t)row * NOW + (col - 256)) = o;
                    }
                }
            }
        }
    }
}

// ---------------------------------------------------------------------------
// Deformable attention sampling. One warp per (b,q,head); lane = channel.
// v in fp16; off/att fp32 from compact ow buffer.
// ---------------------------------------------------------------------------
__constant__ int c_SW[4] = {128, 64, 32, 16};
__constant__ int c_START[4] = {0, 16384, 20480, 21504};

__global__ __launch_bounds__(256)
void deform_kernel(const __half* __restrict__ vh, const float* __restrict__ ow,
                   const float* __restrict__ ref, __half* __restrict__ oh) {
    const int wid  = blockIdx.x * 8 + (threadIdx.x >> 5);
    const int lane = threadIdx.x & 31;
    const int h    = wid & 7;
    const int bq   = wid >> 3;
    const int b    = bq / LQ_;

    const float* ar = ow + (size_t)bq * NOW + 256 + h * 16;
    float w[16];
    float mx = -1e30f;
    #pragma unroll
    for (int j = 0; j < 16; j++) { w[j] = ar[j]; mx = fmaxf(mx, w[j]); }
    float s = 0.0f;
    #pragma unroll
    for (int j = 0; j < 16; j++) { w[j] = expf(w[j] - mx); s += w[j]; }
    const float inv_s = 1.0f / s;

    const float refx = ref[bq * 2 + 0];
    const float refy = ref[bq * 2 + 1];
    const float* ob = ow + (size_t)bq * NOW + h * 32;
    const __half* vb = vh + (size_t)b * LQ_ * C_ + h * DK_ + lane;

    float acc = 0.0f;
    #pragma unroll
    for (int l = 0; l < 4; l++) {
        const int   Wl = c_SW[l];
        const float fw = (float)Wl;
        const int   st = c_START[l];
        #pragma unroll
        for (int k = 0; k < KPT; k++) {
            float ox = ob[l * 8 + k * 2 + 0];
            float oy = ob[l * 8 + k * 2 + 1];
            float x = (refx + ox * (1.0f / fw)) * (fw - 1.0f);
            float y = (refy + oy * (1.0f / fw)) * (fw - 1.0f);
            x = fminf(fmaxf(x, 0.0f), fw - 1.0f);
            y = fminf(fmaxf(y, 0.0f), fw - 1.0f);
            float x0f = floorf(x), y0f = floorf(y);
            int x0 = (int)x0f, y0 = (int)y0f;
            int x1 = min(x0 + 1, Wl - 1);
            int y1 = min(y0 + 1, Wl - 1);
            float wx = x - x0f, wy = y - y0f;
            float aw = w[l * 4 + k] * inv_s;

            float v00 = __half2float(vb[(size_t)(st + y0 * Wl + x0) * C_]);
            float v01 = __half2float(vb[(size_t)(st + y0 * Wl + x1) * C_]);
            float v10 = __half2float(vb[(size_t)(st + y1 * Wl + x0) * C_]);
            float v11 = __half2float(vb[(size_t)(st + y1 * Wl + x1) * C_]);
            float bil = (1.0f - wx) * (1.0f - wy) * v00
                      + wx * (1.0f - wy) * v01
                      + (1.0f - wx) * wy * v10
                      + wx * wy * v11;
            acc = fmaf(aw, bil, acc);
        }
    }
    oh[(size_t)bq * C_ + h * DK_ + lane] = __float2half_rn(acc);
}

// ---------------------------------------------------------------------------
// LayerNorm w/ residual: v = LN(a + r)*s + bb.
// POSADD: emit v+pos (fused next-layer addpos). EMITH: also emit fp16.
// ---------------------------------------------------------------------------
template<int POSADD, int EMITH>
__global__ __launch_bounds__(256)
void ln_residual(const float* __restrict__ a, const float* __restrict__ r,
                 const float* __restrict__ s, const float* __restrict__ bb,
                 const float* __restrict__ pos,
                 float* __restrict__ o, __half* __restrict__ ph) {
    const int row  = blockIdx.x * 8 + (threadIdx.x >> 5);
    const int lane = threadIdx.x & 31;
    const float* pa = a + (size_t)row * C_;
    const float* pr = r + (size_t)row * C_;

    float vals[8];
    float sum = 0.0f;
    #pragma unroll
    for (int j = 0; j < 8; j++) {
        int e = lane + 32 * j;
        float t = pa[e] + pr[e];
        vals[j] = t;
        sum += t;
    }
    #pragma unroll
    for (int d = 16; d > 0; d >>= 1) sum += __shfl_xor_sync(0xFFFFFFFF, sum, d);
    const float mean = sum * (1.0f / C_);

    float sq = 0.0f;
    #pragma unroll
    for (int j = 0; j < 8; j++) {
        float d = vals[j] - mean;
        sq = fmaf(d, d, sq);
    }
    #pragma unroll
    for (int d = 16; d > 0; d >>= 1) sq += __shfl_xor_sync(0xFFFFFFFF, sq, d);
    const float inv = rsqrtf(sq * (1.0f / C_) + 1e-5f);

    float* po = o + (size_t)row * C_;
    #pragma unroll
    for (int j = 0; j < 8; j++) {
        int e = lane + 32 * j;
        float v = (vals[j] - mean) * inv * s[e] + bb[e];
        if (POSADD) v += pos[(size_t)row * C_ + e];
        po[e] = v;
        if (EMITH) ph[(size_t)row * C_ + e] = __float2half_rn(v);
    }
}

// ---------------------------------------------------------------------------
// Host orchestration
// ---------------------------------------------------------------------------
extern "C" void kernel_launch(void* const* d_in, const int* in_sizes, int n_in,
                              void* d_out, int out_size) {
    const float* src  = (const float*)d_in[0];
    const float* pos  = (const float*)d_in[1];
    const float* ref  = (const float*)d_in[2];
    const float* Woff = (const float*)d_in[3];
    const float* boff = (const float*)d_in[4];
    const float* Wat  = (const float*)d_in[5];
    const float* bat  = (const float*)d_in[6];
    const float* Wv   = (const float*)d_in[7];
    const float* bv   = (const float*)d_in[8];
    const float* Wo   = (const float*)d_in[9];
    const float* bo   = (const float*)d_in[10];
    const float* W1   = (const float*)d_in[11];
    const float* b1   = (const float*)d_in[12];
    const float* W2   = (const float*)d_in[13];
    const float* b2   = (const float*)d_in[14];
    const float* n1s  = (const float*)d_in[15];
    const float* n1b  = (const float*)d_in[16];
    const float* n2s  = (const float*)d_in[17];
    const float* n2b  = (const float*)d_in[18];
    float* outp = (float*)d_out;

    float *px, *pxp, *pow, *pproj, *pbp;
    __half *pvh, *pah, *phh;
    __half *wproj, *wo, *w1, *w2;
    cudaGetSymbolAddress((void**)&px,     g_x);
    cudaGetSymbolAddress((void**)&pxp,    g_xp);
    cudaGetSymbolAddress((void**)&pow,    g_ow);
    cudaGetSymbolAddress((void**)&pproj,  g_proj);
    cudaGetSymbolAddress((void**)&pbp,    g_bpack);
    cudaGetSymbolAddress((void**)&pvh,    g_v_h);
    cudaGetSymbolAddress((void**)&pah,    g_a_h);
    cudaGetSymbolAddress((void**)&phh,    g_h_h);
    cudaGetSymbolAddress((void**)&wproj,  g_wproj);
    cudaGetSymbolAddress((void**)&wo,     g_wo);
    cudaGetSymbolAddress((void**)&w1,     g_w1);
    cudaGetSymbolAddress((void**)&w2,     g_w2);

    const int M = MROWS;
    const int n4 = M * C_ / 4;
    const int SMEM = 98304;   // 3 stages x 32KB

    cudaFuncSetAttribute(mma_gemm<0, 0>,
                         cudaFuncAttributeMaxDynamicSharedMemorySize, SMEM);
    cudaFuncSetAttribute(mma_gemm<0, 2>,
                         cudaFuncAttributeMaxDynamicSharedMemorySize, SMEM);
    cudaFuncSetAttribute(mma_gemm<1, 1>,
                         cudaFuncAttributeMaxDynamicSharedMemorySize, SMEM);

    // Weight packing (deterministic, per call)
    {
        int t0 = NL_ * NPACK * C_;
        pack_proj_w<<<(t0 + 255) / 256, 256>>>(Wv, Woff, Wat, wproj);
        int t1 = NL_ * C_ * C_;
        pack_w<<<(t1 + 255) / 256, 256>>>(Wo, wo, C_, C_);
        int t2 = NL_ * FF_ * C_;
        pack_w<<<(t2 + 255) / 256, 256>>>(W1, w1, C_, FF_);
        pack_w<<<(t2 + 255) / 256, 256>>>(W2, w2, FF_, C_);
        int tb = NL_ * NPACK;
        packb_kernel<<<(tb + 255) / 256, 256>>>(bv, boff, bat, pbp);
    }

    dim3 gAdd((n4 + 255) / 256);
    dim3 gProj(NPACK / 128, M / 128);   // (5, 340)
    dim3 gN256(C_ / 128, M / 128);      // (2, 340)
    dim3 gN1024(FF_ / 128, M / 128);    // (8, 340)
    dim3 gDef(M);
    dim3 gLN(M / 8);

    // Layer 0 addpos; later layers get it fused into LN2
    addpos_kernel<<<gAdd, 256>>>(src, pos, pxp, pah, n4);

    for (int i = 0; i < NL_; i++) {
        const float* bp_i = pbp + (size_t)i * NPACK;
        const float* bo_i = bo + (size_t)i * C_;
        const float* b1_i = b1 + (size_t)i * FF_;
        const float* b2_i = b2 + (size_t)i * C_;

        // Fused projections -> v fp16 | off/att fp32   (N=640, K=256)
        mma_gemm<0, 2><<<gProj, 256, SMEM>>>(pah,
            wproj + (size_t)i * NPACK * C_,
            bp_i, nullptr, pvh, pow, NPACK, C_);

        deform_kernel<<<gDef, 256>>>(pvh, pow, ref, pah);

        // Wo: proj = attn @ Wo   (N=256, K=256)
        mma_gemm<0, 0><<<gN256, 256, SMEM>>>(pah,
            wo + (size_t)i * C_ * C_,
            bo_i, pproj, nullptr, nullptr, C_, C_);

        // LN1: x = LN(xp + proj); emit fp32 + fp16
        ln_residual<0, 1><<<gLN, 256>>>(pxp, pproj, n1s + (size_t)i * C_,
                                        n1b + (size_t)i * C_, nullptr, px, pah);

        // W1 + ReLU -> hid fp16   (N=1024, K=256)
        mma_gemm<1, 1><<<gN1024, 256, SMEM>>>(pah,
            w1 + (size_t)i * FF_ * C_,
            b1_i, nullptr, phh, nullptr, FF_, C_);

        // W2: proj = hid @ W2   (N=256, K=1024)
        mma_gemm<0, 0><<<gN256, 256, SMEM>>>(phh,
            w2 + (size_t)i * C_ * FF_,
            b2_i, pproj, nullptr, nullptr, C_, FF_);

        // LN2: final layer emits output; else fuse +pos for next layer
        if (i == NL_ - 1) {
            ln_residual<0, 0><<<gLN, 256>>>(px, pproj, n2s + (size_t)i * C_,
                                            n2b + (size_t)i * C_, nullptr,
                                            outp, nullptr);
        } else {
            ln_residual<1, 1><<<gLN, 256>>>(px, pproj, n2s + (size_t)i * C_,
                                            n2b + (size_t)i * C_, pos,
                                            pxp, pah);
        }
    }
}

// round 11
// speedup vs baseline: 3.3003x; 1.2429x over previous
#include <cuda_runtime.h>
#include <cuda_fp16.h>
#include <math.h>
#include <stdint.h>

// Problem constants
#define B_    2
#define LQ_   21760
#define C_    256
#define NHEAD 8
#define KPT   4
#define NL_   6
#define FF_   1024
#define DK_   32
#define MROWS (B_ * LQ_)          // 43520
#define NPACK 640                 // 256 (v) + 256 (off) + 128 (att)
#define NOW   384                 // off|att compact row width

// ---------------------------------------------------------------------------
// Device scratch (no runtime allocation)
// ---------------------------------------------------------------------------
__device__ float g_x    [MROWS * C_];
__device__ float g_xp   [MROWS * C_];
__device__ float g_ow   [MROWS * NOW];    // off (256) | att (128), fp32
__device__ float g_proj [MROWS * C_];

__device__ __half g_v_h [MROWS * C_];     // sampled-value tensor, fp16
__device__ __half g_a_h [MROWS * C_];     // xp / attn / ln1-out fp16 (reused)
__device__ __half g_h_h [MROWS * FF_];    // hid fp16

// fp16 weights, [N,K] transposed layout (single-rounded)
__device__ __half g_wproj[NL_ * NPACK * C_];
__device__ __half g_wo   [NL_ * C_ * C_];
__device__ __half g_w1   [NL_ * FF_ * C_];
__device__ __half g_w2   [NL_ * C_ * FF_];
__device__ float  g_bpack[NL_ * NPACK];

// ---------------------------------------------------------------------------
// Helpers
// ---------------------------------------------------------------------------
__device__ __forceinline__ uint32_t smem_u32(const void* p) {
    uint32_t a;
    asm("{ .reg .u64 t; cvta.to.shared.u64 t, %1; cvt.u32.u64 %0, t; }"
        : "=r"(a) : "l"(p));
    return a;
}

#define MMA_F16(d, a, b0v, b1v)                                               \
    asm volatile("mma.sync.aligned.m16n8k16.row.col.f32.f16.f16.f32 "         \
        "{%0,%1,%2,%3}, {%4,%5,%6,%7}, {%8,%9}, {%0,%1,%2,%3};"               \
        : "+f"((d)[0]), "+f"((d)[1]), "+f"((d)[2]), "+f"((d)[3])              \
        : "r"((a)[0]), "r"((a)[1]), "r"((a)[2]), "r"((a)[3]),                 \
          "r"(b0v), "r"(b1v))

#define LDMATRIX_X4(r0, r1, r2, r3, addr)                                     \
    asm volatile("ldmatrix.sync.aligned.m8n8.x4.shared.b16 {%0,%1,%2,%3}, [%4];" \
        : "=r"(r0), "=r"(r1), "=r"(r2), "=r"(r3) : "r"(addr))

#define CP_ASYNC16(saddr, gptr)                                               \
    asm volatile("cp.async.cg.shared.global [%0], [%1], 16;"                  \
        :: "r"(saddr), "l"(gptr))

// ---------------------------------------------------------------------------
// Weight packing (fp32 [K,N] -> fp16 [N,K])
// ---------------------------------------------------------------------------
__global__ void pack_proj_w(const float* __restrict__ Wv,
                            const float* __restrict__ Woff,
                            const float* __restrict__ Wat,
                            __half* __restrict__ Bh) {
    int idx = blockIdx.x * blockDim.x + threadIdx.x;   // NL*640*256
    if (idx >= NL_ * NPACK * C_) return;
    int k = idx & 255;
    int n = (idx >> 8) % NPACK;
    int l = idx / (NPACK * C_);
    float v;
    if (n < 256)      v = Wv  [((size_t)l * C_ + k) * 256 + n];
    else if (n < 512) v = Woff[((size_t)l * C_ + k) * 256 + (n - 256)];
    else              v = Wat [((size_t)l * C_ + k) * 128 + (n - 512)];
    Bh[idx] = __float2half_rn(v);
}

__global__ void pack_w(const float* __restrict__ W,
                       __half* __restrict__ Bh, int K, int N) {
    int idx = blockIdx.x * blockDim.x + threadIdx.x;   // NL*N*K
    if (idx >= NL_ * N * K) return;
    int k = idx % K;
    int n = (idx / K) % N;
    int l = idx / (N * K);
    Bh[idx] = __float2half_rn(W[(size_t)l * K * N + (size_t)k * N + n]);
}

__global__ void packb_kernel(const float* __restrict__ bv,
                             const float* __restrict__ boff,
                             const float* __restrict__ bat,
                             float* __restrict__ bp) {
    int idx = blockIdx.x * blockDim.x + threadIdx.x;
    if (idx >= NL_ * NPACK) return;
    int n = idx % NPACK;
    int l = idx / NPACK;
    float val;
    if (n < 256)      val = bv  [(size_t)l * 256 + n];
    else if (n < 512) val = boff[(size_t)l * 256 + (n - 256)];
    else              val = bat [(size_t)l * 128 + (n - 512)];
    bp[idx] = val;
}

// ---------------------------------------------------------------------------
// addpos (layer 0 only): xp = x + pos -> fp32 + fp16
// ---------------------------------------------------------------------------
__global__ void addpos_kernel(const float* __restrict__ x,
                              const float* __restrict__ pos,
                              float* __restrict__ xp,
                              __half* __restrict__ ph, int n4) {
    int i = blockIdx.x * blockDim.x + threadIdx.x;
    if (i >= n4) return;
    float4 a = ((const float4*)x)[i];
    float4 b = ((const float4*)pos)[i];
    float4 o;
    o.x = a.x + b.x; o.y = a.y + b.y; o.z = a.z + b.z; o.w = a.w + b.w;
    ((float4*)xp)[i] = o;
    ((__half2*)ph)[i * 2]     = __halves2half2(__float2half_rn(o.x), __float2half_rn(o.y));
    ((__half2*)ph)[i * 2 + 1] = __halves2half2(__float2half_rn(o.z), __float2half_rn(o.w));
}

// ---------------------------------------------------------------------------
// mma.sync fp16 GEMM: C[M,N] = A[M,K] @ B[N,K]^T + bias.
// CTA 128x128, BK=64, 8 warps (4Mx2N). Stage {A,B} = 32KB; 3 stages, 96KB.
// __launch_bounds__(256, 2): cap regs at 128 so 2 CTAs/SM actually fit.
// OMODE: 0 = fp32 out, 1 = fp16 out, 2 = proj split (v fp16 | ow fp32)
// ---------------------------------------------------------------------------
template<int RELU, int OMODE>
__global__ __launch_bounds__(256, 2)
void mma_gemm(const __half* __restrict__ A,
              const __half* __restrict__ Bm,
              const float* __restrict__ bias,
              float* __restrict__ Cf,
              __half* __restrict__ Chf,
              float* __restrict__ Cow,
              int N, int K) {
    extern __shared__ uint8_t smem[];
    const int tid  = threadIdx.x;
    const int wid  = tid >> 5;
    const int lane = tid & 31;
    const int brow = blockIdx.y * 128;
    const int bcol = blockIdx.x * 128;
    const int kIters = K >> 6;

    const int ldrow = tid >> 1;
    const int ldcb  = (tid & 1) << 2;
    const uint32_t smbase = smem_u32(smem);
    const uint32_t rb = ldrow * 128;

    auto load_tile = [&](int k, int buf) {
        uint32_t sA = smbase + buf * 32768;
        uint32_t sB = sA + 16384;
        const __half* ga = A  + (size_t)(brow + ldrow) * K + (k << 6) + ldcb * 8;
        const __half* gb = Bm + (size_t)(bcol + ldrow) * K + (k << 6) + ldcb * 8;
        #pragma unroll
        for (int j = 0; j < 4; j++) {
            uint32_t sw = rb + (((ldcb + j) ^ (ldrow & 7)) << 4);
            CP_ASYNC16(sA + sw, ga + j * 8);
            CP_ASYNC16(sB + sw, gb + j * 8);
        }
    };

    const int wm = (wid & 3) * 32;
    const int wn = (wid >> 2) * 64;

    float acc[2][8][4];
    #pragma unroll
    for (int mi = 0; mi < 2; mi++)
        #pragma unroll
        for (int nj = 0; nj < 8; nj++)
            #pragma unroll
            for (int r = 0; r < 4; r++) acc[mi][nj][r] = 0.0f;

    auto compute = [&](int buf) {
        uint32_t sA = smbase + buf * 32768;
        uint32_t sB = sA + 16384;
        #pragma unroll
        for (int ks = 0; ks < 4; ks++) {
            uint32_t a[2][4];
            const int c = ks * 2 + (lane >> 4);
            #pragma unroll
            for (int mi = 0; mi < 2; mi++) {
                int r = wm + mi * 16 + (lane & 15);
                uint32_t addr = sA + r * 128 + ((c ^ (r & 7)) << 4);
                LDMATRIX_X4(a[mi][0], a[mi][1], a[mi][2], a[mi][3], addr);
            }
            #pragma unroll
            for (int ng = 0; ng < 4; ng++) {
                int r = wn + ng * 16 + (lane & 15);
                uint32_t soff = r * 128 + ((c ^ (r & 7)) << 4);
                uint32_t b0, b1, b2, b3;
                LDMATRIX_X4(b0, b1, b2, b3, sB + soff);
                #pragma unroll
                for (int mi = 0; mi < 2; mi++) {
                    MMA_F16(acc[mi][ng * 2 + 0], a[mi], b0, b2);
                    MMA_F16(acc[mi][ng * 2 + 1], a[mi], b1, b3);
                }
            }
        }
    };

    // 3-stage pipeline, one sync per iteration
    load_tile(0, 0);
    asm volatile("cp.async.commit_group;" ::: "memory");
    if (kIters > 1) {
        load_tile(1, 1);
        asm volatile("cp.async.commit_group;" ::: "memory");
    }
    for (int t = 0; t < kIters; t++) {
        if (t + 1 < kIters)
            asm volatile("cp.async.wait_group 1;" ::: "memory");
        else
            asm volatile("cp.async.wait_group 0;" ::: "memory");
        __syncthreads();
        if (t + 2 < kIters) {
            load_tile(t + 2, (t + 2) % 3);
            asm volatile("cp.async.commit_group;" ::: "memory");
        }
        compute(t % 3);
    }

    // Epilogue
    const int tr = lane >> 2;
    const int tc = (lane & 3) * 2;
    #pragma unroll
    for (int mi = 0; mi < 2; mi++) {
        #pragma unroll
        for (int nj = 0; nj < 8; nj++) {
            const int col = bcol + wn + nj * 8 + tc;
            const float bb0 = bias[col], bb1 = bias[col + 1];
            #pragma unroll
            for (int rr = 0; rr < 2; rr++) {
                const int row = brow + wm + mi * 16 + rr * 8 + tr;
                float v0 = acc[mi][nj][rr * 2 + 0] + bb0;
                float v1 = acc[mi][nj][rr * 2 + 1] + bb1;
                if (RELU) { v0 = fmaxf(v0, 0.f); v1 = fmaxf(v1, 0.f); }
                if (OMODE == 0) {
                    float2 o; o.x = v0; o.y = v1;
                    *(float2*)(Cf + (size_t)row * N + col) = o;
                } else if (OMODE == 1) {
                    *(__half2*)(Chf + (size_t)row * N + col) =
                        __halves2half2(__float2half_rn(v0), __float2half_rn(v1));
                } else {
                    if (col < 256) {
                        *(__half2*)(Chf + (size_t)row * C_ + col) =
                            __halves2half2(__float2half_rn(v0), __float2half_rn(v1));
                    } else {
                        float2 o; o.x = v0; o.y = v1;
                        *(float2*)(Cow + (size_t)row * NOW + (col - 256)) = o;
                    }
                }
            }
        }
    }
}

// ---------------------------------------------------------------------------
// Deformable attention sampling, half2 channel pairs.
// 16 lanes per head (lane=channel pair), 2 heads per warp, 2 bq per block.
// ---------------------------------------------------------------------------
__constant__ int c_SW[4] = {128, 64, 32, 16};
__constant__ int c_START[4] = {0, 16384, 20480, 21504};

__global__ __launch_bounds__(256)
void deform_kernel(const __half* __restrict__ vh, const float* __restrict__ ow,
                   const float* __restrict__ ref, __half* __restrict__ oh) {
    const int tid  = threadIdx.x;
    const int wblk = tid >> 5;            // warp in block 0..7
    const int lane = tid & 31;
    const int sub  = lane >> 4;           // which head within warp
    const int li   = lane & 15;           // channel pair index
    const int bq   = blockIdx.x * 2 + (wblk >> 2);
    const int h    = ((wblk & 3) << 1) + sub;
    const int b    = bq / LQ_;

    // Softmax over 16 logits (redundant across the 16 lanes of this head)
    const float* ar = ow + (size_t)bq * NOW + 256 + h * 16;
    float w[16];
    float mx = -1e30f;
    #pragma unroll
    for (int j = 0; j < 16; j++) { w[j] = ar[j]; mx = fmaxf(mx, w[j]); }
    float s = 0.0f;
    #pragma unroll
    for (int j = 0; j < 16; j++) { w[j] = expf(w[j] - mx); s += w[j]; }
    const float inv_s = 1.0f / s;

    const float refx = ref[bq * 2 + 0];
    const float refy = ref[bq * 2 + 1];
    const float* ob = ow + (size_t)bq * NOW + h * 32;
    const __half2* vb2 = (const __half2*)vh
                       + ((size_t)b * LQ_ * C_ + h * DK_) / 2 + li;

    float accx = 0.0f, accy = 0.0f;
    #pragma unroll
    for (int l = 0; l < 4; l++) {
        const int   Wl = c_SW[l];
        const float fw = (float)Wl;
        const int   st = c_START[l];
        #pragma unroll
        for (int k = 0; k < KPT; k++) {
            float ox = ob[l * 8 + k * 2 + 0];
            float oy = ob[l * 8 + k * 2 + 1];
            float x = (refx + ox * (1.0f / fw)) * (fw - 1.0f);
            float y = (refy + oy * (1.0f / fw)) * (fw - 1.0f);
            x = fminf(fmaxf(x, 0.0f), fw - 1.0f);
            y = fminf(fmaxf(y, 0.0f), fw - 1.0f);
            float x0f = floorf(x), y0f = floorf(y);
            int x0 = (int)x0f, y0 = (int)y0f;
            int x1 = min(x0 + 1, Wl - 1);
            int y1 = min(y0 + 1, Wl - 1);
            float wx = x - x0f, wy = y - y0f;
            float aw = w[l * 4 + k] * inv_s;

            float2 v00 = __half22float2(vb2[(size_t)(st + y0 * Wl + x0) * (C_ / 2)]);
            float2 v01 = __half22float2(vb2[(size_t)(st + y0 * Wl + x1) * (C_ / 2)]);
            float2 v10 = __half22float2(vb2[(size_t)(st + y1 * Wl + x0) * (C_ / 2)]);
            float2 v11 = __half22float2(vb2[(size_t)(st + y1 * Wl + x1) * (C_ / 2)]);
            float w00 = (1.0f - wx) * (1.0f - wy);
            float w01 = wx * (1.0f - wy);
            float w10 = (1.0f - wx) * wy;
            float w11 = wx * wy;
            float bx = w00 * v00.x + w01 * v01.x + w10 * v10.x + w11 * v11.x;
            float by = w00 * v00.y + w01 * v01.y + w10 * v10.y + w11 * v11.y;
            accx = fmaf(aw, bx, accx);
            accy = fmaf(aw, by, accy);
        }
    }
    ((__half2*)oh)[((size_t)bq * C_ + h * DK_) / 2 + li] =
        __halves2half2(__float2half_rn(accx), __float2half_rn(accy));
}

// ---------------------------------------------------------------------------
// LayerNorm w/ residual: v = LN(a + r)*s + bb.
// POSADD: emit v+pos (fused next-layer addpos). EMITH: also emit fp16.
// ---------------------------------------------------------------------------
template<int POSADD, int EMITH>
__global__ __launch_bounds__(256)
void ln_residual(const float* __restrict__ a, const float* __restrict__ r,
                 const float* __restrict__ s, const float* __restrict__ bb,
                 const float* __restrict__ pos,
                 float* __restrict__ o, __half* __restrict__ ph) {
    const int row  = blockIdx.x * 8 + (threadIdx.x >> 5);
    const int lane = threadIdx.x & 31;
    const float* pa = a + (size_t)row * C_;
    const float* pr = r + (size_t)row * C_;

    float vals[8];
    float sum = 0.0f;
    #pragma unroll
    for (int j = 0; j < 8; j++) {
        int e = lane + 32 * j;
        float t = pa[e] + pr[e];
        vals[j] = t;
        sum += t;
    }
    #pragma unroll
    for (int d = 16; d > 0; d >>= 1) sum += __shfl_xor_sync(0xFFFFFFFF, sum, d);
    const float mean = sum * (1.0f / C_);

    float sq = 0.0f;
    #pragma unroll
    for (int j = 0; j < 8; j++) {
        float d = vals[j] - mean;
        sq = fmaf(d, d, sq);
    }
    #pragma unroll
    for (int d = 16; d > 0; d >>= 1) sq += __shfl_xor_sync(0xFFFFFFFF, sq, d);
    const float inv = rsqrtf(sq * (1.0f / C_) + 1e-5f);

    float* po = o + (size_t)row * C_;
    #pragma unroll
    for (int j = 0; j < 8; j++) {
        int e = lane + 32 * j;
        float v = (vals[j] - mean) * inv * s[e] + bb[e];
        if (POSADD) v += pos[(size_t)row * C_ + e];
        po[e] = v;
        if (EMITH) ph[(size_t)row * C_ + e] = __float2half_rn(v);
    }
}

// ---------------------------------------------------------------------------
// Host orchestration
// ---------------------------------------------------------------------------
extern "C" void kernel_launch(void* const* d_in, const int* in_sizes, int n_in,
                              void* d_out, int out_size) {
    const float* src  = (const float*)d_in[0];
    const float* pos  = (const float*)d_in[1];
    const float* ref  = (const float*)d_in[2];
    const float* Woff = (const float*)d_in[3];
    const float* boff = (const float*)d_in[4];
    const float* Wat  = (const float*)d_in[5];
    const float* bat  = (const float*)d_in[6];
    const float* Wv   = (const float*)d_in[7];
    const float* bv   = (const float*)d_in[8];
    const float* Wo   = (const float*)d_in[9];
    const float* bo   = (const float*)d_in[10];
    const float* W1   = (const float*)d_in[11];
    const float* b1   = (const float*)d_in[12];
    const float* W2   = (const float*)d_in[13];
    const float* b2   = (const float*)d_in[14];
    const float* n1s  = (const float*)d_in[15];
    const float* n1b  = (const float*)d_in[16];
    const float* n2s  = (const float*)d_in[17];
    const float* n2b  = (const float*)d_in[18];
    float* outp = (float*)d_out;

    float *px, *pxp, *pow, *pproj, *pbp;
    __half *pvh, *pah, *phh;
    __half *wproj, *wo, *w1, *w2;
    cudaGetSymbolAddress((void**)&px,     g_x);
    cudaGetSymbolAddress((void**)&pxp,    g_xp);
    cudaGetSymbolAddress((void**)&pow,    g_ow);
    cudaGetSymbolAddress((void**)&pproj,  g_proj);
    cudaGetSymbolAddress((void**)&pbp,    g_bpack);
    cudaGetSymbolAddress((void**)&pvh,    g_v_h);
    cudaGetSymbolAddress((void**)&pah,    g_a_h);
    cudaGetSymbolAddress((void**)&phh,    g_h_h);
    cudaGetSymbolAddress((void**)&wproj,  g_wproj);
    cudaGetSymbolAddress((void**)&wo,     g_wo);
    cudaGetSymbolAddress((void**)&w1,     g_w1);
    cudaGetSymbolAddress((void**)&w2,     g_w2);

    const int M = MROWS;
    const int n4 = M * C_ / 4;
    const int SMEM = 98304;   // 3 stages x 32KB

    cudaFuncSetAttribute(mma_gemm<0, 0>,
                         cudaFuncAttributeMaxDynamicSharedMemorySize, SMEM);
    cudaFuncSetAttribute(mma_gemm<0, 2>,
                         cudaFuncAttributeMaxDynamicSharedMemorySize, SMEM);
    cudaFuncSetAttribute(mma_gemm<1, 1>,
                         cudaFuncAttributeMaxDynamicSharedMemorySize, SMEM);

    // Weight packing (deterministic, per call)
    {
        int t0 = NL_ * NPACK * C_;
        pack_proj_w<<<(t0 + 255) / 256, 256>>>(Wv, Woff, Wat, wproj);
        int t1 = NL_ * C_ * C_;
        pack_w<<<(t1 + 255) / 256, 256>>>(Wo, wo, C_, C_);
        int t2 = NL_ * FF_ * C_;
        pack_w<<<(t2 + 255) / 256, 256>>>(W1, w1, C_, FF_);
        pack_w<<<(t2 + 255) / 256, 256>>>(W2, w2, FF_, C_);
        int tb = NL_ * NPACK;
        packb_kernel<<<(tb + 255) / 256, 256>>>(bv, boff, bat, pbp);
    }

    dim3 gAdd((n4 + 255) / 256);
    dim3 gProj(NPACK / 128, M / 128);   // (5, 340)
    dim3 gN256(C_ / 128, M / 128);      // (2, 340)
    dim3 gN1024(FF_ / 128, M / 128);    // (8, 340)
    dim3 gDef(M / 2);                   // 2 bq per block
    dim3 gLN(M / 8);

    // Layer 0 addpos; later layers get it fused into LN2
    addpos_kernel<<<gAdd, 256>>>(src, pos, pxp, pah, n4);

    for (int i = 0; i < NL_; i++) {
        const float* bp_i = pbp + (size_t)i * NPACK;
        const float* bo_i = bo + (size_t)i * C_;
        const float* b1_i = b1 + (size_t)i * FF_;
        const float* b2_i = b2 + (size_t)i * C_;

        // Fused projections -> v fp16 | off/att fp32   (N=640, K=256)
        mma_gemm<0, 2><<<gProj, 256, SMEM>>>(pah,
            wproj + (size_t)i * NPACK * C_,
            bp_i, nullptr, pvh, pow, NPACK, C_);

        deform_kernel<<<gDef, 256>>>(pvh, pow, ref, pah);

        // Wo: proj = attn @ Wo   (N=256, K=256)
        mma_gemm<0, 0><<<gN256, 256, SMEM>>>(pah,
            wo + (size_t)i * C_ * C_,
            bo_i, pproj, nullptr, nullptr, C_, C_);

        // LN1: x = LN(xp + proj); emit fp32 + fp16
        ln_residual<0, 1><<<gLN, 256>>>(pxp, pproj, n1s + (size_t)i * C_,
                                        n1b + (size_t)i * C_, nullptr, px, pah);

        // W1 + ReLU -> hid fp16   (N=1024, K=256)
        mma_gemm<1, 1><<<gN1024, 256, SMEM>>>(pah,
            w1 + (size_t)i * FF_ * C_,
            b1_i, nullptr, phh, nullptr, FF_, C_);

        // W2: proj = hid @ W2   (N=256, K=1024)
        mma_gemm<0, 0><<<gN256, 256, SMEM>>>(phh,
            w2 + (size_t)i * C_ * FF_,
            b2_i, pproj, nullptr, nullptr, C_, FF_);

        // LN2: final layer emits output; else fuse +pos for next layer
        if (i == NL_ - 1) {
            ln_residual<0, 0><<<gLN, 256>>>(px, pproj, n2s + (size_t)i * C_,
                                            n2b + (size_t)i * C_, nullptr,
                                            outp, nullptr);
        } else {
            ln_residual<1, 1><<<gLN, 256>>>(px, pproj, n2s + (size_t)i * C_,
                                            n2b + (size_t)i * C_, pos,
                                            pxp, pah);
        }
    }
}

// round 12
// speedup vs baseline: 3.6519x; 1.1065x over previous
#include <cuda_runtime.h>
#include <cuda_fp16.h>
#include <math.h>
#include <stdint.h>

// Problem constants
#define B_    2
#define LQ_   21760
#define C_    256
#define NHEAD 8
#define KPT   4
#define NL_   6
#define FF_   1024
#define DK_   32
#define MROWS (B_ * LQ_)          // 43520
#define NPACK 640                 // 256 (v) + 256 (off) + 128 (att)
#define NOW   384                 // off|att compact row width

// ---------------------------------------------------------------------------
// Device scratch (no runtime allocation)
// ---------------------------------------------------------------------------
__device__ float g_x    [MROWS * C_];
__device__ float g_xp   [MROWS * C_];
__device__ float g_ow   [MROWS * NOW];    // off (256) | att (128), fp32
__device__ float g_proj [MROWS * C_];

__device__ __half g_v_h [MROWS * C_];     // sampled-value tensor, fp16
__device__ __half g_a_h [MROWS * C_];     // xp / attn / ln1-out fp16 (reused)
__device__ __half g_h_h [MROWS * FF_];    // hid fp16

// fp16 weights, [N,K] transposed layout (single-rounded)
__device__ __half g_wproj[NL_ * NPACK * C_];
__device__ __half g_wo   [NL_ * C_ * C_];
__device__ __half g_w1   [NL_ * FF_ * C_];
__device__ __half g_w2   [NL_ * C_ * FF_];
__device__ float  g_bpack[NL_ * NPACK];

// ---------------------------------------------------------------------------
// Helpers
// ---------------------------------------------------------------------------
__device__ __forceinline__ uint32_t smem_u32(const void* p) {
    uint32_t a;
    asm("{ .reg .u64 t; cvta.to.shared.u64 t, %1; cvt.u32.u64 %0, t; }"
        : "=r"(a) : "l"(p));
    return a;
}

#define MMA_F16(d, a, b0v, b1v)                                               \
    asm volatile("mma.sync.aligned.m16n8k16.row.col.f32.f16.f16.f32 "         \
        "{%0,%1,%2,%3}, {%4,%5,%6,%7}, {%8,%9}, {%0,%1,%2,%3};"               \
        : "+f"((d)[0]), "+f"((d)[1]), "+f"((d)[2]), "+f"((d)[3])              \
        : "r"((a)[0]), "r"((a)[1]), "r"((a)[2]), "r"((a)[3]),                 \
          "r"(b0v), "r"(b1v))

#define LDMATRIX_X4(r0, r1, r2, r3, addr)                                     \
    asm volatile("ldmatrix.sync.aligned.m8n8.x4.shared.b16 {%0,%1,%2,%3}, [%4];" \
        : "=r"(r0), "=r"(r1), "=r"(r2), "=r"(r3) : "r"(addr))

#define CP_ASYNC16(saddr, gptr)                                               \
    asm volatile("cp.async.cg.shared.global [%0], [%1], 16;"                  \
        :: "r"(saddr), "l"(gptr))

// ---------------------------------------------------------------------------
// Weight packing (fp32 [K,N] -> fp16 [N,K])
// ---------------------------------------------------------------------------
__global__ void pack_proj_w(const float* __restrict__ Wv,
                            const float* __restrict__ Woff,
                            const float* __restrict__ Wat,
                            __half* __restrict__ Bh) {
    int idx = blockIdx.x * blockDim.x + threadIdx.x;   // NL*640*256
    if (idx >= NL_ * NPACK * C_) return;
    int k = idx & 255;
    int n = (idx >> 8) % NPACK;
    int l = idx / (NPACK * C_);
    float v;
    if (n < 256)      v = Wv  [((size_t)l * C_ + k) * 256 + n];
    else if (n < 512) v = Woff[((size_t)l * C_ + k) * 256 + (n - 256)];
    else              v = Wat [((size_t)l * C_ + k) * 128 + (n - 512)];
    Bh[idx] = __float2half_rn(v);
}

__global__ void pack_w(const float* __restrict__ W,
                       __half* __restrict__ Bh, int K, int N) {
    int idx = blockIdx.x * blockDim.x + threadIdx.x;   // NL*N*K
    if (idx >= NL_ * N * K) return;
    int k = idx % K;
    int n = (idx / K) % N;
    int l = idx / (N * K);
    Bh[idx] = __float2half_rn(W[(size_t)l * K * N + (size_t)k * N + n]);
}

__global__ void packb_kernel(const float* __restrict__ bv,
                             const float* __restrict__ boff,
                             const float* __restrict__ bat,
                             float* __restrict__ bp) {
    int idx = blockIdx.x * blockDim.x + threadIdx.x;
    if (idx >= NL_ * NPACK) return;
    int n = idx % NPACK;
    int l = idx / NPACK;
    float val;
    if (n < 256)      val = bv  [(size_t)l * 256 + n];
    else if (n < 512) val = boff[(size_t)l * 256 + (n - 256)];
    else              val = bat [(size_t)l * 128 + (n - 512)];
    bp[idx] = val;
}

// ---------------------------------------------------------------------------
// addpos (layer 0 only): xp = x + pos -> fp32 + fp16
// ---------------------------------------------------------------------------
__global__ void addpos_kernel(const float* __restrict__ x,
                              const float* __restrict__ pos,
                              float* __restrict__ xp,
                              __half* __restrict__ ph, int n4) {
    int i = blockIdx.x * blockDim.x + threadIdx.x;
    if (i >= n4) return;
    float4 a = ((const float4*)x)[i];
    float4 b = ((const float4*)pos)[i];
    float4 o;
    o.x = a.x + b.x; o.y = a.y + b.y; o.z = a.z + b.z; o.w = a.w + b.w;
    ((float4*)xp)[i] = o;
    ((__half2*)ph)[i * 2]     = __halves2half2(__float2half_rn(o.x), __float2half_rn(o.y));
    ((__half2*)ph)[i * 2 + 1] = __halves2half2(__float2half_rn(o.z), __float2half_rn(o.w));
}

// ---------------------------------------------------------------------------
// mma.sync fp16 GEMM: C[M,N] = A[M,K] @ B[N,K]^T + bias.
// Template BMt in {128, 64}; BN=128; 8 warps; 3-stage cp.async pipeline.
//   BMt=128: warps 4Mx2N (warp 32x64), stage 32KB
//   BMt=64 : warps 2Mx4N (warp 32x32), stage 24KB  (anti-wave-quantization)
// OMODE: 0 = fp32 out, 1 = fp16 out, 2 = proj split (v fp16 | ow fp32)
// ---------------------------------------------------------------------------
template<int BMt, int RELU, int OMODE>
__global__ __launch_bounds__(256, 2)
void mma_gemm(const __half* __restrict__ A,
              const __half* __restrict__ Bm,
              const float* __restrict__ bias,
              float* __restrict__ Cf,
              __half* __restrict__ Chf,
              float* __restrict__ Cow,
              int N, int K) {
    constexpr int MW    = BMt / 32;        // M-warps: 4 or 2
    constexpr int NW    = 8 / MW;          // N-warps: 2 or 4
    constexpr int WN    = 128 / NW;        // warp N extent: 64 or 32
    constexpr int NG    = WN / 16;         // 16-wide n-groups/warp: 4 or 2
    constexpr int ROWS  = BMt + 128;       // A rows + B rows per stage
    constexpr int STAGE = ROWS * 128;      // bytes per stage
    constexpr int PERT  = ROWS * 8 / 256;  // 16B chunks per thread: 8 or 6

    extern __shared__ uint8_t smem[];
    const int tid  = threadIdx.x;
    const int wid  = tid >> 5;
    const int lane = tid & 31;
    const int brow = blockIdx.y * BMt;
    const int bcol = blockIdx.x * 128;
    const int kIters = K >> 6;

    const uint32_t smbase = smem_u32(smem);

    auto load_tile = [&](int k, int buf) {
        uint32_t sbuf = smbase + buf * STAGE;
        const int koff = k << 6;
        #pragma unroll
        for (int i = 0; i < PERT; i++) {
            int cid = tid + (i << 8);
            int row = cid >> 3;
            int col = cid & 7;
            const __half* g;
            if (row < BMt) g = A  + (size_t)(brow + row) * K + koff + col * 8;
            else           g = Bm + (size_t)(bcol + row - BMt) * K + koff + col * 8;
            uint32_t sw = row * 128 + (((uint32_t)(col ^ (row & 7))) << 4);
            CP_ASYNC16(sbuf + sw, g);
        }
    };

    const int wm = (wid % MW) * 32;
    const int wn = (wid / MW) * WN;

    float acc[2][2 * NG][4];
    #pragma unroll
    for (int mi = 0; mi < 2; mi++)
        #pragma unroll
        for (int nj = 0; nj < 2 * NG; nj++)
            #pragma unroll
            for (int r = 0; r < 4; r++) acc[mi][nj][r] = 0.0f;

    auto compute = [&](int buf) {
        uint32_t sA = smbase + buf * STAGE;
        uint32_t sB = sA + BMt * 128;
        #pragma unroll
        for (int ks = 0; ks < 4; ks++) {
            uint32_t a[2][4];
            const int c = ks * 2 + (lane >> 4);
            #pragma unroll
            for (int mi = 0; mi < 2; mi++) {
                int r = wm + mi * 16 + (lane & 15);
                uint32_t addr = sA + r * 128 + ((c ^ (r & 7)) << 4);
                LDMATRIX_X4(a[mi][0], a[mi][1], a[mi][2], a[mi][3], addr);
            }
            #pragma unroll
            for (int ng = 0; ng < NG; ng++) {
                int r = wn + ng * 16 + (lane & 15);
                uint32_t soff = r * 128 + ((c ^ (r & 7)) << 4);
                uint32_t b0, b1, b2, b3;
                LDMATRIX_X4(b0, b1, b2, b3, sB + soff);
                #pragma unroll
                for (int mi = 0; mi < 2; mi++) {
                    MMA_F16(acc[mi][ng * 2 + 0], a[mi], b0, b2);
                    MMA_F16(acc[mi][ng * 2 + 1], a[mi], b1, b3);
                }
            }
        }
    };

    // 3-stage pipeline, one sync per iteration
    load_tile(0, 0);
    asm volatile("cp.async.commit_group;" ::: "memory");
    if (kIters > 1) {
        load_tile(1, 1);
        asm volatile("cp.async.commit_group;" ::: "memory");
    }
    for (int t = 0; t < kIters; t++) {
        if (t + 1 < kIters)
            asm volatile("cp.async.wait_group 1;" ::: "memory");
        else
            asm volatile("cp.async.wait_group 0;" ::: "memory");
        __syncthreads();
        if (t + 2 < kIters) {
            load_tile(t + 2, (t + 2) % 3);
            asm volatile("cp.async.commit_group;" ::: "memory");
        }
        compute(t % 3);
    }

    // Epilogue
    const int tr = lane >> 2;
    const int tc = (lane & 3) * 2;
    #pragma unroll
    for (int mi = 0; mi < 2; mi++) {
        #pragma unroll
        for (int nj = 0; nj < 2 * NG; nj++) {
            const int col = bcol + wn + nj * 8 + tc;
            const float bb0 = bias[col], bb1 = bias[col + 1];
            #pragma unroll
            for (int rr = 0; rr < 2; rr++) {
                const int row = brow + wm + mi * 16 + rr * 8 + tr;
                float v0 = acc[mi][nj][rr * 2 + 0] + bb0;
                float v1 = acc[mi][nj][rr * 2 + 1] + bb1;
                if (RELU) { v0 = fmaxf(v0, 0.f); v1 = fmaxf(v1, 0.f); }
                if (OMODE == 0) {
                    float2 o; o.x = v0; o.y = v1;
                    *(float2*)(Cf + (size_t)row * N + col) = o;
                } else if (OMODE == 1) {
                    *(__half2*)(Chf + (size_t)row * N + col) =
                        __halves2half2(__float2half_rn(v0), __float2half_rn(v1));
                } else {
                    if (col < 256) {
                        *(__half2*)(Chf + (size_t)row * C_ + col) =
                            __halves2half2(__float2half_rn(v0), __float2half_rn(v1));
                    } else {
                        float2 o; o.x = v0; o.y = v1;
                        *(float2*)(Cow + (size_t)row * NOW + (col - 256)) = o;
                    }
                }
            }
        }
    }
}

// ---------------------------------------------------------------------------
// Deformable attention sampling, half2 channel pairs.
// 16 lanes per head (lane=channel pair), 2 heads per warp, 2 bq per block.
// ---------------------------------------------------------------------------
__constant__ int c_SW[4] = {128, 64, 32, 16};
__constant__ int c_START[4] = {0, 16384, 20480, 21504};

__global__ __launch_bounds__(256)
void deform_kernel(const __half* __restrict__ vh, const float* __restrict__ ow,
                   const float* __restrict__ ref, __half* __restrict__ oh) {
    const int tid  = threadIdx.x;
    const int wblk = tid >> 5;
    const int lane = tid & 31;
    const int sub  = lane >> 4;
    const int li   = lane & 15;
    const int bq   = blockIdx.x * 2 + (wblk >> 2);
    const int h    = ((wblk & 3) << 1) + sub;
    const int b    = bq / LQ_;

    const float* ar = ow + (size_t)bq * NOW + 256 + h * 16;
    float w[16];
    float mx = -1e30f;
    #pragma unroll
    for (int j = 0; j < 16; j++) { w[j] = ar[j]; mx = fmaxf(mx, w[j]); }
    float s = 0.0f;
    #pragma unroll
    for (int j = 0; j < 16; j++) { w[j] = expf(w[j] - mx); s += w[j]; }
    const float inv_s = 1.0f / s;

    const float refx = ref[bq * 2 + 0];
    const float refy = ref[bq * 2 + 1];
    const float* ob = ow + (size_t)bq * NOW + h * 32;
    const __half2* vb2 = (const __half2*)vh
                       + ((size_t)b * LQ_ * C_ + h * DK_) / 2 + li;

    float accx = 0.0f, accy = 0.0f;
    #pragma unroll
    for (int l = 0; l < 4; l++) {
        const int   Wl = c_SW[l];
        const float fw = (float)Wl;
        const int   st = c_START[l];
        #pragma unroll
        for (int k = 0; k < KPT; k++) {
            float ox = ob[l * 8 + k * 2 + 0];
            float oy = ob[l * 8 + k * 2 + 1];
            float x = (refx + ox * (1.0f / fw)) * (fw - 1.0f);
            float y = (refy + oy * (1.0f / fw)) * (fw - 1.0f);
            x = fminf(fmaxf(x, 0.0f), fw - 1.0f);
            y = fminf(fmaxf(y, 0.0f), fw - 1.0f);
            float x0f = floorf(x), y0f = floorf(y);
            int x0 = (int)x0f, y0 = (int)y0f;
            int x1 = min(x0 + 1, Wl - 1);
            int y1 = min(y0 + 1, Wl - 1);
            float wx = x - x0f, wy = y - y0f;
            float aw = w[l * 4 + k] * inv_s;

            float2 v00 = __half22float2(vb2[(size_t)(st + y0 * Wl + x0) * (C_ / 2)]);
            float2 v01 = __half22float2(vb2[(size_t)(st + y0 * Wl + x1) * (C_ / 2)]);
            float2 v10 = __half22float2(vb2[(size_t)(st + y1 * Wl + x0) * (C_ / 2)]);
            float2 v11 = __half22float2(vb2[(size_t)(st + y1 * Wl + x1) * (C_ / 2)]);
            float w00 = (1.0f - wx) * (1.0f - wy);
            float w01 = wx * (1.0f - wy);
            float w10 = (1.0f - wx) * wy;
            float w11 = wx * wy;
            float bx = w00 * v00.x + w01 * v01.x + w10 * v10.x + w11 * v11.x;
            float by = w00 * v00.y + w01 * v01.y + w10 * v10.y + w11 * v11.y;
            accx = fmaf(aw, bx, accx);
            accy = fmaf(aw, by, accy);
        }
    }
    ((__half2*)oh)[((size_t)bq * C_ + h * DK_) / 2 + li] =
        __halves2half2(__float2half_rn(accx), __float2half_rn(accy));
}

// ---------------------------------------------------------------------------
// LayerNorm w/ residual: v = LN(a + r)*s + bb.
// POSADD: emit v+pos (fused next-layer addpos). EMITH: also emit fp16.
// ---------------------------------------------------------------------------
template<int POSADD, int EMITH>
__global__ __launch_bounds__(256)
void ln_residual(const float* __restrict__ a, const float* __restrict__ r,
                 const float* __restrict__ s, const float* __restrict__ bb,
                 const float* __restrict__ pos,
                 float* __restrict__ o, __half* __restrict__ ph) {
    const int row  = blockIdx.x * 8 + (threadIdx.x >> 5);
    const int lane = threadIdx.x & 31;
    const float* pa = a + (size_t)row * C_;
    const float* pr = r + (size_t)row * C_;

    float vals[8];
    float sum = 0.0f;
    #pragma unroll
    for (int j = 0; j < 8; j++) {
        int e = lane + 32 * j;
        float t = pa[e] + pr[e];
        vals[j] = t;
        sum += t;
    }
    #pragma unroll
    for (int d = 16; d > 0; d >>= 1) sum += __shfl_xor_sync(0xFFFFFFFF, sum, d);
    const float mean = sum * (1.0f / C_);

    float sq = 0.0f;
    #pragma unroll
    for (int j = 0; j < 8; j++) {
        float d = vals[j] - mean;
        sq = fmaf(d, d, sq);
    }
    #pragma unroll
    for (int d = 16; d > 0; d >>= 1) sq += __shfl_xor_sync(0xFFFFFFFF, sq, d);
    const float inv = rsqrtf(sq * (1.0f / C_) + 1e-5f);

    float* po = o + (size_t)row * C_;
    #pragma unroll
    for (int j = 0; j < 8; j++) {
        int e = lane + 32 * j;
        float v = (vals[j] - mean) * inv * s[e] + bb[e];
        if (POSADD) v += pos[(size_t)row * C_ + e];
        po[e] = v;
        if (EMITH) ph[(size_t)row * C_ + e] = __float2half_rn(v);
    }
}

// ---------------------------------------------------------------------------
// Host orchestration
// ---------------------------------------------------------------------------
extern "C" void kernel_launch(void* const* d_in, const int* in_sizes, int n_in,
                              void* d_out, int out_size) {
    const float* src  = (const float*)d_in[0];
    const float* pos  = (const float*)d_in[1];
    const float* ref  = (const float*)d_in[2];
    const float* Woff = (const float*)d_in[3];
    const float* boff = (const float*)d_in[4];
    const float* Wat  = (const float*)d_in[5];
    const float* bat  = (const float*)d_in[6];
    const float* Wv   = (const float*)d_in[7];
    const float* bv   = (const float*)d_in[8];
    const float* Wo   = (const float*)d_in[9];
    const float* bo   = (const float*)d_in[10];
    const float* W1   = (const float*)d_in[11];
    const float* b1   = (const float*)d_in[12];
    const float* W2   = (const float*)d_in[13];
    const float* b2   = (const float*)d_in[14];
    const float* n1s  = (const float*)d_in[15];
    const float* n1b  = (const float*)d_in[16];
    const float* n2s  = (const float*)d_in[17];
    const float* n2b  = (const float*)d_in[18];
    float* outp = (float*)d_out;

    float *px, *pxp, *pow, *pproj, *pbp;
    __half *pvh, *pah, *phh;
    __half *wproj, *wo, *w1, *w2;
    cudaGetSymbolAddress((void**)&px,     g_x);
    cudaGetSymbolAddress((void**)&pxp,    g_xp);
    cudaGetSymbolAddress((void**)&pow,    g_ow);
    cudaGetSymbolAddress((void**)&pproj,  g_proj);
    cudaGetSymbolAddress((void**)&pbp,    g_bpack);
    cudaGetSymbolAddress((void**)&pvh,    g_v_h);
    cudaGetSymbolAddress((void**)&pah,    g_a_h);
    cudaGetSymbolAddress((void**)&phh,    g_h_h);
    cudaGetSymbolAddress((void**)&wproj,  g_wproj);
    cudaGetSymbolAddress((void**)&wo,     g_wo);
    cudaGetSymbolAddress((void**)&w1,     g_w1);
    cudaGetSymbolAddress((void**)&w2,     g_w2);

    const int M = MROWS;
    const int n4 = M * C_ / 4;
    const int SMEM128 = 3 * 256 * 128;   // 98304
    const int SMEM64  = 3 * 192 * 128;   // 73728

    cudaFuncSetAttribute(mma_gemm<128, 0, 2>,
                         cudaFuncAttributeMaxDynamicSharedMemorySize, SMEM128);
    cudaFuncSetAttribute(mma_gemm<64, 0, 0>,
                         cudaFuncAttributeMaxDynamicSharedMemorySize, SMEM64);
    cudaFuncSetAttribute(mma_gemm<64, 1, 1>,
                         cudaFuncAttributeMaxDynamicSharedMemorySize, SMEM64);

    // Weight packing (deterministic, per call)
    {
        int t0 = NL_ * NPACK * C_;
        pack_proj_w<<<(t0 + 255) / 256, 256>>>(Wv, Woff, Wat, wproj);
        int t1 = NL_ * C_ * C_;
        pack_w<<<(t1 + 255) / 256, 256>>>(Wo, wo, C_, C_);
        int t2 = NL_ * FF_ * C_;
        pack_w<<<(t2 + 255) / 256, 256>>>(W1, w1, C_, FF_);
        pack_w<<<(t2 + 255) / 256, 256>>>(W2, w2, FF_, C_);
        int tb = NL_ * NPACK;
        packb_kernel<<<(tb + 255) / 256, 256>>>(bv, boff, bat, pbp);
    }

    dim3 gAdd((n4 + 255) / 256);
    dim3 gProj(NPACK / 128, M / 128);   // (5, 340)  BM=128
    dim3 gN256(C_ / 128, M / 64);       // (2, 680)  BM=64
    dim3 gN1024(FF_ / 128, M / 64);     // (8, 680)  BM=64
    dim3 gDef(M / 2);
    dim3 gLN(M / 8);

    // Layer 0 addpos; later layers get it fused into LN2
    addpos_kernel<<<gAdd, 256>>>(src, pos, pxp, pah, n4);

    for (int i = 0; i < NL_; i++) {
        const float* bp_i = pbp + (size_t)i * NPACK;
        const float* bo_i = bo + (size_t)i * C_;
        const float* b1_i = b1 + (size_t)i * FF_;
        const float* b2_i = b2 + (size_t)i * C_;

        // Fused projections -> v fp16 | off/att fp32   (N=640, K=256)
        mma_gemm<128, 0, 2><<<gProj, 256, SMEM128>>>(pah,
            wproj + (size_t)i * NPACK * C_,
            bp_i, nullptr, pvh, pow, NPACK, C_);

        deform_kernel<<<gDef, 256>>>(pvh, pow, ref, pah);

        // Wo: proj = attn @ Wo   (N=256, K=256)
        mma_gemm<64, 0, 0><<<gN256, 256, SMEM64>>>(pah,
            wo + (size_t)i * C_ * C_,
            bo_i, pproj, nullptr, nullptr, C_, C_);

        // LN1: x = LN(xp + proj); emit fp32 + fp16
        ln_residual<0, 1><<<gLN, 256>>>(pxp, pproj, n1s + (size_t)i * C_,
                                        n1b + (size_t)i * C_, nullptr, px, pah);

        // W1 + ReLU -> hid fp16   (N=1024, K=256)
        mma_gemm<64, 1, 1><<<gN1024, 256, SMEM64>>>(pah,
            w1 + (size_t)i * FF_ * C_,
            b1_i, nullptr, phh, nullptr, FF_, C_);

        // W2: proj = hid @ W2   (N=256, K=1024)
        mma_gemm<64, 0, 0><<<gN256, 256, SMEM64>>>(phh,
            w2 + (size_t)i * C_ * FF_,
            b2_i, pproj, nullptr, nullptr, C_, FF_);

        // LN2: final layer emits output; else fuse +pos for next layer
        if (i == NL_ - 1) {
            ln_residual<0, 0><<<gLN, 256>>>(px, pproj, n2s + (size_t)i * C_,
                                            n2b + (size_t)i * C_, nullptr,
                                            outp, nullptr);
        } else {
            ln_residual<1, 1><<<gLN, 256>>>(px, pproj, n2s + (size_t)i * C_,
                                            n2b + (size_t)i * C_, pos,
                                            pxp, pah);
        }
    }
}

// round 13
// speedup vs baseline: 3.6649x; 1.0036x over previous
#include <cuda_runtime.h>
#include <cuda_fp16.h>
#include <math.h>
#include <stdint.h>

// Problem constants
#define B_    2
#define LQ_   21760
#define C_    256
#define NHEAD 8
#define KPT   4
#define NL_   6
#define FF_   1024
#define DK_   32
#define MROWS (B_ * LQ_)          // 43520
#define NPACK 640                 // 256 (v) + 256 (off) + 128 (att)
#define NOW   384                 // off|att compact row width

// ---------------------------------------------------------------------------
// Device scratch (no runtime allocation)
// ---------------------------------------------------------------------------
__device__ float g_x    [MROWS * C_];
__device__ float g_xp   [MROWS * C_];
__device__ float g_ow   [MROWS * NOW];    // off (256) | att (128), fp32

__device__ __half g_v_h [MROWS * C_];     // sampled-value tensor, fp16
__device__ __half g_a_h [MROWS * C_];     // xp / attn / ln1-out fp16 (reused)
__device__ __half g_h_h [MROWS * FF_];    // hid fp16

// fp16 weights, [N,K] transposed layout (single-rounded)
__device__ __half g_wproj[NL_ * NPACK * C_];
__device__ __half g_wo   [NL_ * C_ * C_];
__device__ __half g_w1   [NL_ * FF_ * C_];
__device__ __half g_w2   [NL_ * C_ * FF_];
__device__ float  g_bpack[NL_ * NPACK];

// ---------------------------------------------------------------------------
// Helpers
// ---------------------------------------------------------------------------
__device__ __forceinline__ uint32_t smem_u32(const void* p) {
    uint32_t a;
    asm("{ .reg .u64 t; cvta.to.shared.u64 t, %1; cvt.u32.u64 %0, t; }"
        : "=r"(a) : "l"(p));
    return a;
}

#define MMA_F16(d, a, b0v, b1v)                                               \
    asm volatile("mma.sync.aligned.m16n8k16.row.col.f32.f16.f16.f32 "         \
        "{%0,%1,%2,%3}, {%4,%5,%6,%7}, {%8,%9}, {%0,%1,%2,%3};"               \
        : "+f"((d)[0]), "+f"((d)[1]), "+f"((d)[2]), "+f"((d)[3])              \
        : "r"((a)[0]), "r"((a)[1]), "r"((a)[2]), "r"((a)[3]),                 \
          "r"(b0v), "r"(b1v))

#define LDMATRIX_X4(r0, r1, r2, r3, addr)                                     \
    asm volatile("ldmatrix.sync.aligned.m8n8.x4.shared.b16 {%0,%1,%2,%3}, [%4];" \
        : "=r"(r0), "=r"(r1), "=r"(r2), "=r"(r3) : "r"(addr))

#define CP_ASYNC16(saddr, gptr)                                               \
    asm volatile("cp.async.cg.shared.global [%0], [%1], 16;"                  \
        :: "r"(saddr), "l"(gptr))

// ---------------------------------------------------------------------------
// Weight packing (fp32 [K,N] -> fp16 [N,K])
// ---------------------------------------------------------------------------
__global__ void pack_proj_w(const float* __restrict__ Wv,
                            const float* __restrict__ Woff,
                            const float* __restrict__ Wat,
                            __half* __restrict__ Bh) {
    int idx = blockIdx.x * blockDim.x + threadIdx.x;   // NL*640*256
    if (idx >= NL_ * NPACK * C_) return;
    int k = idx & 255;
    int n = (idx >> 8) % NPACK;
    int l = idx / (NPACK * C_);
    float v;
    if (n < 256)      v = Wv  [((size_t)l * C_ + k) * 256 + n];
    else if (n < 512) v = Woff[((size_t)l * C_ + k) * 256 + (n - 256)];
    else              v = Wat [((size_t)l * C_ + k) * 128 + (n - 512)];
    Bh[idx] = __float2half_rn(v);
}

__global__ void pack_w(const float* __restrict__ W,
                       __half* __restrict__ Bh, int K, int N) {
    int idx = blockIdx.x * blockDim.x + threadIdx.x;   // NL*N*K
    if (idx >= NL_ * N * K) return;
    int k = idx % K;
    int n = (idx / K) % N;
    int l = idx / (N * K);
    Bh[idx] = __float2half_rn(W[(size_t)l * K * N + (size_t)k * N + n]);
}

__global__ void packb_kernel(const float* __restrict__ bv,
                             const float* __restrict__ boff,
                             const float* __restrict__ bat,
                             float* __restrict__ bp) {
    int idx = blockIdx.x * blockDim.x + threadIdx.x;
    if (idx >= NL_ * NPACK) return;
    int n = idx % NPACK;
    int l = idx / NPACK;
    float val;
    if (n < 256)      val = bv  [(size_t)l * 256 + n];
    else if (n < 512) val = boff[(size_t)l * 256 + (n - 256)];
    else              val = bat [(size_t)l * 128 + (n - 512)];
    bp[idx] = val;
}

// ---------------------------------------------------------------------------
// addpos (layer 0 only): xp = x + pos -> fp32 + fp16
// ---------------------------------------------------------------------------
__global__ void addpos_kernel(const float* __restrict__ x,
                              const float* __restrict__ pos,
                              float* __restrict__ xp,
                              __half* __restrict__ ph, int n4) {
    int i = blockIdx.x * blockDim.x + threadIdx.x;
    if (i >= n4) return;
    float4 a = ((const float4*)x)[i];
    float4 b = ((const float4*)pos)[i];
    float4 o;
    o.x = a.x + b.x; o.y = a.y + b.y; o.z = a.z + b.z; o.w = a.w + b.w;
    ((float4*)xp)[i] = o;
    ((__half2*)ph)[i * 2]     = __halves2half2(__float2half_rn(o.x), __float2half_rn(o.y));
    ((__half2*)ph)[i * 2 + 1] = __halves2half2(__float2half_rn(o.z), __float2half_rn(o.w));
}

// ---------------------------------------------------------------------------
// mma.sync fp16 GEMM: C[M,N] = A[M,K] @ B[N,K]^T + bias.
// Template BMt in {128, 64}; BN=128; 8 warps; 3-stage cp.async pipeline.
// OMODE: 1 = fp16 out, 2 = proj split (v fp16 | ow fp32)
// ---------------------------------------------------------------------------
template<int BMt, int RELU, int OMODE>
__global__ __launch_bounds__(256, 2)
void mma_gemm(const __half* __restrict__ A,
              const __half* __restrict__ Bm,
              const float* __restrict__ bias,
              __half* __restrict__ Chf,
              float* __restrict__ Cow,
              int N, int K) {
    constexpr int MW    = BMt / 32;
    constexpr int NW    = 8 / MW;
    constexpr int WN    = 128 / NW;
    constexpr int NG    = WN / 16;
    constexpr int ROWS  = BMt + 128;
    constexpr int STAGE = ROWS * 128;
    constexpr int PERT  = ROWS * 8 / 256;

    extern __shared__ uint8_t smem[];
    const int tid  = threadIdx.x;
    const int wid  = tid >> 5;
    const int lane = tid & 31;
    const int brow = blockIdx.y * BMt;
    const int bcol = blockIdx.x * 128;
    const int kIters = K >> 6;

    const uint32_t smbase = smem_u32(smem);

    auto load_tile = [&](int k, int buf) {
        uint32_t sbuf = smbase + buf * STAGE;
        const int koff = k << 6;
        #pragma unroll
        for (int i = 0; i < PERT; i++) {
            int cid = tid + (i << 8);
            int row = cid >> 3;
            int col = cid & 7;
            const __half* g;
            if (row < BMt) g = A  + (size_t)(brow + row) * K + koff + col * 8;
            else           g = Bm + (size_t)(bcol + row - BMt) * K + koff + col * 8;
            uint32_t sw = row * 128 + (((uint32_t)(col ^ (row & 7))) << 4);
            CP_ASYNC16(sbuf + sw, g);
        }
    };

    const int wm = (wid % MW) * 32;
    const int wn = (wid / MW) * WN;

    float acc[2][2 * NG][4];
    #pragma unroll
    for (int mi = 0; mi < 2; mi++)
        #pragma unroll
        for (int nj = 0; nj < 2 * NG; nj++)
            #pragma unroll
            for (int r = 0; r < 4; r++) acc[mi][nj][r] = 0.0f;

    auto compute = [&](int buf) {
        uint32_t sA = smbase + buf * STAGE;
        uint32_t sB = sA + BMt * 128;
        #pragma unroll
        for (int ks = 0; ks < 4; ks++) {
            uint32_t a[2][4];
            const int c = ks * 2 + (lane >> 4);
            #pragma unroll
            for (int mi = 0; mi < 2; mi++) {
                int r = wm + mi * 16 + (lane & 15);
                uint32_t addr = sA + r * 128 + ((c ^ (r & 7)) << 4);
                LDMATRIX_X4(a[mi][0], a[mi][1], a[mi][2], a[mi][3], addr);
            }
            #pragma unroll
            for (int ng = 0; ng < NG; ng++) {
                int r = wn + ng * 16 + (lane & 15);
                uint32_t soff = r * 128 + ((c ^ (r & 7)) << 4);
                uint32_t b0, b1, b2, b3;
                LDMATRIX_X4(b0, b1, b2, b3, sB + soff);
                #pragma unroll
                for (int mi = 0; mi < 2; mi++) {
                    MMA_F16(acc[mi][ng * 2 + 0], a[mi], b0, b2);
                    MMA_F16(acc[mi][ng * 2 + 1], a[mi], b1, b3);
                }
            }
        }
    };

    load_tile(0, 0);
    asm volatile("cp.async.commit_group;" ::: "memory");
    if (kIters > 1) {
        load_tile(1, 1);
        asm volatile("cp.async.commit_group;" ::: "memory");
    }
    for (int t = 0; t < kIters; t++) {
        if (t + 1 < kIters)
            asm volatile("cp.async.wait_group 1;" ::: "memory");
        else
            asm volatile("cp.async.wait_group 0;" ::: "memory");
        __syncthreads();
        if (t + 2 < kIters) {
            load_tile(t + 2, (t + 2) % 3);
            asm volatile("cp.async.commit_group;" ::: "memory");
        }
        compute(t % 3);
    }

    const int tr = lane >> 2;
    const int tc = (lane & 3) * 2;
    #pragma unroll
    for (int mi = 0; mi < 2; mi++) {
        #pragma unroll
        for (int nj = 0; nj < 2 * NG; nj++) {
            const int col = bcol + wn + nj * 8 + tc;
            const float bb0 = bias[col], bb1 = bias[col + 1];
            #pragma unroll
            for (int rr = 0; rr < 2; rr++) {
                const int row = brow + wm + mi * 16 + rr * 8 + tr;
                float v0 = acc[mi][nj][rr * 2 + 0] + bb0;
                float v1 = acc[mi][nj][rr * 2 + 1] + bb1;
                if (RELU) { v0 = fmaxf(v0, 0.f); v1 = fmaxf(v1, 0.f); }
                if (OMODE == 1) {
                    *(__half2*)(Chf + (size_t)row * N + col) =
                        __halves2half2(__float2half_rn(v0), __float2half_rn(v1));
                } else {
                    if (col < 256) {
                        *(__half2*)(Chf + (size_t)row * C_ + col) =
                            __halves2half2(__float2half_rn(v0), __float2half_rn(v1));
                    } else {
                        float2 o; o.x = v0; o.y = v1;
                        *(float2*)(Cow + (size_t)row * NOW + (col - 256)) = o;
                    }
                }
            }
        }
    }
}

// ---------------------------------------------------------------------------
// Fused GEMM + residual + LayerNorm.
// out = LN(resid + A@B^T + bias) * s + bb  [+ pos if POSADD]
// BM=32, BN=256 (full row -> rowwise LN in-CTA), BK=64, 2-stage pipeline.
// 8 warps as 2Mx4N, warp tile 16x64. Grid = M/32 = 1360 blocks (4.59 waves).
// FINAL: write fp32 only (network output); else write fp32 + fp16.
// ---------------------------------------------------------------------------
template<int POSADD, int FINAL>
__global__ __launch_bounds__(256, 2)
void mma_gemm_ln(const __half* __restrict__ A,
                 const __half* __restrict__ Bm,
                 const float* __restrict__ bias,
                 const float* __restrict__ resid,
                 const float* __restrict__ s,
                 const float* __restrict__ bb,
                 const float* __restrict__ pos,
                 float* __restrict__ outF,
                 __half* __restrict__ outH,
                 int K) {
    constexpr int STAGE = 288 * 128;   // (32 A-rows + 256 B-rows) * 128B
    extern __shared__ uint8_t smem[];
    const int tid  = threadIdx.x;
    const int wid  = tid >> 5;
    const int lane = tid & 31;
    const int brow = blockIdx.x * 32;
    const int kIters = K >> 6;
    const uint32_t smbase = smem_u32(smem);

    auto load_tile = [&](int k, int buf) {
        uint32_t sbuf = smbase + buf * STAGE;
        const int koff = k << 6;
        #pragma unroll
        for (int i = 0; i < 9; i++) {          // 288*8/256 = 9 chunks/thread
            int cid = tid + (i << 8);
            int row = cid >> 3;
            int col = cid & 7;
            const __half* g = (row < 32)
                ? A  + (size_t)(brow + row) * K + koff + col * 8
                : Bm + (size_t)(row - 32) * K + koff + col * 8;
            uint32_t sw = row * 128 + (((uint32_t)(col ^ (row & 7))) << 4);
            CP_ASYNC16(sbuf + sw, g);
        }
    };

    const int wm = (wid & 1) * 16;       // M-warp: rows wm..wm+15
    const int wn = (wid >> 1) * 64;      // N-warp: cols wn..wn+63
    const int nw = wid >> 1;             // N-warp index 0..3

    float acc[8][4];
    #pragma unroll
    for (int nj = 0; nj < 8; nj++)
        #pragma unroll
        for (int r = 0; r < 4; r++) acc[nj][r] = 0.0f;

    auto compute = [&](int buf) {
        uint32_t sA = smbase + buf * STAGE;
        uint32_t sB = sA + 32 * 128;
        #pragma unroll
        for (int ks = 0; ks < 4; ks++) {
            const int c = ks * 2 + (lane >> 4);
            int r = wm + (lane & 15);
            uint32_t addr = sA + r * 128 + ((c ^ (r & 7)) << 4);
            uint32_t av[4];
            LDMATRIX_X4(av[0], av[1], av[2], av[3], addr);
            #pragma unroll
            for (int ng = 0; ng < 4; ng++) {
                int r2 = wn + ng * 16 + (lane & 15);
                uint32_t soff = r2 * 128 + ((c ^ (r2 & 7)) << 4);
                uint32_t b0, b1, b2, b3;
                LDMATRIX_X4(b0, b1, b2, b3, sB + soff);
                MMA_F16(acc[ng * 2 + 0], av, b0, b2);
                MMA_F16(acc[ng * 2 + 1], av, b1, b3);
            }
        }
    };

    // 2-stage pipeline
    load_tile(0, 0);
    asm volatile("cp.async.commit_group;" ::: "memory");
    for (int t = 0; t < kIters; t++) {
        if (t + 1 < kIters) {
            load_tile(t + 1, (t + 1) & 1);
            asm volatile("cp.async.commit_group;" ::: "memory");
            asm volatile("cp.async.wait_group 1;" ::: "memory");
        } else {
            asm volatile("cp.async.wait_group 0;" ::: "memory");
        }
        __syncthreads();
        compute(t & 1);
        __syncthreads();
    }

    // ---- Fused epilogue: residual add + two-pass LayerNorm ----
    const int tr = lane >> 2;            // 0..7
    const int tc = (lane & 3) * 2;       // 0,2,4,6
    float* red = (float*)smem;           // 32 rows x 4 nwarps (reuse stage smem)

    // Pass A: t = acc + bias + resid; row sums
    float mean_[2], inv_[2];
    #pragma unroll
    for (int rr = 0; rr < 2; rr++) {
        int rowl = wm + rr * 8 + tr;
        size_t rowg = (size_t)(brow + rowl) * C_;
        float sum = 0.f;
        #pragma unroll
        for (int nj = 0; nj < 8; nj++) {
            int col = wn + nj * 8 + tc;
            float2 rv = *(const float2*)(resid + rowg + col);
            float t0 = acc[nj][rr * 2 + 0] + bias[col]     + rv.x;
            float t1 = acc[nj][rr * 2 + 1] + bias[col + 1] + rv.y;
            acc[nj][rr * 2 + 0] = t0;
            acc[nj][rr * 2 + 1] = t1;
            sum += t0 + t1;
        }
        sum += __shfl_xor_sync(0xFFFFFFFF, sum, 1);
        sum += __shfl_xor_sync(0xFFFFFFFF, sum, 2);
        if ((lane & 3) == 0) red[rowl * 4 + nw] = sum;
    }
    __syncthreads();
    #pragma unroll
    for (int rr = 0; rr < 2; rr++) {
        int rowl = wm + rr * 8 + tr;
        mean_[rr] = (red[rowl * 4 + 0] + red[rowl * 4 + 1] +
                     red[rowl * 4 + 2] + red[rowl * 4 + 3]) * (1.0f / C_);
    }
    __syncthreads();

    // Pass B: variance
    #pragma unroll
    for (int rr = 0; rr < 2; rr++) {
        int rowl = wm + rr * 8 + tr;
        float sq = 0.f;
        #pragma unroll
        for (int nj = 0; nj < 8; nj++) {
            float d0 = acc[nj][rr * 2 + 0] - mean_[rr];
            float d1 = acc[nj][rr * 2 + 1] - mean_[rr];
            sq = fmaf(d0, d0, sq);
            sq = fmaf(d1, d1, sq);
        }
        sq += __shfl_xor_sync(0xFFFFFFFF, sq, 1);
        sq += __shfl_xor_sync(0xFFFFFFFF, sq, 2);
        if ((lane & 3) == 0) red[rowl * 4 + nw] = sq;
    }
    __syncthreads();
    #pragma unroll
    for (int rr = 0; rr < 2; rr++) {
        int rowl = wm + rr * 8 + tr;
        float sq = red[rowl * 4 + 0] + red[rowl * 4 + 1] +
                   red[rowl * 4 + 2] + red[rowl * 4 + 3];
        inv_[rr] = rsqrtf(sq * (1.0f / C_) + 1e-5f);
    }

    // Apply + write
    #pragma unroll
    for (int rr = 0; rr < 2; rr++) {
        int rowl = wm + rr * 8 + tr;
        size_t rowg = (size_t)(brow + rowl) * C_;
        #pragma unroll
        for (int nj = 0; nj < 8; nj++) {
            int col = wn + nj * 8 + tc;
            float v0 = (acc[nj][rr * 2 + 0] - mean_[rr]) * inv_[rr] * s[col]     + bb[col];
            float v1 = (acc[nj][rr * 2 + 1] - mean_[rr]) * inv_[rr] * s[col + 1] + bb[col + 1];
            if (POSADD) {
                float2 pv = *(const float2*)(pos + rowg + col);
                v0 += pv.x; v1 += pv.y;
            }
            float2 o; o.x = v0; o.y = v1;
            *(float2*)(outF + rowg + col) = o;
            if (!FINAL)
                *(__half2*)(outH + rowg + col) =
                    __halves2half2(__float2half_rn(v0), __float2half_rn(v1));
        }
    }
}

// ---------------------------------------------------------------------------
// Deformable attention sampling, half2 channel pairs.
// ---------------------------------------------------------------------------
__constant__ int c_SW[4] = {128, 64, 32, 16};
__constant__ int c_START[4] = {0, 16384, 20480, 21504};

__global__ __launch_bounds__(256)
void deform_kernel(const __half* __restrict__ vh, const float* __restrict__ ow,
                   const float* __restrict__ ref, __half* __restrict__ oh) {
    const int tid  = threadIdx.x;
    const int wblk = tid >> 5;
    const int lane = tid & 31;
    const int sub  = lane >> 4;
    const int li   = lane & 15;
    const int bq   = blockIdx.x * 2 + (wblk >> 2);
    const int h    = ((wblk & 3) << 1) + sub;
    const int b    = bq / LQ_;

    const float* ar = ow + (size_t)bq * NOW + 256 + h * 16;
    float w[16];
    float mx = -1e30f;
    #pragma unroll
    for (int j = 0; j < 16; j++) { w[j] = ar[j]; mx = fmaxf(mx, w[j]); }
    float s = 0.0f;
    #pragma unroll
    for (int j = 0; j < 16; j++) { w[j] = expf(w[j] - mx); s += w[j]; }
    const float inv_s = 1.0f / s;

    const float refx = ref[bq * 2 + 0];
    const float refy = ref[bq * 2 + 1];
    const float* ob = ow + (size_t)bq * NOW + h * 32;
    const __half2* vb2 = (const __half2*)vh
                       + ((size_t)b * LQ_ * C_ + h * DK_) / 2 + li;

    float accx = 0.0f, accy = 0.0f;
    #pragma unroll
    for (int l = 0; l < 4; l++) {
        const int   Wl = c_SW[l];
        const float fw = (float)Wl;
        const int   st = c_START[l];
        #pragma unroll
        for (int k = 0; k < KPT; k++) {
            float ox = ob[l * 8 + k * 2 + 0];
            float oy = ob[l * 8 + k * 2 + 1];
            float x = (refx + ox * (1.0f / fw)) * (fw - 1.0f);
            float y = (refy + oy * (1.0f / fw)) * (fw - 1.0f);
            x = fminf(fmaxf(x, 0.0f), fw - 1.0f);
            y = fminf(fmaxf(y, 0.0f), fw - 1.0f);
            float x0f = floorf(x), y0f = floorf(y);
            int x0 = (int)x0f, y0 = (int)y0f;
            int x1 = min(x0 + 1, Wl - 1);
            int y1 = min(y0 + 1, Wl - 1);
            float wx = x - x0f, wy = y - y0f;
            float aw = w[l * 4 + k] * inv_s;

            float2 v00 = __half22float2(vb2[(size_t)(st + y0 * Wl + x0) * (C_ / 2)]);
            float2 v01 = __half22float2(vb2[(size_t)(st + y0 * Wl + x1) * (C_ / 2)]);
            float2 v10 = __half22float2(vb2[(size_t)(st + y1 * Wl + x0) * (C_ / 2)]);
            float2 v11 = __half22float2(vb2[(size_t)(st + y1 * Wl + x1) * (C_ / 2)]);
            float w00 = (1.0f - wx) * (1.0f - wy);
            float w01 = wx * (1.0f - wy);
            float w10 = (1.0f - wx) * wy;
            float w11 = wx * wy;
            float bx = w00 * v00.x + w01 * v01.x + w10 * v10.x + w11 * v11.x;
            float by = w00 * v00.y + w01 * v01.y + w10 * v10.y + w11 * v11.y;
            accx = fmaf(aw, bx, accx);
            accy = fmaf(aw, by, accy);
        }
    }
    ((__half2*)oh)[((size_t)bq * C_ + h * DK_) / 2 + li] =
        __halves2half2(__float2half_rn(accx), __float2half_rn(accy));
}

// ---------------------------------------------------------------------------
// Host orchestration
// ---------------------------------------------------------------------------
extern "C" void kernel_launch(void* const* d_in, const int* in_sizes, int n_in,
                              void* d_out, int out_size) {
    const float* src  = (const float*)d_in[0];
    const float* pos  = (const float*)d_in[1];
    const float* ref  = (const float*)d_in[2];
    const float* Woff = (const float*)d_in[3];
    const float* boff = (const float*)d_in[4];
    const float* Wat  = (const float*)d_in[5];
    const float* bat  = (const float*)d_in[6];
    const float* Wv   = (const float*)d_in[7];
    const float* bv   = (const float*)d_in[8];
    const float* Wo   = (const float*)d_in[9];
    const float* bo   = (const float*)d_in[10];
    const float* W1   = (const float*)d_in[11];
    const float* b1   = (const float*)d_in[12];
    const float* W2   = (const float*)d_in[13];
    const float* b2   = (const float*)d_in[14];
    const float* n1s  = (const float*)d_in[15];
    const float* n1b  = (const float*)d_in[16];
    const float* n2s  = (const float*)d_in[17];
    const float* n2b  = (const float*)d_in[18];
    float* outp = (float*)d_out;

    float *px, *pxp, *pow, *pbp;
    __half *pvh, *pah, *phh;
    __half *wproj, *wo, *w1, *w2;
    cudaGetSymbolAddress((void**)&px,     g_x);
    cudaGetSymbolAddress((void**)&pxp,    g_xp);
    cudaGetSymbolAddress((void**)&pow,    g_ow);
    cudaGetSymbolAddress((void**)&pbp,    g_bpack);
    cudaGetSymbolAddress((void**)&pvh,    g_v_h);
    cudaGetSymbolAddress((void**)&pah,    g_a_h);
    cudaGetSymbolAddress((void**)&phh,    g_h_h);
    cudaGetSymbolAddress((void**)&wproj,  g_wproj);
    cudaGetSymbolAddress((void**)&wo,     g_wo);
    cudaGetSymbolAddress((void**)&w1,     g_w1);
    cudaGetSymbolAddress((void**)&w2,     g_w2);

    const int M = MROWS;
    const int n4 = M * C_ / 4;
    const int SMEM128 = 3 * 256 * 128;   // 98304 (proj, 3-stage)
    const int SMEM64  = 3 * 192 * 128;   // 73728 (W1, 3-stage)
    const int SMEMLN  = 2 * 288 * 128;   // 73728 (fused LN, 2-stage)

    cudaFuncSetAttribute(mma_gemm<128, 0, 2>,
                         cudaFuncAttributeMaxDynamicSharedMemorySize, SMEM128);
    cudaFuncSetAttribute(mma_gemm<64, 1, 1>,
                         cudaFuncAttributeMaxDynamicSharedMemorySize, SMEM64);
    cudaFuncSetAttribute(mma_gemm_ln<0, 0>,
                         cudaFuncAttributeMaxDynamicSharedMemorySize, SMEMLN);
    cudaFuncSetAttribute(mma_gemm_ln<1, 0>,
                         cudaFuncAttributeMaxDynamicSharedMemorySize, SMEMLN);
    cudaFuncSetAttribute(mma_gemm_ln<0, 1>,
                         cudaFuncAttributeMaxDynamicSharedMemorySize, SMEMLN);

    // Weight packing (deterministic, per call)
    {
        int t0 = NL_ * NPACK * C_;
        pack_proj_w<<<(t0 + 255) / 256, 256>>>(Wv, Woff, Wat, wproj);
        int t1 = NL_ * C_ * C_;
        pack_w<<<(t1 + 255) / 256, 256>>>(Wo, wo, C_, C_);
        int t2 = NL_ * FF_ * C_;
        pack_w<<<(t2 + 255) / 256, 256>>>(W1, w1, C_, FF_);
        pack_w<<<(t2 + 255) / 256, 256>>>(W2, w2, FF_, C_);
        int tb = NL_ * NPACK;
        packb_kernel<<<(tb + 255) / 256, 256>>>(bv, boff, bat, pbp);
    }

    dim3 gAdd((n4 + 255) / 256);
    dim3 gProj(NPACK / 128, M / 128);   // (5, 340)  BM=128
    dim3 gN1024(FF_ / 128, M / 64);     // (8, 680)  BM=64
    dim3 gLNG(M / 32);                  // 1360 blocks, fused GEMM+LN
    dim3 gDef(M / 2);

    // Layer 0 addpos; later layers get it fused into LN2
    addpos_kernel<<<gAdd, 256>>>(src, pos, pxp, pah, n4);

    for (int i = 0; i < NL_; i++) {
        const float* bp_i = pbp + (size_t)i * NPACK;
        const float* bo_i = bo + (size_t)i * C_;
        const float* b1_i = b1 + (size_t)i * FF_;
        const float* b2_i = b2 + (size_t)i * C_;

        // Fused projections -> v fp16 | off/att fp32   (N=640, K=256)
        mma_gemm<128, 0, 2><<<gProj, 256, SMEM128>>>(pah,
            wproj + (size_t)i * NPACK * C_,
            bp_i, pvh, pow, NPACK, C_);

        deform_kernel<<<gDef, 256>>>(pvh, pow, ref, pah);

        // Wo GEMM + LN1 fused: x = LN(xp + attn@Wo + bo); emit px fp32 + pah fp16
        mma_gemm_ln<0, 0><<<gLNG, 256, SMEMLN>>>(pah,
            wo + (size_t)i * C_ * C_, bo_i, pxp,
            n1s + (size_t)i * C_, n1b + (size_t)i * C_, nullptr,
            px, pah, C_);

        // W1 + ReLU -> hid fp16   (N=1024, K=256)
        mma_gemm<64, 1, 1><<<gN1024, 256, SMEM64>>>(pah,
            w1 + (size_t)i * FF_ * C_,
            b1_i, phh, nullptr, FF_, C_);

        // W2 GEMM + LN2 fused
        if (i == NL_ - 1) {
            mma_gemm_ln<0, 1><<<gLNG, 256, SMEMLN>>>(phh,
                w2 + (size_t)i * C_ * FF_, b2_i, px,
                n2s + (size_t)i * C_, n2b + (size_t)i * C_, nullptr,
                outp, nullptr, FF_);
        } else {
            mma_gemm_ln<1, 0><<<gLNG, 256, SMEMLN>>>(phh,
                w2 + (size_t)i * C_ * FF_, b2_i, px,
                n2s + (size_t)i * C_, n2b + (size_t)i * C_, pos,
                pxp, pah, FF_);
        }
    }
}